// round 11
// baseline (speedup 1.0000x reference)
#include <cuda_runtime.h>
#include <math.h>
#include <stdint.h>

// ---------------- problem constants ----------------
#define NB 8
#define NPIX 1024
#define NS 8
#define D 256
#define H 512
#define NROWS (NB*NPIX)
#define EPSA 1e-8f
#define LNEPS 1e-5f
#define ATTN_SCALE 0.0625f
#define GSTEP (2.0f/31.0f)

// ---------------- scratch ----------------
__device__ __align__(16) float g_K [NROWS*D];
__device__ __align__(16) float g_V [NROWS*D];
__device__ __align__(16) float g_Pk[NROWS*H];
__device__ __align__(16) float g_Pv[NROWS*H];
__device__ __align__(16) float g_statsK[NROWS*4];
__device__ __align__(16) float g_statsV[NROWS*4];
__device__ float g_meanK[NROWS];
__device__ float g_meanV[NROWS];
__device__ float g_lnM[NROWS];
__device__ float g_lnIS[NROWS];
__device__ __align__(16) float g_U0[H];
__device__ __align__(16) float g_U1[H];
__device__ __align__(16) float g_Ub[H];
__device__ __align__(16) float g_C[H];
__device__ __align__(16) float g_G1[H];
__device__ float g_cov[16];
__device__ float g_Cond[NB*NS*260];
__device__ __align__(16) float g_slot[NB*NS*520];
__device__ float g_attn0[NB*NS*NPIX];
__device__ float g_part[NB*NS*64*8];
__device__ float g_spart[NB*NS*16*H];
// transposed + tf32-split weights (n-major: [n][k])
__device__ __align__(16) uint32_t g_WkTh[65536], g_WkTl[65536];
__device__ __align__(16) uint32_t g_WvTh[65536], g_WvTl[65536];
__device__ __align__(16) uint32_t g_W1Th[131072], g_W1Tl[131072];

__device__ __forceinline__ float warpSum(float v) {
    #pragma unroll
    for (int o = 16; o; o >>= 1) v += __shfl_xor_sync(0xffffffffu, v, o);
    return v;
}

__device__ __forceinline__ void tf32split(float x, uint32_t& h, uint32_t& l){
    uint32_t hb; asm("cvt.rna.tf32.f32 %0, %1;" : "=r"(hb) : "f"(x));
    float lo = x - __uint_as_float(hb);
    uint32_t lb; asm("cvt.rna.tf32.f32 %0, %1;" : "=r"(lb) : "f"(lo));
    h = hb; l = lb;
}

__device__ __forceinline__ void mma_tf32(float* d, const uint32_t* a, const uint32_t* b){
    asm volatile("mma.sync.aligned.m16n8k8.row.col.f32.tf32.tf32.f32 "
        "{%0,%1,%2,%3}, {%4,%5,%6,%7}, {%8,%9}, {%0,%1,%2,%3};"
        : "+f"(d[0]), "+f"(d[1]), "+f"(d[2]), "+f"(d[3])
        : "r"(a[0]), "r"(a[1]), "r"(a[2]), "r"(a[3]), "r"(b[0]), "r"(b[1]));
}

// ---------------- pre: constants + cond copy + LN row stats + weight transpose/split ----------------
__global__ __launch_bounds__(512) void pre_kernel(
    const float* __restrict__ gp_w, const float* __restrict__ gp_b,
    const float* __restrict__ lg,   const float* __restrict__ lb,
    const float* __restrict__ W1,   const float* __restrict__ b1,
    const float* __restrict__ cond, const float* __restrict__ inputs,
    const float* __restrict__ wk,   const float* __restrict__ wv)
{
    int bid = blockIdx.x;
    int t = threadIdx.x;
    if (bid >= 546){
        int idx = (bid - 546)*512 + t;
        if (idx < 65536){
            int k = idx >> 8, n = idx & 255;
            uint32_t h, l; tf32split(wk[idx], h, l);
            g_WkTh[n*256+k] = h; g_WkTl[n*256+k] = l;
        } else if (idx < 131072){
            int i2 = idx - 65536;
            int k = i2 >> 8, n = i2 & 255;
            uint32_t h, l; tf32split(wv[i2], h, l);
            g_WvTh[n*256+k] = h; g_WvTl[n*256+k] = l;
        } else {
            int i2 = idx - 131072;
            int k = i2 >> 9, n = i2 & 511;
            uint32_t h, l; tf32split(W1[i2] * lg[k], h, l);
            g_W1Th[n*256+k] = h; g_W1Tl[n*256+k] = l;
        }
        return;
    }
    if (bid >= 34) {
        int r = (bid - 34)*16 + (t>>5);
        int lane = t & 31;
        const float* row = inputs + (size_t)r*D;
        float v[8]; float s = 0.f;
        #pragma unroll
        for (int k=0;k<8;k++){ v[k]=row[k*32+lane]; s+=v[k]; }
        float m = warpSum(s) * (1.f/D);
        float q = 0.f;
        #pragma unroll
        for (int k=0;k<8;k++){ float d=v[k]-m; q += d*d; }
        float is = rsqrtf(warpSum(q)*(1.f/D) + LNEPS);
        if (lane == 0){ g_lnM[r]=m; g_lnIS[r]=is; }
        return;
    }
    if (bid > 0) {
        int i = (bid - 1)*512 + t;
        if (i < NB*NS*260) g_Cond[i] = cond[i];
        return;
    }
    __shared__ float sg0[D], sg1[D], sgb[D], slg[D], slb[D];
    __shared__ float sm[4];
    if (t < D) { sg0[t]=gp_w[t]; sg1[t]=gp_w[D+t]; sgb[t]=gp_b[t]; slg[t]=lg[t]; slb[t]=lb[t]; }
    __syncthreads();
    if (t == 0) {
        float m0=0,m1=0,mb=0;
        for (int d=0; d<D; d++){ m0+=sg0[d]; m1+=sg1[d]; mb+=sgb[d]; }
        m0*=(1.f/D); m1*=(1.f/D); mb*=(1.f/D);
        float V00=0,V11=0,Vbb=0,C01=0,C0b=0,C1b=0;
        for (int d=0; d<D; d++){
            float a=sg0[d]-m0, b_=sg1[d]-m1, c=sgb[d]-mb;
            V00+=a*a; V11+=b_*b_; Vbb+=c*c; C01+=a*b_; C0b+=a*c; C1b+=b_*c;
        }
        g_cov[0]=m0; g_cov[1]=m1; g_cov[2]=mb;
        g_cov[3]=V00/D; g_cov[4]=V11/D; g_cov[5]=Vbb/D;
        g_cov[6]=C01/D; g_cov[7]=C0b/D; g_cov[8]=C1b/D;
        float s2=0;
        for (int i=0;i<32;i++){ float x=-1.f + i*GSTEP; s2+=x*x; }
        g_cov[9]=s2*32.f;
        sm[0]=m0; sm[1]=m1; sm[2]=mb;
    }
    __syncthreads();
    float m0=sm[0], m1=sm[1], mb=sm[2];
    float U0=0,U1=0,Ub=0,Cc=0,G1=0;
    for (int d=0; d<D; d++){
        float w = W1[d*H + t];
        float gd = slg[d];
        U0 = fmaf((sg0[d]-m0)*gd, w, U0);
        U1 = fmaf((sg1[d]-m1)*gd, w, U1);
        Ub = fmaf((sgb[d]-mb)*gd, w, Ub);
        Cc = fmaf(slb[d], w, Cc);
        G1 = fmaf(gd, w, G1);
    }
    g_U0[t]=U0; g_U1[t]=U1; g_Ub[t]=Ub; g_C[t]=Cc + b1[t]; g_G1[t]=G1;
}

// ---------------- tensor-core GEMM: tf32 3-term split, 128x128 CTA tile, 64x32 warp tile ----------------
// mode 0: C = LN(inputs)@wk / @wv  (z selects; N=256)
// mode 2: C = K@(diag(sg)W1) - mk*G1 + Ub   (sg folded into W1T; N=512)
__global__ __launch_bounds__(256) void gemmT(int mode, const float* __restrict__ A0,
                                             const float* __restrict__ sgv,
                                             const float* __restrict__ sbv, int N)
{
    int z = blockIdx.z;
    const float* A = (mode==0) ? A0 : (z ? g_V : g_K);
    const uint32_t* BTh = (mode==0) ? (z ? g_WvTh : g_WkTh) : g_W1Th;
    const uint32_t* BTl = (mode==0) ? (z ? g_WvTl : g_WkTl) : g_W1Tl;
    float* Cm = (mode==0) ? (z ? g_V : g_K) : (z ? g_Pv : g_Pk);
    const float* meanV = (mode==0) ? nullptr : (z ? g_meanV : g_meanK);

    __shared__ __align__(16) uint32_t Ah[128*20], Al[128*20];
    __shared__ __align__(16) uint32_t Bh[128*20], Bl[128*20];
    __shared__ float SG[256], SB[256];

    int bm = blockIdx.y*128, bn = blockIdx.x*128;
    int tid = threadIdx.x, lane = tid & 31, wrp = tid >> 5;
    int wm = wrp & 1, wn = wrp >> 1;       // warp grid 2(M) x 4(N), warp tile 64x32
    int qr = lane >> 2, ql = lane & 3;

    if (mode == 0){ SG[tid] = sgv[tid]; SB[tid] = sbv[tid]; }

    int arow = tid >> 1, akoff = (tid & 1) * 8;   // A: 128 rows, 2 thr/row
    float rm = 0.f, ris = 1.f;
    if (mode == 0){ rm = g_lnM[bm+arow]; ris = g_lnIS[bm+arow]; }
    __syncthreads();

    float acc[4][4][4] = {};
    const float* aptr = A + (size_t)(bm+arow)*256 + akoff;
    const uint32_t* bhp = BTh + (size_t)(bn+arow)*256 + akoff;  // B: same row/k mapping
    const uint32_t* blp = BTl + (size_t)(bn+arow)*256 + akoff;

    float4 pa0 = *(const float4*)aptr;
    float4 pa1 = *(const float4*)(aptr + 4);
    uint4 pbh0 = *(const uint4*)bhp;
    uint4 pbh1 = *(const uint4*)(bhp + 4);
    uint4 pbl0 = *(const uint4*)blp;
    uint4 pbl1 = *(const uint4*)(blp + 4);

    #pragma unroll 1
    for (int kc = 0; kc < 16; kc++){
        float av[8] = {pa0.x,pa0.y,pa0.z,pa0.w,pa1.x,pa1.y,pa1.z,pa1.w};
        if (mode == 0){
            int kb = kc*16 + akoff;
            #pragma unroll
            for (int i=0;i<8;i++) av[i] = fmaf((av[i]-rm)*ris, SG[kb+i], SB[kb+i]);
        }
        uint32_t ahv[8], alv[8];
        #pragma unroll
        for (int i=0;i<8;i++) tf32split(av[i], ahv[i], alv[i]);
        __syncthreads();
        *(uint4*)&Ah[arow*20 + akoff]     = make_uint4(ahv[0],ahv[1],ahv[2],ahv[3]);
        *(uint4*)&Ah[arow*20 + akoff + 4] = make_uint4(ahv[4],ahv[5],ahv[6],ahv[7]);
        *(uint4*)&Al[arow*20 + akoff]     = make_uint4(alv[0],alv[1],alv[2],alv[3]);
        *(uint4*)&Al[arow*20 + akoff + 4] = make_uint4(alv[4],alv[5],alv[6],alv[7]);
        *(uint4*)&Bh[arow*20 + akoff]     = pbh0;
        *(uint4*)&Bh[arow*20 + akoff + 4] = pbh1;
        *(uint4*)&Bl[arow*20 + akoff]     = pbl0;
        *(uint4*)&Bl[arow*20 + akoff + 4] = pbl1;
        __syncthreads();
        if (kc < 15){
            pa0 = *(const float4*)(aptr + kc*16 + 16);
            pa1 = *(const float4*)(aptr + kc*16 + 20);
            pbh0 = *(const uint4*)(bhp + kc*16 + 16);
            pbh1 = *(const uint4*)(bhp + kc*16 + 20);
            pbl0 = *(const uint4*)(blp + kc*16 + 16);
            pbl1 = *(const uint4*)(blp + kc*16 + 20);
        }
        #pragma unroll
        for (int kk = 0; kk < 16; kk += 8){
            uint32_t ah[4][4], al[4][4];
            #pragma unroll
            for (int mi=0; mi<4; mi++){
                int r = wm*64 + mi*16 + qr;
                ah[mi][0] = Ah[r*20 + kk + ql];
                ah[mi][1] = Ah[(r+8)*20 + kk + ql];
                ah[mi][2] = Ah[r*20 + kk + ql + 4];
                ah[mi][3] = Ah[(r+8)*20 + kk + ql + 4];
                al[mi][0] = Al[r*20 + kk + ql];
                al[mi][1] = Al[(r+8)*20 + kk + ql];
                al[mi][2] = Al[r*20 + kk + ql + 4];
                al[mi][3] = Al[(r+8)*20 + kk + ql + 4];
            }
            #pragma unroll
            for (int nj=0; nj<4; nj++){
                int n = wn*32 + nj*8 + qr;
                uint32_t bhv[2] = { Bh[n*20 + kk + ql], Bh[n*20 + kk + ql + 4] };
                uint32_t blv[2] = { Bl[n*20 + kk + ql], Bl[n*20 + kk + ql + 4] };
                #pragma unroll
                for (int mi=0; mi<4; mi++){
                    mma_tf32(acc[mi][nj], al[mi], bhv);
                    mma_tf32(acc[mi][nj], ah[mi], blv);
                    mma_tf32(acc[mi][nj], ah[mi], bhv);
                }
            }
        }
    }
    // epilogue
    #pragma unroll
    for (int mi=0; mi<4; mi++){
        int r0 = bm + wm*64 + mi*16 + qr;
        int r1 = r0 + 8;
        float mk0 = 0.f, mk1 = 0.f;
        if (mode){ mk0 = __ldg(meanV + r0); mk1 = __ldg(meanV + r1); }
        #pragma unroll
        for (int nj=0; nj<4; nj++){
            int c0 = bn + wn*32 + nj*8 + ql*2;
            float v00 = acc[mi][nj][0], v01 = acc[mi][nj][1];
            float v10 = acc[mi][nj][2], v11 = acc[mi][nj][3];
            if (mode){
                float g0 = g_G1[c0], g1 = g_G1[c0+1];
                float u0 = g_Ub[c0], u1 = g_Ub[c0+1];
                v00 = v00 - mk0*g0 + u0; v01 = v01 - mk0*g1 + u1;
                v10 = v10 - mk1*g0 + u0; v11 = v11 - mk1*g1 + u1;
            }
            *(float2*)(Cm + (size_t)r0*N + c0) = make_float2(v00, v01);
            *(float2*)(Cm + (size_t)r1*N + c0) = make_float2(v10, v11);
        }
    }
}

// ---------------- stats (warp-per-row) ----------------
__global__ __launch_bounds__(512) void stats2(const float* __restrict__ gp_w, const float* __restrict__ gp_b)
{
    int r = blockIdx.x*16 + (threadIdx.x>>5);
    int lane = threadIdx.x & 31;
    float m0=g_cov[0], m1=g_cov[1], mb=g_cov[2];
    float Vbb=g_cov[5], C0b=g_cov[7], C1b=g_cov[8];
    float g0[8], g1[8], gbv[8];
    #pragma unroll
    for (int k=0;k<8;k++){
        int d = k*32+lane;
        g0[k]=gp_w[d]-m0; g1[k]=gp_w[D+d]-m1; gbv[k]=gp_b[d]-mb;
    }
    #pragma unroll
    for (int br=0; br<2; br++){
        const float* src = br ? g_V : g_K;
        float sK=0,sK2=0,s0=0,s1=0,sb=0;
        #pragma unroll
        for (int k=0;k<8;k++){
            float x = src[(size_t)r*D + k*32 + lane];
            sK+=x; sK2=fmaf(x,x,sK2); s0=fmaf(x,g0[k],s0); s1=fmaf(x,g1[k],s1); sb=fmaf(x,gbv[k],sb);
        }
        sK=warpSum(sK); sK2=warpSum(sK2); s0=warpSum(s0); s1=warpSum(s1); sb=warpSum(sb);
        if (lane == 0){
            float mk = sK*(1.f/D);
            float Vkk = sK2*(1.f/D) - mk*mk;
            float Ck0 = s0*(1.f/D), Ck1 = s1*(1.f/D), Ckb = sb*(1.f/D);
            float* st = br ? (g_statsV + r*4) : (g_statsK + r*4);
            st[0] = Vkk + Vbb + 2.f*Ckb;
            st[1] = 2.f*(Ck0 + C0b);
            st[2] = 2.f*(Ck1 + C1b);
            st[3] = 0.f;
            if (br) g_meanV[r]=mk; else g_meanK[r]=mk;
        }
    }
}

// ---------------- per-slot q/wtil/scalars (1024 threads) ----------------
__device__ __forceinline__ void slot_compute(
    int s, int t, const float* so,
    const float* __restrict__ ns_g, const float* __restrict__ ns_b,
    const float* __restrict__ wq,   const float* __restrict__ W2, const float* __restrict__ b2,
    float* sh, float* sq, float* qp, float* red)
{
    int w = t >> 5, lane = t & 31;
    float v = (t < 256) ? so[t] : 0.f;
    float ws = warpSum(v);
    if (lane == 0 && t < 256) red[w] = ws;
    __syncthreads();
    float m = 0.f;
    #pragma unroll
    for (int i=0;i<8;i++) m += red[i];
    m *= (1.f/D);
    float d = (t < 256) ? (v - m) : 0.f;
    ws = warpSum(d*d);
    __syncthreads();
    if (lane == 0 && t < 256) red[w] = ws;
    __syncthreads();
    float var = 0.f;
    #pragma unroll
    for (int i=0;i<8;i++) var += red[i];
    var *= (1.f/D);
    if (t < 256) sh[t] = d * rsqrtf(var + LNEPS) * ns_g[t] + ns_b[t];
    __syncthreads();

    {
        int cg = t & 63, ks = t >> 6;
        const float4* wq4 = (const float4*)wq;
        float4 a = make_float4(0.f,0.f,0.f,0.f);
        #pragma unroll 4
        for (int j = ks*16; j < ks*16 + 16; j++){
            float4 wv = __ldg(wq4 + j*64 + cg);
            float sv = sh[j];
            a.x = fmaf(sv, wv.x, a.x);
            a.y = fmaf(sv, wv.y, a.y);
            a.z = fmaf(sv, wv.z, a.z);
            a.w = fmaf(sv, wv.w, a.w);
        }
        *(float4*)(qp + ks*256 + cg*4) = a;
    }
    __syncthreads();
    if (t < 256){
        float vq = 0.f;
        #pragma unroll
        for (int ks=0; ks<16; ks++) vq += qp[ks*256 + t];
        sq[t] = vq;
    }
    __syncthreads();

    float p = (t < 256) ? sq[t]*b2[t] : 0.f;
    ws = warpSum(p);
    __syncthreads();
    if (lane == 0 && t < 256) red[w] = ws;
    __syncthreads();

    float4 qa = *(const float4*)(sq + lane*8);
    float4 qb = *(const float4*)(sq + lane*8 + 4);
    #pragma unroll 2
    for (int k = 0; k < 16; k++){
        int j = (k << 5) + w;
        const float4* w2r = (const float4*)(W2 + j*D);
        float4 wa = __ldg(w2r + lane*2);
        float4 wb = __ldg(w2r + lane*2 + 1);
        float acc = wa.x*qa.x + wa.y*qa.y + wa.z*qa.z + wa.w*qa.w
                  + wb.x*qb.x + wb.y*qb.y + wb.z*qb.z + wb.w*qb.w;
        acc = warpSum(acc);
        if (lane == 0) g_slot[s*520 + j] = acc;
    }
    if (t == 0){
        float qb2 = 0.f;
        #pragma unroll
        for (int i=0;i<8;i++) qb2 += red[i];
        float px = fminf(fmaxf(g_Cond[s*260+256], -1.f), 1.f);
        float py = fminf(fmaxf(g_Cond[s*260+257], -1.f), 1.f);
        float sx = fminf(fmaxf(g_Cond[s*260+258], 1e-3f), 2.f);
        float sy = fminf(fmaxf(g_Cond[s*260+259], 1e-3f), 2.f);
        float* o = g_slot + s*520 + 512;
        o[0]=qb2; o[1]=px; o[2]=py; o[3]=1.f/(5.f*sx); o[4]=1.f/(5.f*sy);
    }
}

__global__ __launch_bounds__(1024) void slot0(const float* __restrict__ ns_g, const float* __restrict__ ns_b,
                                              const float* __restrict__ wq,   const float* __restrict__ W2,
                                              const float* __restrict__ b2)
{
    __shared__ float so[256], sh[256], sq[256], qp[4096], red[16];
    int s = blockIdx.x, t = threadIdx.x;
    if (t < 256) so[t] = g_Cond[s*260 + t];
    __syncthreads();
    slot_compute(s, t, so, ns_g, ns_b, wq, W2, b2, sh, sq, qp, red);
}

// ---------------- fused: dots + softmax + attn0 + partials ----------------
__global__ __launch_bounds__(256) void iter1_kernel(int last, float* __restrict__ out)
{
    int b = blockIdx.y, chunk = blockIdx.x;
    int t = threadIdx.x, w = t >> 5, lane = t & 31;
    __shared__ float sPk[16*512];
    __shared__ float sdots[NS][16];
    __shared__ float sscal[NS][5];

    float* attnDst = last ? (out + 16640) : g_attn0;
    float* relOut  = out + 16640 + 65536;
    int n0 = chunk*16;

    {
        const float4* src = (const float4*)(g_Pk + (((size_t)(b<<10) + n0)<<9));
        float4* dst = (float4*)sPk;
        #pragma unroll
        for (int i=0;i<8;i++) dst[t + i*256] = __ldg(src + t + i*256);
    }

    float4 u0v[4], u1v[4], wtv[4], cv[4];
    const float* wts = g_slot + (b*NS + w)*520;
    #pragma unroll
    for (int jj=0; jj<4; jj++){
        int j = jj*128 + lane*4;
        u0v[jj] = *(const float4*)(g_U0 + j);
        u1v[jj] = *(const float4*)(g_U1 + j);
        cv[jj]  = *(const float4*)(g_C  + j);
        wtv[jj] = *(const float4*)(wts  + j);
    }
    if (t < 40) sscal[t/5][t%5] = g_slot[(b*NS + t/5)*520 + 512 + (t%5)];
    __syncthreads();

    float qb2=sscal[w][0], px=sscal[w][1], py=sscal[w][2], i5x=sscal[w][3], i5y=sscal[w][4];
    float V00=g_cov[3], V11=g_cov[4], C01_2=2.f*g_cov[6];

    for (int pp=0; pp<16; pp++){
        int n = n0 + pp;
        float gx = -1.f + (float)(n>>5)*GSTEP;
        float gy = -1.f + (float)(n&31)*GSTEP;
        float a = (gx-px)*i5x, c = (gy-py)*i5y;
        const float4 st = *(const float4*)(g_statsK + ((b<<10)+n)*4);
        float var = st.x + a*st.y + c*st.z + a*a*V00 + c*c*V11 + a*c*C01_2;
        float isig = rsqrtf(var + LNEPS);
        const float* pk = sPk + pp*512;
        float ac0=0.f, ac1=0.f;
        #pragma unroll
        for (int jj=0; jj<4; jj++){
            float4 p4 = *(const float4*)(pk + jj*128 + lane*4);
            float e0 = fmaf(isig, fmaf(c,u1v[jj].x, fmaf(a,u0v[jj].x, p4.x)), cv[jj].x);
            float e1 = fmaf(isig, fmaf(c,u1v[jj].y, fmaf(a,u0v[jj].y, p4.y)), cv[jj].y);
            float e2 = fmaf(isig, fmaf(c,u1v[jj].z, fmaf(a,u0v[jj].z, p4.z)), cv[jj].z);
            float e3 = fmaf(isig, fmaf(c,u1v[jj].w, fmaf(a,u0v[jj].w, p4.w)), cv[jj].w);
            ac0 = fmaf(fmaxf(e0,0.f), wtv[jj].x, ac0);
            ac1 = fmaf(fmaxf(e1,0.f), wtv[jj].y, ac1);
            ac0 = fmaf(fmaxf(e2,0.f), wtv[jj].z, ac0);
            ac1 = fmaf(fmaxf(e3,0.f), wtv[jj].w, ac1);
        }
        float acc = warpSum(ac0 + ac1);
        if (lane == 0){
            sdots[w][pp] = ATTN_SCALE * (acc + qb2);
            if (last){
                float2* rp = (float2*)(relOut + ((((size_t)(b*NS+w)<<10)+n)<<1));
                *rp = make_float2(a, c);
            }
        }
    }
    __syncthreads();

    float a0 = 0.f, gx = 0.f, gy = 0.f;
    if (lane < 16){
        int n = n0 + lane;
        float dd[NS]; float mx = -1e30f;
        #pragma unroll
        for (int k=0;k<NS;k++){ dd[k] = sdots[k][lane]; mx = fmaxf(mx, dd[k]); }
        float sum = 0.f;
        #pragma unroll
        for (int k=0;k<NS;k++){ dd[k] = expf(dd[k]-mx); sum += dd[k]; }
        a0 = dd[w] / sum;
        attnDst[((b*NS+w)<<10) + n] = a0;
        gx = -1.f + (float)(n>>5)*GSTEP;
        gy = -1.f + (float)(n&31)*GSTEP;
    }
    float S0 = warpSum(a0);
    float Sx = warpSum(a0*gx);
    float Sy = warpSum(a0*gy);
    float Sxx = warpSum(a0*gx*gx);
    float Syy = warpSum(a0*gy*gy);
    if (lane == 0){
        float* pp = g_part + ((size_t)((b*NS+w)*64 + chunk))*8;
        pp[0]=S0; pp[1]=Sx; pp[2]=Sy; pp[3]=Sxx; pp[4]=Syy;
    }
}

// ---------------- slot-fused vacc + finalize ----------------
__global__ __launch_bounds__(512) void vaccF_kernel()
{
    int chunk = blockIdx.x;
    int b = blockIdx.y;
    int t = threadIdx.x;
    __shared__ float4 sC4[NS][64];
    __shared__ float sden[NS];

    int sl = t >> 6, p = t & 63;
    int n = chunk*64 + p;
    int gs = b*NS + sl;
    float rawA;
    {
        float px = g_slot[gs*520+513], py = g_slot[gs*520+514];
        float i5x= g_slot[gs*520+515], i5y= g_slot[gs*520+516];
        float gx = -1.f + (float)(n>>5)*GSTEP;
        float gy = -1.f + (float)(n&31)*GSTEP;
        float a = (gx-px)*i5x, c = (gy-py)*i5y;
        const float4 st = *(const float4*)(g_statsV + ((b<<10)+n)*4);
        float var = st.x + a*st.y + c*st.z + a*a*g_cov[3] + c*c*g_cov[4] + a*c*2.f*g_cov[6];
        float is = rsqrtf(var + LNEPS);
        rawA = g_attn0[(gs<<10)+n];
        sC4[sl][p] = make_float4(is, is*a, is*c, 0.f);
    }
    if (t < 256){
        int w = t >> 5, lane = t & 31;
        const float* pp0 = g_part + ((size_t)((b*NS+w)*64 + lane))*8;
        const float* pp1 = pp0 + 32*8;
        float S0 = warpSum(pp0[0] + pp1[0]);
        if (chunk == 0){
            float Sx = warpSum(pp0[1] + pp1[1]);
            float Sy = warpSum(pp0[2] + pp1[2]);
            float Sxx = warpSum(pp0[3] + pp1[3]);
            float Syy = warpSum(pp0[4] + pp1[4]);
            if (lane == 0){
                float px = Sx, py = Sy, G2 = g_cov[9];
                float vx = Sxx - 2.f*px*Sx + px*px*S0 + EPSA*(G2 + 1024.f*px*px);
                float vy = Syy - 2.f*py*Sy + py*py*S0 + EPSA*(G2 + 1024.f*py*py);
                float sx = fminf(fmaxf(sqrtf(fmaxf(vx,0.f)), 1e-3f), 2.f);
                float sy = fminf(fmaxf(sqrtf(fmaxf(vy,0.f)), 1e-3f), 2.f);
                int s2 = b*NS + w;
                g_Cond[s2*260+256]=px; g_Cond[s2*260+257]=py;
                g_Cond[s2*260+258]=sx; g_Cond[s2*260+259]=sy;
            }
        }
        if (lane == 0) sden[w] = 1.f/(S0 + 1024.f*EPSA);
    }
    __syncthreads();
    sC4[sl][p].w = (rawA + EPSA) * sden[sl];
    __syncthreads();

    float u0 = g_U0[t], u1 = g_U1[t], C = g_C[t];
    const float* pvb = g_Pv + ((((size_t)(b<<10)) + (size_t)chunk*64) << 9) + t;
    float acc[NS] = {};
    #pragma unroll 4
    for (int q=0; q<64; q++){
        float pv = __ldg(pvb + ((size_t)q << 9));
        #pragma unroll
        for (int s2=0; s2<NS; s2++){
            float4 cf = sC4[s2][q];
            float pre = fmaf(cf.y, u0, fmaf(cf.z, u1, fmaf(cf.x, pv, C)));
            acc[s2] = fmaf(fmaxf(pre, 0.f), cf.w, acc[s2]);
        }
    }
    #pragma unroll
    for (int s2=0; s2<NS; s2++)
        g_spart[((size_t)((b*NS+s2)*16 + chunk))*H + t] = acc[s2];
}

// ---------------- GRU update + slot prep for next iter ----------------
__global__ __launch_bounds__(1024) void updslot_kernel(
    const float* __restrict__ W2,  const float* __restrict__ b2,
    const float* __restrict__ Wih, const float* __restrict__ Whh,
    const float* __restrict__ bih, const float* __restrict__ bhh,
    const float* __restrict__ ns_g, const float* __restrict__ ns_b,
    const float* __restrict__ wq)
{
    __shared__ float ss[H], so[256], su[256], qp[4096], sgx[768], sgh[768], sh[256], sq[256], red[16];
    int s = blockIdx.x, t = threadIdx.x, w = t >> 5, lane = t & 31;

    if (t < 512){
        float r0 = 0.f;
        #pragma unroll
        for (int c=0; c<16; c++) r0 += g_spart[((size_t)(s*16 + c))*H + t];
        ss[t] = r0;
    }
    if (t < 256) so[t] = g_Cond[s*260 + t];
    __syncthreads();

    {
        int cg = t & 63, ks = t >> 6;
        const float4* W24 = (const float4*)W2;
        float4 a = make_float4(0.f,0.f,0.f,0.f);
        #pragma unroll 4
        for (int j = ks*32; j < ks*32 + 32; j++){
            float4 wv = __ldg(W24 + j*64 + cg);
            float sv = ss[j];
            a.x = fmaf(sv, wv.x, a.x);
            a.y = fmaf(sv, wv.y, a.y);
            a.z = fmaf(sv, wv.z, a.z);
            a.w = fmaf(sv, wv.w, a.w);
        }
        *(float4*)(qp + ks*256 + cg*4) = a;
    }
    __syncthreads();
    if (t < 256){
        float u = b2[t];
        #pragma unroll
        for (int ks=0; ks<16; ks++) u += qp[ks*256 + t];
        su[t] = u;
    }
    __syncthreads();

    {
        float4 sua = *(const float4*)(su + lane*8);
        float4 sub = *(const float4*)(su + lane*8 + 4);
        float4 soa = *(const float4*)(so + lane*8);
        float4 sob = *(const float4*)(so + lane*8 + 4);
        #pragma unroll 2
        for (int k = 0; k < 24; k++){
            int i = (k << 5) + w;
            const float4* wi4 = (const float4*)(Wih + i*D);
            const float4* wh4 = (const float4*)(Whh + i*D);
            float4 wa = __ldg(wi4 + lane*2);
            float4 wb = __ldg(wi4 + lane*2 + 1);
            float4 ha = __ldg(wh4 + lane*2);
            float4 hb = __ldg(wh4 + lane*2 + 1);
            float ax = wa.x*sua.x + wa.y*sua.y + wa.z*sua.z + wa.w*sua.w
                     + wb.x*sub.x + wb.y*sub.y + wb.z*sub.z + wb.w*sub.w;
            float ah = ha.x*soa.x + ha.y*soa.y + ha.z*soa.z + ha.w*soa.w
                     + hb.x*sob.x + hb.y*sob.y + hb.z*sob.z + hb.w*sob.w;
            ax = warpSum(ax); ah = warpSum(ah);
            if (lane == 0){ sgx[i] = ax + bih[i]; sgh[i] = ah + bhh[i]; }
        }
    }
    __syncthreads();

    if (t < 256){
        float r = 1.f/(1.f + expf(-(sgx[t]     + sgh[t])));
        float z = 1.f/(1.f + expf(-(sgx[256+t] + sgh[256+t])));
        float nn = tanhf(sgx[512+t] + r*sgh[512+t]);
        float nv = (1.f - z)*nn + z*so[t];
        g_Cond[s*260 + t] = nv;
        so[t] = nv;
    }
    __syncthreads();

    slot_compute(s, t, so, ns_g, ns_b, wq, W2, b2, sh, sq, qp, red);
}

// ---------------- final: pos/scl + write conditioning to out ----------------
__global__ void finz3_kernel(float* __restrict__ out)
{
    __shared__ float sres[4];
    int s = blockIdx.x, t = threadIdx.x;
    if (t < 32){
        const float* pp0 = g_part + ((size_t)(s*64 + t))*8;
        const float* pp1 = pp0 + 32*8;
        float S0 = warpSum(pp0[0] + pp1[0]);
        float Sx = warpSum(pp0[1] + pp1[1]);
        float Sy = warpSum(pp0[2] + pp1[2]);
        float Sxx = warpSum(pp0[3] + pp1[3]);
        float Syy = warpSum(pp0[4] + pp1[4]);
        if (t == 0){
            float px = Sx, py = Sy, G2 = g_cov[9];
            float vx = Sxx - 2.f*px*Sx + px*px*S0 + EPSA*(G2 + 1024.f*px*px);
            float vy = Syy - 2.f*py*Sy + py*py*S0 + EPSA*(G2 + 1024.f*py*py);
            float sx = fminf(fmaxf(sqrtf(fmaxf(vx,0.f)), 1e-3f), 2.f);
            float sy = fminf(fmaxf(sqrtf(fmaxf(vy,0.f)), 1e-3f), 2.f);
            sres[0]=px; sres[1]=py; sres[2]=sx; sres[3]=sy;
        }
    }
    __syncthreads();
    for (int i = t; i < 260; i += 256)
        out[s*260 + i] = (i < 256) ? g_Cond[s*260 + i] : sres[i - 256];
}

// ---------------- launch ----------------
extern "C" void kernel_launch(void* const* d_in, const int* in_sizes, int n_in,
                              void* d_out, int out_size)
{
    const float* inputs = (const float*)d_in[0];
    const float* cond   = (const float*)d_in[1];
    const float* ni_g   = (const float*)d_in[2];
    const float* ni_b   = (const float*)d_in[3];
    const float* ns_g   = (const float*)d_in[4];
    const float* ns_b   = (const float*)d_in[5];
    const float* wq     = (const float*)d_in[6];
    const float* wk     = (const float*)d_in[7];
    const float* wv     = (const float*)d_in[8];
    const float* gp_w   = (const float*)d_in[9];
    const float* gp_b   = (const float*)d_in[10];
    const float* ge_ln_g= (const float*)d_in[11];
    const float* ge_ln_b= (const float*)d_in[12];
    const float* ge_w1  = (const float*)d_in[13];
    const float* ge_b1  = (const float*)d_in[14];
    const float* ge_w2  = (const float*)d_in[15];
    const float* ge_b2  = (const float*)d_in[16];
    const float* gru_wih= (const float*)d_in[17];
    const float* gru_whh= (const float*)d_in[18];
    const float* gru_bih= (const float*)d_in[19];
    const float* gru_bhh= (const float*)d_in[20];
    float* out = (float*)d_out;

    pre_kernel<<<1058, 512>>>(gp_w, gp_b, ge_ln_g, ge_ln_b, ge_w1, ge_b1, cond, inputs, wk, wv);
    gemmT<<<dim3(2,64,2), 256>>>(0, inputs, ni_g, ni_b, 256);
    stats2<<<512, 512>>>(gp_w, gp_b);
    gemmT<<<dim3(4,64,2), 256>>>(2, nullptr, nullptr, nullptr, 512);
    slot0<<<64, 1024>>>(ns_g, ns_b, wq, ge_w2, ge_b2);

    for (int it = 0; it < 3; it++) {
        iter1_kernel<<<dim3(64,8), 256>>>(0, out);
        vaccF_kernel<<<dim3(16,8), 512>>>();
        updslot_kernel<<<64, 1024>>>(ge_w2, ge_b2, gru_wih, gru_whh, gru_bih, gru_bhh,
                                     ns_g, ns_b, wq);
    }
    iter1_kernel<<<dim3(64,8), 256>>>(1, out);
    finz3_kernel<<<64, 256>>>(out);
}

// round 12
// speedup vs baseline: 1.6059x; 1.6059x over previous
#include <cuda_runtime.h>
#include <math.h>
#include <stdint.h>

// ---------------- problem constants ----------------
#define NB 8
#define NPIX 1024
#define NS 8
#define D 256
#define H 512
#define NROWS (NB*NPIX)
#define EPSA 1e-8f
#define LNEPS 1e-5f
#define ATTN_SCALE 0.0625f
#define GSTEP (2.0f/31.0f)

// ---------------- scratch ----------------
__device__ __align__(16) float g_K [NROWS*D];
__device__ __align__(16) float g_V [NROWS*D];
__device__ __align__(16) float g_Pk[NROWS*H];
__device__ __align__(16) float g_Pv[NROWS*H];
__device__ __align__(16) float g_statsK[NROWS*4];
__device__ __align__(16) float g_statsV[NROWS*4];
__device__ float g_meanK[NROWS];
__device__ float g_meanV[NROWS];
__device__ float g_lnM[NROWS];
__device__ float g_lnIS[NROWS];
__device__ __align__(16) float g_U0[H];
__device__ __align__(16) float g_U1[H];
__device__ __align__(16) float g_Ub[H];
__device__ __align__(16) float g_C[H];
__device__ __align__(16) float g_G1[H];
__device__ float g_cov[16];
__device__ float g_Cond[NB*NS*260];
__device__ __align__(16) float g_slot[NB*NS*520];
__device__ float g_attn0[NB*NS*NPIX];
__device__ float g_part[NB*NS*64*8];
__device__ float g_spart[NB*NS*16*H];
// transposed + tf32-split weights (n-major: [n][k])
__device__ __align__(16) uint32_t g_WkTh[65536], g_WkTl[65536];
__device__ __align__(16) uint32_t g_WvTh[65536], g_WvTl[65536];
__device__ __align__(16) uint32_t g_W1Th[131072], g_W1Tl[131072];

__device__ __forceinline__ float warpSum(float v) {
    #pragma unroll
    for (int o = 16; o; o >>= 1) v += __shfl_xor_sync(0xffffffffu, v, o);
    return v;
}

__device__ __forceinline__ void tf32split(float x, uint32_t& h, uint32_t& l){
    uint32_t hb; asm("cvt.rna.tf32.f32 %0, %1;" : "=r"(hb) : "f"(x));
    float lo = x - __uint_as_float(hb);
    uint32_t lb; asm("cvt.rna.tf32.f32 %0, %1;" : "=r"(lb) : "f"(lo));
    h = hb; l = lb;
}

__device__ __forceinline__ void mma_tf32(float* d, const uint32_t* a, const uint32_t* b){
    asm volatile("mma.sync.aligned.m16n8k8.row.col.f32.tf32.tf32.f32 "
        "{%0,%1,%2,%3}, {%4,%5,%6,%7}, {%8,%9}, {%0,%1,%2,%3};"
        : "+f"(d[0]), "+f"(d[1]), "+f"(d[2]), "+f"(d[3])
        : "r"(a[0]), "r"(a[1]), "r"(a[2]), "r"(a[3]), "r"(b[0]), "r"(b[1]));
}

// ---------------- pre: constants + cond copy + LN row stats + weight transpose/split ----------------
__global__ __launch_bounds__(512) void pre_kernel(
    const float* __restrict__ gp_w, const float* __restrict__ gp_b,
    const float* __restrict__ lg,   const float* __restrict__ lb,
    const float* __restrict__ W1,   const float* __restrict__ b1,
    const float* __restrict__ cond, const float* __restrict__ inputs,
    const float* __restrict__ wk,   const float* __restrict__ wv)
{
    int bid = blockIdx.x;
    int t = threadIdx.x;
    if (bid >= 546){
        int idx = (bid - 546)*512 + t;
        if (idx < 65536){
            int k = idx >> 8, n = idx & 255;
            uint32_t h, l; tf32split(wk[idx], h, l);
            g_WkTh[n*256+k] = h; g_WkTl[n*256+k] = l;
        } else if (idx < 131072){
            int i2 = idx - 65536;
            int k = i2 >> 8, n = i2 & 255;
            uint32_t h, l; tf32split(wv[i2], h, l);
            g_WvTh[n*256+k] = h; g_WvTl[n*256+k] = l;
        } else {
            int i2 = idx - 131072;
            int k = i2 >> 9, n = i2 & 511;
            uint32_t h, l; tf32split(W1[i2] * lg[k], h, l);
            g_W1Th[n*256+k] = h; g_W1Tl[n*256+k] = l;
        }
        return;
    }
    if (bid >= 34) {
        int r = (bid - 34)*16 + (t>>5);
        int lane = t & 31;
        const float* row = inputs + (size_t)r*D;
        float v[8]; float s = 0.f;
        #pragma unroll
        for (int k=0;k<8;k++){ v[k]=row[k*32+lane]; s+=v[k]; }
        float m = warpSum(s) * (1.f/D);
        float q = 0.f;
        #pragma unroll
        for (int k=0;k<8;k++){ float d=v[k]-m; q += d*d; }
        float is = rsqrtf(warpSum(q)*(1.f/D) + LNEPS);
        if (lane == 0){ g_lnM[r]=m; g_lnIS[r]=is; }
        return;
    }
    if (bid > 0) {
        int i = (bid - 1)*512 + t;
        if (i < NB*NS*260) g_Cond[i] = cond[i];
        return;
    }
    __shared__ float sg0[D], sg1[D], sgb[D], slg[D], slb[D];
    __shared__ float sm[4];
    if (t < D) { sg0[t]=gp_w[t]; sg1[t]=gp_w[D+t]; sgb[t]=gp_b[t]; slg[t]=lg[t]; slb[t]=lb[t]; }
    __syncthreads();
    if (t == 0) {
        float m0=0,m1=0,mb=0;
        for (int d=0; d<D; d++){ m0+=sg0[d]; m1+=sg1[d]; mb+=sgb[d]; }
        m0*=(1.f/D); m1*=(1.f/D); mb*=(1.f/D);
        float V00=0,V11=0,Vbb=0,C01=0,C0b=0,C1b=0;
        for (int d=0; d<D; d++){
            float a=sg0[d]-m0, b_=sg1[d]-m1, c=sgb[d]-mb;
            V00+=a*a; V11+=b_*b_; Vbb+=c*c; C01+=a*b_; C0b+=a*c; C1b+=b_*c;
        }
        g_cov[0]=m0; g_cov[1]=m1; g_cov[2]=mb;
        g_cov[3]=V00/D; g_cov[4]=V11/D; g_cov[5]=Vbb/D;
        g_cov[6]=C01/D; g_cov[7]=C0b/D; g_cov[8]=C1b/D;
        float s2=0;
        for (int i=0;i<32;i++){ float x=-1.f + i*GSTEP; s2+=x*x; }
        g_cov[9]=s2*32.f;
        sm[0]=m0; sm[1]=m1; sm[2]=mb;
    }
    __syncthreads();
    float m0=sm[0], m1=sm[1], mb=sm[2];
    float U0=0,U1=0,Ub=0,Cc=0,G1=0;
    for (int d=0; d<D; d++){
        float w = W1[d*H + t];
        float gd = slg[d];
        U0 = fmaf((sg0[d]-m0)*gd, w, U0);
        U1 = fmaf((sg1[d]-m1)*gd, w, U1);
        Ub = fmaf((sgb[d]-mb)*gd, w, Ub);
        Cc = fmaf(slb[d], w, Cc);
        G1 = fmaf(gd, w, G1);
    }
    g_U0[t]=U0; g_U1[t]=U1; g_Ub[t]=Ub; g_C[t]=Cc + b1[t]; g_G1[t]=G1;
}

// ---------------- tensor-core GEMM: tf32 3-term split, 128x64 tile (R10 config) ----------------
// mode 0: C = LN(inputs)@wk / @wv  (z selects; N=256)
// mode 2: C = K@(diag(sg)W1) - mk*G1 + Ub   (sg folded into W1T; N=512)
__global__ __launch_bounds__(256,2) void gemmT(int mode, const float* __restrict__ A0,
                                               const float* __restrict__ sgv,
                                               const float* __restrict__ sbv, int N)
{
    int z = blockIdx.z;
    const float* A = (mode==0) ? A0 : (z ? g_V : g_K);
    const uint32_t* BTh = (mode==0) ? (z ? g_WvTh : g_WkTh) : g_W1Th;
    const uint32_t* BTl = (mode==0) ? (z ? g_WvTl : g_WkTl) : g_W1Tl;
    float* Cm = (mode==0) ? (z ? g_V : g_K) : (z ? g_Pv : g_Pk);
    const float* meanV = (mode==0) ? nullptr : (z ? g_meanV : g_meanK);

    __shared__ __align__(16) uint32_t Ah[128*20], Al[128*20];
    __shared__ __align__(16) uint32_t Bh[64*20],  Bl[64*20];
    __shared__ float SG[256], SB[256];

    int bm = blockIdx.y*128, bn = blockIdx.x*64;
    int tid = threadIdx.x, lane = tid & 31, wrp = tid >> 5;
    int wm = wrp & 3, wn = wrp >> 2;       // warp grid 4(M) x 2(N), warp tile 32x32
    int qr = lane >> 2, ql = lane & 3;

    if (mode == 0){ SG[tid] = sgv[tid]; SB[tid] = sbv[tid]; }

    int arow = tid >> 1, akoff = (tid & 1) * 8;
    int brow = tid >> 2, bkoff = (tid & 3) * 4;
    float rm = 0.f, ris = 1.f;
    if (mode == 0){ rm = g_lnM[bm+arow]; ris = g_lnIS[bm+arow]; }
    __syncthreads();

    float acc[2][4][4] = {};
    const float* aptr = A + (size_t)(bm+arow)*256 + akoff;
    const uint32_t* bhp = BTh + (size_t)(bn+brow)*256 + bkoff;
    const uint32_t* blp = BTl + (size_t)(bn+brow)*256 + bkoff;

    float4 pa0 = *(const float4*)aptr;
    float4 pa1 = *(const float4*)(aptr + 4);
    uint4 pbh = *(const uint4*)bhp;
    uint4 pbl = *(const uint4*)blp;

    #pragma unroll 1
    for (int kc = 0; kc < 16; kc++){
        float av[8] = {pa0.x,pa0.y,pa0.z,pa0.w,pa1.x,pa1.y,pa1.z,pa1.w};
        if (mode == 0){
            int kb = kc*16 + akoff;
            #pragma unroll
            for (int i=0;i<8;i++) av[i] = fmaf((av[i]-rm)*ris, SG[kb+i], SB[kb+i]);
        }
        uint32_t ahv[8], alv[8];
        #pragma unroll
        for (int i=0;i<8;i++) tf32split(av[i], ahv[i], alv[i]);
        __syncthreads();
        *(uint4*)&Ah[arow*20 + akoff]     = make_uint4(ahv[0],ahv[1],ahv[2],ahv[3]);
        *(uint4*)&Ah[arow*20 + akoff + 4] = make_uint4(ahv[4],ahv[5],ahv[6],ahv[7]);
        *(uint4*)&Al[arow*20 + akoff]     = make_uint4(alv[0],alv[1],alv[2],alv[3]);
        *(uint4*)&Al[arow*20 + akoff + 4] = make_uint4(alv[4],alv[5],alv[6],alv[7]);
        *(uint4*)&Bh[brow*20 + bkoff] = pbh;
        *(uint4*)&Bl[brow*20 + bkoff] = pbl;
        __syncthreads();
        if (kc < 15){
            pa0 = *(const float4*)(aptr + kc*16 + 16);
            pa1 = *(const float4*)(aptr + kc*16 + 20);
            pbh = *(const uint4*)(bhp + kc*16 + 16);
            pbl = *(const uint4*)(blp + kc*16 + 16);
        }
        #pragma unroll
        for (int kk = 0; kk < 16; kk += 8){
            uint32_t ah[2][4], al[2][4];
            #pragma unroll
            for (int mi=0; mi<2; mi++){
                int r = wm*32 + mi*16 + qr;
                ah[mi][0] = Ah[r*20 + kk + ql];
                ah[mi][1] = Ah[(r+8)*20 + kk + ql];
                ah[mi][2] = Ah[r*20 + kk + ql + 4];
                ah[mi][3] = Ah[(r+8)*20 + kk + ql + 4];
                al[mi][0] = Al[r*20 + kk + ql];
                al[mi][1] = Al[(r+8)*20 + kk + ql];
                al[mi][2] = Al[r*20 + kk + ql + 4];
                al[mi][3] = Al[(r+8)*20 + kk + ql + 4];
            }
            #pragma unroll
            for (int nj=0; nj<4; nj++){
                int n = wn*32 + nj*8 + qr;
                uint32_t bhv[2] = { Bh[n*20 + kk + ql], Bh[n*20 + kk + ql + 4] };
                uint32_t blv[2] = { Bl[n*20 + kk + ql], Bl[n*20 + kk + ql + 4] };
                #pragma unroll
                for (int mi=0; mi<2; mi++){
                    mma_tf32(acc[mi][nj], al[mi], bhv);
                    mma_tf32(acc[mi][nj], ah[mi], blv);
                    mma_tf32(acc[mi][nj], ah[mi], bhv);
                }
            }
        }
    }
    // epilogue
    #pragma unroll
    for (int mi=0; mi<2; mi++){
        int r0 = bm + wm*32 + mi*16 + qr;
        int r1 = r0 + 8;
        float mk0 = 0.f, mk1 = 0.f;
        if (mode){ mk0 = __ldg(meanV + r0); mk1 = __ldg(meanV + r1); }
        #pragma unroll
        for (int nj=0; nj<4; nj++){
            int c0 = bn + wn*32 + nj*8 + ql*2;
            float v00 = acc[mi][nj][0], v01 = acc[mi][nj][1];
            float v10 = acc[mi][nj][2], v11 = acc[mi][nj][3];
            if (mode){
                float g0 = g_G1[c0], g1 = g_G1[c0+1];
                float u0 = g_Ub[c0], u1 = g_Ub[c0+1];
                v00 = v00 - mk0*g0 + u0; v01 = v01 - mk0*g1 + u1;
                v10 = v10 - mk1*g0 + u0; v11 = v11 - mk1*g1 + u1;
            }
            *(float2*)(Cm + (size_t)r0*N + c0) = make_float2(v00, v01);
            *(float2*)(Cm + (size_t)r1*N + c0) = make_float2(v10, v11);
        }
    }
}

// ---------------- stats (warp-per-row) ----------------
__global__ __launch_bounds__(512) void stats2(const float* __restrict__ gp_w, const float* __restrict__ gp_b)
{
    int r = blockIdx.x*16 + (threadIdx.x>>5);
    int lane = threadIdx.x & 31;
    float m0=g_cov[0], m1=g_cov[1], mb=g_cov[2];
    float Vbb=g_cov[5], C0b=g_cov[7], C1b=g_cov[8];
    float g0[8], g1[8], gbv[8];
    #pragma unroll
    for (int k=0;k<8;k++){
        int d = k*32+lane;
        g0[k]=gp_w[d]-m0; g1[k]=gp_w[D+d]-m1; gbv[k]=gp_b[d]-mb;
    }
    #pragma unroll
    for (int br=0; br<2; br++){
        const float* src = br ? g_V : g_K;
        float sK=0,sK2=0,s0=0,s1=0,sb=0;
        #pragma unroll
        for (int k=0;k<8;k++){
            float x = src[(size_t)r*D + k*32 + lane];
            sK+=x; sK2=fmaf(x,x,sK2); s0=fmaf(x,g0[k],s0); s1=fmaf(x,g1[k],s1); sb=fmaf(x,gbv[k],sb);
        }
        sK=warpSum(sK); sK2=warpSum(sK2); s0=warpSum(s0); s1=warpSum(s1); sb=warpSum(sb);
        if (lane == 0){
            float mk = sK*(1.f/D);
            float Vkk = sK2*(1.f/D) - mk*mk;
            float Ck0 = s0*(1.f/D), Ck1 = s1*(1.f/D), Ckb = sb*(1.f/D);
            float* st = br ? (g_statsV + r*4) : (g_statsK + r*4);
            st[0] = Vkk + Vbb + 2.f*Ckb;
            st[1] = 2.f*(Ck0 + C0b);
            st[2] = 2.f*(Ck1 + C1b);
            st[3] = 0.f;
            if (br) g_meanV[r]=mk; else g_meanK[r]=mk;
        }
    }
}

// ---------------- per-slot q/wtil/scalars (1024 threads) ----------------
__device__ __forceinline__ void slot_compute(
    int s, int t, const float* so,
    const float* __restrict__ ns_g, const float* __restrict__ ns_b,
    const float* __restrict__ wq,   const float* __restrict__ W2, const float* __restrict__ b2,
    float* sh, float* sq, float* qp, float* red)
{
    int w = t >> 5, lane = t & 31;
    float v = (t < 256) ? so[t] : 0.f;
    float ws = warpSum(v);
    if (lane == 0 && t < 256) red[w] = ws;
    __syncthreads();
    float m = 0.f;
    #pragma unroll
    for (int i=0;i<8;i++) m += red[i];
    m *= (1.f/D);
    float d = (t < 256) ? (v - m) : 0.f;
    ws = warpSum(d*d);
    __syncthreads();
    if (lane == 0 && t < 256) red[w] = ws;
    __syncthreads();
    float var = 0.f;
    #pragma unroll
    for (int i=0;i<8;i++) var += red[i];
    var *= (1.f/D);
    if (t < 256) sh[t] = d * rsqrtf(var + LNEPS) * ns_g[t] + ns_b[t];
    __syncthreads();

    {
        int cg = t & 63, ks = t >> 6;
        const float4* wq4 = (const float4*)wq;
        float4 a = make_float4(0.f,0.f,0.f,0.f);
        #pragma unroll 4
        for (int j = ks*16; j < ks*16 + 16; j++){
            float4 wv = __ldg(wq4 + j*64 + cg);
            float sv = sh[j];
            a.x = fmaf(sv, wv.x, a.x);
            a.y = fmaf(sv, wv.y, a.y);
            a.z = fmaf(sv, wv.z, a.z);
            a.w = fmaf(sv, wv.w, a.w);
        }
        *(float4*)(qp + ks*256 + cg*4) = a;
    }
    __syncthreads();
    if (t < 256){
        float vq = 0.f;
        #pragma unroll
        for (int ks=0; ks<16; ks++) vq += qp[ks*256 + t];
        sq[t] = vq;
    }
    __syncthreads();

    float p = (t < 256) ? sq[t]*b2[t] : 0.f;
    ws = warpSum(p);
    __syncthreads();
    if (lane == 0 && t < 256) red[w] = ws;
    __syncthreads();

    float4 qa = *(const float4*)(sq + lane*8);
    float4 qb = *(const float4*)(sq + lane*8 + 4);
    #pragma unroll 2
    for (int k = 0; k < 16; k++){
        int j = (k << 5) + w;
        const float4* w2r = (const float4*)(W2 + j*D);
        float4 wa = __ldg(w2r + lane*2);
        float4 wb = __ldg(w2r + lane*2 + 1);
        float acc = wa.x*qa.x + wa.y*qa.y + wa.z*qa.z + wa.w*qa.w
                  + wb.x*qb.x + wb.y*qb.y + wb.z*qb.z + wb.w*qb.w;
        acc = warpSum(acc);
        if (lane == 0) g_slot[s*520 + j] = acc;
    }
    if (t == 0){
        float qb2 = 0.f;
        #pragma unroll
        for (int i=0;i<8;i++) qb2 += red[i];
        float px = fminf(fmaxf(g_Cond[s*260+256], -1.f), 1.f);
        float py = fminf(fmaxf(g_Cond[s*260+257], -1.f), 1.f);
        float sx = fminf(fmaxf(g_Cond[s*260+258], 1e-3f), 2.f);
        float sy = fminf(fmaxf(g_Cond[s*260+259], 1e-3f), 2.f);
        float* o = g_slot + s*520 + 512;
        o[0]=qb2; o[1]=px; o[2]=py; o[3]=1.f/(5.f*sx); o[4]=1.f/(5.f*sy);
    }
}

__global__ __launch_bounds__(1024) void slot0(const float* __restrict__ ns_g, const float* __restrict__ ns_b,
                                              const float* __restrict__ wq,   const float* __restrict__ W2,
                                              const float* __restrict__ b2)
{
    __shared__ float so[256], sh[256], sq[256], qp[4096], red[16];
    int s = blockIdx.x, t = threadIdx.x;
    if (t < 256) so[t] = g_Cond[s*260 + t];
    __syncthreads();
    slot_compute(s, t, so, ns_g, ns_b, wq, W2, b2, sh, sq, qp, red);
}

// ---------------- fused: dots + softmax + attn0 + partials (2-px ILP) ----------------
__global__ __launch_bounds__(256) void iter1_kernel(int last, float* __restrict__ out)
{
    int b = blockIdx.y, chunk = blockIdx.x;
    int t = threadIdx.x, w = t >> 5, lane = t & 31;
    __shared__ float sPk[16*512];
    __shared__ float sdots[NS][16];
    __shared__ float sscal[NS][5];

    float* attnDst = last ? (out + 16640) : g_attn0;
    float* relOut  = out + 16640 + 65536;
    int n0 = chunk*16;

    {
        const float4* src = (const float4*)(g_Pk + (((size_t)(b<<10) + n0)<<9));
        float4* dst = (float4*)sPk;
        #pragma unroll
        for (int i=0;i<8;i++) dst[t + i*256] = __ldg(src + t + i*256);
    }

    float4 u0v[4], u1v[4], wtv[4], cv[4];
    const float* wts = g_slot + (b*NS + w)*520;
    #pragma unroll
    for (int jj=0; jj<4; jj++){
        int j = jj*128 + lane*4;
        u0v[jj] = *(const float4*)(g_U0 + j);
        u1v[jj] = *(const float4*)(g_U1 + j);
        cv[jj]  = *(const float4*)(g_C  + j);
        wtv[jj] = *(const float4*)(wts  + j);
    }
    if (t < 40) sscal[t/5][t%5] = g_slot[(b*NS + t/5)*520 + 512 + (t%5)];
    __syncthreads();

    float qb2=sscal[w][0], px=sscal[w][1], py=sscal[w][2], i5x=sscal[w][3], i5y=sscal[w][4];
    float V00=g_cov[3], V11=g_cov[4], C01_2=2.f*g_cov[6];

    for (int pp=0; pp<16; pp+=2){
        int nA = n0 + pp, nB = nA + 1;
        float gxA = -1.f + (float)(nA>>5)*GSTEP, gyA = -1.f + (float)(nA&31)*GSTEP;
        float gxB = -1.f + (float)(nB>>5)*GSTEP, gyB = -1.f + (float)(nB&31)*GSTEP;
        float aA = (gxA-px)*i5x, cA = (gyA-py)*i5y;
        float aB = (gxB-px)*i5x, cB = (gyB-py)*i5y;
        const float4 stA = *(const float4*)(g_statsK + ((b<<10)+nA)*4);
        const float4 stB = *(const float4*)(g_statsK + ((b<<10)+nB)*4);
        float varA = stA.x + aA*stA.y + cA*stA.z + aA*aA*V00 + cA*cA*V11 + aA*cA*C01_2;
        float varB = stB.x + aB*stB.y + cB*stB.z + aB*aB*V00 + cB*cB*V11 + aB*cB*C01_2;
        float isA = rsqrtf(varA + LNEPS);
        float isB = rsqrtf(varB + LNEPS);
        const float* pkA = sPk + pp*512;
        const float* pkB = pkA + 512;
        float acA0=0.f, acA1=0.f, acB0=0.f, acB1=0.f;
        #pragma unroll
        for (int jj=0; jj<4; jj++){
            float4 p4A = *(const float4*)(pkA + jj*128 + lane*4);
            float4 p4B = *(const float4*)(pkB + jj*128 + lane*4);
            float eA0 = fmaf(isA, fmaf(cA,u1v[jj].x, fmaf(aA,u0v[jj].x, p4A.x)), cv[jj].x);
            float eB0 = fmaf(isB, fmaf(cB,u1v[jj].x, fmaf(aB,u0v[jj].x, p4B.x)), cv[jj].x);
            float eA1 = fmaf(isA, fmaf(cA,u1v[jj].y, fmaf(aA,u0v[jj].y, p4A.y)), cv[jj].y);
            float eB1 = fmaf(isB, fmaf(cB,u1v[jj].y, fmaf(aB,u0v[jj].y, p4B.y)), cv[jj].y);
            float eA2 = fmaf(isA, fmaf(cA,u1v[jj].z, fmaf(aA,u0v[jj].z, p4A.z)), cv[jj].z);
            float eB2 = fmaf(isB, fmaf(cB,u1v[jj].z, fmaf(aB,u0v[jj].z, p4B.z)), cv[jj].z);
            float eA3 = fmaf(isA, fmaf(cA,u1v[jj].w, fmaf(aA,u0v[jj].w, p4A.w)), cv[jj].w);
            float eB3 = fmaf(isB, fmaf(cB,u1v[jj].w, fmaf(aB,u0v[jj].w, p4B.w)), cv[jj].w);
            acA0 = fmaf(fmaxf(eA0,0.f), wtv[jj].x, acA0);
            acB0 = fmaf(fmaxf(eB0,0.f), wtv[jj].x, acB0);
            acA1 = fmaf(fmaxf(eA1,0.f), wtv[jj].y, acA1);
            acB1 = fmaf(fmaxf(eB1,0.f), wtv[jj].y, acB1);
            acA0 = fmaf(fmaxf(eA2,0.f), wtv[jj].z, acA0);
            acB0 = fmaf(fmaxf(eB2,0.f), wtv[jj].z, acB0);
            acA1 = fmaf(fmaxf(eA3,0.f), wtv[jj].w, acA1);
            acB1 = fmaf(fmaxf(eB3,0.f), wtv[jj].w, acB1);
        }
        float sA = acA0 + acA1, sB = acB0 + acB1;
        #pragma unroll
        for (int o=16;o;o>>=1){
            sA += __shfl_xor_sync(0xffffffffu, sA, o);
            sB += __shfl_xor_sync(0xffffffffu, sB, o);
        }
        if (lane == 0){
            sdots[w][pp]   = ATTN_SCALE * (sA + qb2);
            sdots[w][pp+1] = ATTN_SCALE * (sB + qb2);
            if (last){
                float2* rpA = (float2*)(relOut + ((((size_t)(b*NS+w)<<10)+nA)<<1));
                float2* rpB = (float2*)(relOut + ((((size_t)(b*NS+w)<<10)+nB)<<1));
                *rpA = make_float2(aA, cA);
                *rpB = make_float2(aB, cB);
            }
        }
    }
    __syncthreads();

    float a0 = 0.f, gx = 0.f, gy = 0.f;
    if (lane < 16){
        int n = n0 + lane;
        float dd[NS]; float mx = -1e30f;
        #pragma unroll
        for (int k=0;k<NS;k++){ dd[k] = sdots[k][lane]; mx = fmaxf(mx, dd[k]); }
        float sum = 0.f;
        #pragma unroll
        for (int k=0;k<NS;k++){ dd[k] = expf(dd[k]-mx); sum += dd[k]; }
        a0 = dd[w] / sum;
        attnDst[((b*NS+w)<<10) + n] = a0;
        gx = -1.f + (float)(n>>5)*GSTEP;
        gy = -1.f + (float)(n&31)*GSTEP;
    }
    float S0 = warpSum(a0);
    float Sx = warpSum(a0*gx);
    float Sy = warpSum(a0*gy);
    float Sxx = warpSum(a0*gx*gx);
    float Syy = warpSum(a0*gy*gy);
    if (lane == 0){
        float* pp = g_part + ((size_t)((b*NS+w)*64 + chunk))*8;
        pp[0]=S0; pp[1]=Sx; pp[2]=Sy; pp[3]=Sxx; pp[4]=Syy;
    }
}

// ---------------- slot-fused vacc + finalize ----------------
__global__ __launch_bounds__(512) void vaccF_kernel()
{
    int chunk = blockIdx.x;
    int b = blockIdx.y;
    int t = threadIdx.x;
    __shared__ float4 sC4[NS][64];
    __shared__ float sden[NS];

    int sl = t >> 6, p = t & 63;
    int n = chunk*64 + p;
    int gs = b*NS + sl;
    float rawA;
    {
        float px = g_slot[gs*520+513], py = g_slot[gs*520+514];
        float i5x= g_slot[gs*520+515], i5y= g_slot[gs*520+516];
        float gx = -1.f + (float)(n>>5)*GSTEP;
        float gy = -1.f + (float)(n&31)*GSTEP;
        float a = (gx-px)*i5x, c = (gy-py)*i5y;
        const float4 st = *(const float4*)(g_statsV + ((b<<10)+n)*4);
        float var = st.x + a*st.y + c*st.z + a*a*g_cov[3] + c*c*g_cov[4] + a*c*2.f*g_cov[6];
        float is = rsqrtf(var + LNEPS);
        rawA = g_attn0[(gs<<10)+n];
        sC4[sl][p] = make_float4(is, is*a, is*c, 0.f);
    }
    if (t < 256){
        int w = t >> 5, lane = t & 31;
        const float* pp0 = g_part + ((size_t)((b*NS+w)*64 + lane))*8;
        const float* pp1 = pp0 + 32*8;
        float S0 = warpSum(pp0[0] + pp1[0]);
        if (chunk == 0){
            float Sx = warpSum(pp0[1] + pp1[1]);
            float Sy = warpSum(pp0[2] + pp1[2]);
            float Sxx = warpSum(pp0[3] + pp1[3]);
            float Syy = warpSum(pp0[4] + pp1[4]);
            if (lane == 0){
                float px = Sx, py = Sy, G2 = g_cov[9];
                float vx = Sxx - 2.f*px*Sx + px*px*S0 + EPSA*(G2 + 1024.f*px*px);
                float vy = Syy - 2.f*py*Sy + py*py*S0 + EPSA*(G2 + 1024.f*py*py);
                float sx = fminf(fmaxf(sqrtf(fmaxf(vx,0.f)), 1e-3f), 2.f);
                float sy = fminf(fmaxf(sqrtf(fmaxf(vy,0.f)), 1e-3f), 2.f);
                int s2 = b*NS + w;
                g_Cond[s2*260+256]=px; g_Cond[s2*260+257]=py;
                g_Cond[s2*260+258]=sx; g_Cond[s2*260+259]=sy;
            }
        }
        if (lane == 0) sden[w] = 1.f/(S0 + 1024.f*EPSA);
    }
    __syncthreads();
    sC4[sl][p].w = (rawA + EPSA) * sden[sl];
    __syncthreads();

    float u0 = g_U0[t], u1 = g_U1[t], C = g_C[t];
    const float* pvb = g_Pv + ((((size_t)(b<<10)) + (size_t)chunk*64) << 9) + t;
    float acc[NS] = {};
    #pragma unroll 4
    for (int q=0; q<64; q++){
        float pv = __ldg(pvb + ((size_t)q << 9));
        #pragma unroll
        for (int s2=0; s2<NS; s2++){
            float4 cf = sC4[s2][q];
            float pre = fmaf(cf.y, u0, fmaf(cf.z, u1, fmaf(cf.x, pv, C)));
            acc[s2] = fmaf(fmaxf(pre, 0.f), cf.w, acc[s2]);
        }
    }
    #pragma unroll
    for (int s2=0; s2<NS; s2++)
        g_spart[((size_t)((b*NS+s2)*16 + chunk))*H + t] = acc[s2];
}

// ---------------- GRU update + slot prep for next iter ----------------
__global__ __launch_bounds__(1024) void updslot_kernel(
    const float* __restrict__ W2,  const float* __restrict__ b2,
    const float* __restrict__ Wih, const float* __restrict__ Whh,
    const float* __restrict__ bih, const float* __restrict__ bhh,
    const float* __restrict__ ns_g, const float* __restrict__ ns_b,
    const float* __restrict__ wq)
{
    __shared__ float ss[H], so[256], su[256], qp[4096], sgx[768], sgh[768], sh[256], sq[256], red[16];
    int s = blockIdx.x, t = threadIdx.x, w = t >> 5, lane = t & 31;

    if (t < 512){
        float r0 = 0.f;
        #pragma unroll
        for (int c=0; c<16; c++) r0 += g_spart[((size_t)(s*16 + c))*H + t];
        ss[t] = r0;
    }
    if (t < 256) so[t] = g_Cond[s*260 + t];
    __syncthreads();

    {
        int cg = t & 63, ks = t >> 6;
        const float4* W24 = (const float4*)W2;
        float4 a = make_float4(0.f,0.f,0.f,0.f);
        #pragma unroll 4
        for (int j = ks*32; j < ks*32 + 32; j++){
            float4 wv = __ldg(W24 + j*64 + cg);
            float sv = ss[j];
            a.x = fmaf(sv, wv.x, a.x);
            a.y = fmaf(sv, wv.y, a.y);
            a.z = fmaf(sv, wv.z, a.z);
            a.w = fmaf(sv, wv.w, a.w);
        }
        *(float4*)(qp + ks*256 + cg*4) = a;
    }
    __syncthreads();
    if (t < 256){
        float u = b2[t];
        #pragma unroll
        for (int ks=0; ks<16; ks++) u += qp[ks*256 + t];
        su[t] = u;
    }
    __syncthreads();

    {
        float4 sua = *(const float4*)(su + lane*8);
        float4 sub = *(const float4*)(su + lane*8 + 4);
        float4 soa = *(const float4*)(so + lane*8);
        float4 sob = *(const float4*)(so + lane*8 + 4);
        #pragma unroll 2
        for (int k = 0; k < 24; k++){
            int i = (k << 5) + w;
            const float4* wi4 = (const float4*)(Wih + i*D);
            const float4* wh4 = (const float4*)(Whh + i*D);
            float4 wa = __ldg(wi4 + lane*2);
            float4 wb = __ldg(wi4 + lane*2 + 1);
            float4 ha = __ldg(wh4 + lane*2);
            float4 hb = __ldg(wh4 + lane*2 + 1);
            float ax = wa.x*sua.x + wa.y*sua.y + wa.z*sua.z + wa.w*sua.w
                     + wb.x*sub.x + wb.y*sub.y + wb.z*sub.z + wb.w*sub.w;
            float ah = ha.x*soa.x + ha.y*soa.y + ha.z*soa.z + ha.w*soa.w
                     + hb.x*sob.x + hb.y*sob.y + hb.z*sob.z + hb.w*sob.w;
            ax = warpSum(ax); ah = warpSum(ah);
            if (lane == 0){ sgx[i] = ax + bih[i]; sgh[i] = ah + bhh[i]; }
        }
    }
    __syncthreads();

    if (t < 256){
        float r = 1.f/(1.f + expf(-(sgx[t]     + sgh[t])));
        float z = 1.f/(1.f + expf(-(sgx[256+t] + sgh[256+t])));
        float nn = tanhf(sgx[512+t] + r*sgh[512+t]);
        float nv = (1.f - z)*nn + z*so[t];
        g_Cond[s*260 + t] = nv;
        so[t] = nv;
    }
    __syncthreads();

    slot_compute(s, t, so, ns_g, ns_b, wq, W2, b2, sh, sq, qp, red);
}

// ---------------- final: pos/scl + write conditioning to out ----------------
__global__ void finz3_kernel(float* __restrict__ out)
{
    __shared__ float sres[4];
    int s = blockIdx.x, t = threadIdx.x;
    if (t < 32){
        const float* pp0 = g_part + ((size_t)(s*64 + t))*8;
        const float* pp1 = pp0 + 32*8;
        float S0 = warpSum(pp0[0] + pp1[0]);
        float Sx = warpSum(pp0[1] + pp1[1]);
        float Sy = warpSum(pp0[2] + pp1[2]);
        float Sxx = warpSum(pp0[3] + pp1[3]);
        float Syy = warpSum(pp0[4] + pp1[4]);
        if (t == 0){
            float px = Sx, py = Sy, G2 = g_cov[9];
            float vx = Sxx - 2.f*px*Sx + px*px*S0 + EPSA*(G2 + 1024.f*px*px);
            float vy = Syy - 2.f*py*Sy + py*py*S0 + EPSA*(G2 + 1024.f*py*py);
            float sx = fminf(fmaxf(sqrtf(fmaxf(vx,0.f)), 1e-3f), 2.f);
            float sy = fminf(fmaxf(sqrtf(fmaxf(vy,0.f)), 1e-3f), 2.f);
            sres[0]=px; sres[1]=py; sres[2]=sx; sres[3]=sy;
        }
    }
    __syncthreads();
    for (int i = t; i < 260; i += 256)
        out[s*260 + i] = (i < 256) ? g_Cond[s*260 + i] : sres[i - 256];
}

// ---------------- launch ----------------
extern "C" void kernel_launch(void* const* d_in, const int* in_sizes, int n_in,
                              void* d_out, int out_size)
{
    const float* inputs = (const float*)d_in[0];
    const float* cond   = (const float*)d_in[1];
    const float* ni_g   = (const float*)d_in[2];
    const float* ni_b   = (const float*)d_in[3];
    const float* ns_g   = (const float*)d_in[4];
    const float* ns_b   = (const float*)d_in[5];
    const float* wq     = (const float*)d_in[6];
    const float* wk     = (const float*)d_in[7];
    const float* wv     = (const float*)d_in[8];
    const float* gp_w   = (const float*)d_in[9];
    const float* gp_b   = (const float*)d_in[10];
    const float* ge_ln_g= (const float*)d_in[11];
    const float* ge_ln_b= (const float*)d_in[12];
    const float* ge_w1  = (const float*)d_in[13];
    const float* ge_b1  = (const float*)d_in[14];
    const float* ge_w2  = (const float*)d_in[15];
    const float* ge_b2  = (const float*)d_in[16];
    const float* gru_wih= (const float*)d_in[17];
    const float* gru_whh= (const float*)d_in[18];
    const float* gru_bih= (const float*)d_in[19];
    const float* gru_bhh= (const float*)d_in[20];
    float* out = (float*)d_out;

    pre_kernel<<<1058, 512>>>(gp_w, gp_b, ge_ln_g, ge_ln_b, ge_w1, ge_b1, cond, inputs, wk, wv);
    gemmT<<<dim3(4,64,2), 256>>>(0, inputs, ni_g, ni_b, 256);
    stats2<<<512, 512>>>(gp_w, gp_b);
    gemmT<<<dim3(8,64,2), 256>>>(2, nullptr, nullptr, nullptr, 512);
    slot0<<<64, 1024>>>(ns_g, ns_b, wq, ge_w2, ge_b2);

    for (int it = 0; it < 3; it++) {
        iter1_kernel<<<dim3(64,8), 256>>>(0, out);
        vaccF_kernel<<<dim3(16,8), 512>>>();
        updslot_kernel<<<64, 1024>>>(ge_w2, ge_b2, gru_wih, gru_whh, gru_bih, gru_bhh,
                                     ns_g, ns_b, wq);
    }
    iter1_kernel<<<dim3(64,8), 256>>>(1, out);
    finz3_kernel<<<64, 256>>>(out);
}

// round 13
// speedup vs baseline: 1.6241x; 1.0113x over previous
#include <cuda_runtime.h>
#include <math.h>
#include <stdint.h>

// ---------------- problem constants ----------------
#define NB 8
#define NPIX 1024
#define NS 8
#define D 256
#define H 512
#define NROWS (NB*NPIX)
#define EPSA 1e-8f
#define LNEPS 1e-5f
#define ATTN_SCALE 0.0625f
#define GSTEP (2.0f/31.0f)

// ---------------- scratch ----------------
__device__ __align__(16) float g_K [NROWS*D];
__device__ __align__(16) float g_V [NROWS*D];
__device__ __align__(16) float g_Pk[NROWS*H];
__device__ __align__(16) float g_Pv[NROWS*H];
__device__ __align__(16) float g_statsK[NROWS*4];
__device__ __align__(16) float g_statsV[NROWS*4];
__device__ float g_meanK[NROWS];
__device__ float g_meanV[NROWS];
__device__ float g_lnM[NROWS];
__device__ float g_lnIS[NROWS];
__device__ __align__(16) float g_U0[H];
__device__ __align__(16) float g_U1[H];
__device__ __align__(16) float g_Ub[H];
__device__ __align__(16) float g_C[H];
__device__ __align__(16) float g_G1[H];
__device__ float g_cov[16];
__device__ float g_Cond[NB*NS*260];
__device__ __align__(16) float g_slot[NB*NS*520];
__device__ float g_attn0[NB*NS*NPIX];
__device__ float g_part[NB*NS*64*8];
__device__ float g_spart[NB*NS*16*H];
// transposed + tf32-split weights (n-major: [n][k])
__device__ __align__(16) uint32_t g_WkTh[65536], g_WkTl[65536];
__device__ __align__(16) uint32_t g_WvTh[65536], g_WvTl[65536];
__device__ __align__(16) uint32_t g_W1Th[131072], g_W1Tl[131072];

__device__ __forceinline__ float warpSum(float v) {
    #pragma unroll
    for (int o = 16; o; o >>= 1) v += __shfl_xor_sync(0xffffffffu, v, o);
    return v;
}

__device__ __forceinline__ void tf32split(float x, uint32_t& h, uint32_t& l){
    uint32_t hb; asm("cvt.rna.tf32.f32 %0, %1;" : "=r"(hb) : "f"(x));
    float lo = x - __uint_as_float(hb);
    uint32_t lb; asm("cvt.rna.tf32.f32 %0, %1;" : "=r"(lb) : "f"(lo));
    h = hb; l = lb;
}

__device__ __forceinline__ void mma_tf32(float* d, const uint32_t* a, const uint32_t* b){
    asm volatile("mma.sync.aligned.m16n8k8.row.col.f32.tf32.tf32.f32 "
        "{%0,%1,%2,%3}, {%4,%5,%6,%7}, {%8,%9}, {%0,%1,%2,%3};"
        : "+f"(d[0]), "+f"(d[1]), "+f"(d[2]), "+f"(d[3])
        : "r"(a[0]), "r"(a[1]), "r"(a[2]), "r"(a[3]), "r"(b[0]), "r"(b[1]));
}

// ---------------- pre: constants + cond copy + LN row stats + weight transpose/split ----------------
__global__ __launch_bounds__(512) void pre_kernel(
    const float* __restrict__ gp_w, const float* __restrict__ gp_b,
    const float* __restrict__ lg,   const float* __restrict__ lb,
    const float* __restrict__ W1,   const float* __restrict__ b1,
    const float* __restrict__ cond, const float* __restrict__ inputs,
    const float* __restrict__ wk,   const float* __restrict__ wv)
{
    int bid = blockIdx.x;
    int t = threadIdx.x;
    if (bid >= 546){
        int idx = (bid - 546)*512 + t;
        if (idx < 65536){
            int k = idx >> 8, n = idx & 255;
            uint32_t h, l; tf32split(wk[idx], h, l);
            g_WkTh[n*256+k] = h; g_WkTl[n*256+k] = l;
        } else if (idx < 131072){
            int i2 = idx - 65536;
            int k = i2 >> 8, n = i2 & 255;
            uint32_t h, l; tf32split(wv[i2], h, l);
            g_WvTh[n*256+k] = h; g_WvTl[n*256+k] = l;
        } else {
            int i2 = idx - 131072;
            int k = i2 >> 9, n = i2 & 511;
            uint32_t h, l; tf32split(W1[i2] * lg[k], h, l);
            g_W1Th[n*256+k] = h; g_W1Tl[n*256+k] = l;
        }
        return;
    }
    if (bid >= 34) {
        int r = (bid - 34)*16 + (t>>5);
        int lane = t & 31;
        const float* row = inputs + (size_t)r*D;
        float v[8]; float s = 0.f;
        #pragma unroll
        for (int k=0;k<8;k++){ v[k]=row[k*32+lane]; s+=v[k]; }
        float m = warpSum(s) * (1.f/D);
        float q = 0.f;
        #pragma unroll
        for (int k=0;k<8;k++){ float d=v[k]-m; q += d*d; }
        float is = rsqrtf(warpSum(q)*(1.f/D) + LNEPS);
        if (lane == 0){ g_lnM[r]=m; g_lnIS[r]=is; }
        return;
    }
    if (bid > 0) {
        int i = (bid - 1)*512 + t;
        if (i < NB*NS*260) g_Cond[i] = cond[i];
        return;
    }
    __shared__ float sg0[D], sg1[D], sgb[D], slg[D], slb[D];
    __shared__ float sm[4];
    if (t < D) { sg0[t]=gp_w[t]; sg1[t]=gp_w[D+t]; sgb[t]=gp_b[t]; slg[t]=lg[t]; slb[t]=lb[t]; }
    __syncthreads();
    if (t == 0) {
        float m0=0,m1=0,mb=0;
        for (int d=0; d<D; d++){ m0+=sg0[d]; m1+=sg1[d]; mb+=sgb[d]; }
        m0*=(1.f/D); m1*=(1.f/D); mb*=(1.f/D);
        float V00=0,V11=0,Vbb=0,C01=0,C0b=0,C1b=0;
        for (int d=0; d<D; d++){
            float a=sg0[d]-m0, b_=sg1[d]-m1, c=sgb[d]-mb;
            V00+=a*a; V11+=b_*b_; Vbb+=c*c; C01+=a*b_; C0b+=a*c; C1b+=b_*c;
        }
        g_cov[0]=m0; g_cov[1]=m1; g_cov[2]=mb;
        g_cov[3]=V00/D; g_cov[4]=V11/D; g_cov[5]=Vbb/D;
        g_cov[6]=C01/D; g_cov[7]=C0b/D; g_cov[8]=C1b/D;
        float s2=0;
        for (int i=0;i<32;i++){ float x=-1.f + i*GSTEP; s2+=x*x; }
        g_cov[9]=s2*32.f;
        sm[0]=m0; sm[1]=m1; sm[2]=mb;
    }
    __syncthreads();
    float m0=sm[0], m1=sm[1], mb=sm[2];
    float U0=0,U1=0,Ub=0,Cc=0,G1=0;
    for (int d=0; d<D; d++){
        float w = W1[d*H + t];
        float gd = slg[d];
        U0 = fmaf((sg0[d]-m0)*gd, w, U0);
        U1 = fmaf((sg1[d]-m1)*gd, w, U1);
        Ub = fmaf((sgb[d]-mb)*gd, w, Ub);
        Cc = fmaf(slb[d], w, Cc);
        G1 = fmaf(gd, w, G1);
    }
    g_U0[t]=U0; g_U1[t]=U1; g_Ub[t]=Ub; g_C[t]=Cc + b1[t]; g_G1[t]=G1;
}

// ---------------- tensor-core GEMM: tf32 split, 128x64 tile ----------------
// mode 0: C = LN(inputs)@wk / @wv  (3-term split; N=256)
// mode 2: C = K@(diag(sg)W1) - mk*G1 + Ub  (2-term split, Bl dropped; N=512)
__global__ __launch_bounds__(256,2) void gemmT(int mode, const float* __restrict__ A0,
                                               const float* __restrict__ sgv,
                                               const float* __restrict__ sbv, int N)
{
    int z = blockIdx.z;
    const float* A = (mode==0) ? A0 : (z ? g_V : g_K);
    const uint32_t* BTh = (mode==0) ? (z ? g_WvTh : g_WkTh) : g_W1Th;
    const uint32_t* BTl = (mode==0) ? (z ? g_WvTl : g_WkTl) : g_W1Tl;
    float* Cm = (mode==0) ? (z ? g_V : g_K) : (z ? g_Pv : g_Pk);
    const float* meanV = (mode==0) ? nullptr : (z ? g_meanV : g_meanK);

    __shared__ __align__(16) uint32_t Ah[128*20], Al[128*20];
    __shared__ __align__(16) uint32_t Bh[64*20],  Bl[64*20];
    __shared__ float SG[256], SB[256];

    int bm = blockIdx.y*128, bn = blockIdx.x*64;
    int tid = threadIdx.x, lane = tid & 31, wrp = tid >> 5;
    int wm = wrp & 3, wn = wrp >> 2;       // warp grid 4(M) x 2(N), warp tile 32x32
    int qr = lane >> 2, ql = lane & 3;

    if (mode == 0){ SG[tid] = sgv[tid]; SB[tid] = sbv[tid]; }

    int arow = tid >> 1, akoff = (tid & 1) * 8;
    int brow = tid >> 2, bkoff = (tid & 3) * 4;
    float rm = 0.f, ris = 1.f;
    if (mode == 0){ rm = g_lnM[bm+arow]; ris = g_lnIS[bm+arow]; }
    __syncthreads();

    float acc[2][4][4] = {};
    const float* aptr = A + (size_t)(bm+arow)*256 + akoff;
    const uint32_t* bhp = BTh + (size_t)(bn+brow)*256 + bkoff;
    const uint32_t* blp = BTl + (size_t)(bn+brow)*256 + bkoff;

    float4 pa0 = *(const float4*)aptr;
    float4 pa1 = *(const float4*)(aptr + 4);
    uint4 pbh = *(const uint4*)bhp;
    uint4 pbl = make_uint4(0,0,0,0);
    if (mode == 0) pbl = *(const uint4*)blp;

    #pragma unroll 1
    for (int kc = 0; kc < 16; kc++){
        float av[8] = {pa0.x,pa0.y,pa0.z,pa0.w,pa1.x,pa1.y,pa1.z,pa1.w};
        if (mode == 0){
            int kb = kc*16 + akoff;
            #pragma unroll
            for (int i=0;i<8;i++) av[i] = fmaf((av[i]-rm)*ris, SG[kb+i], SB[kb+i]);
        }
        uint32_t ahv[8], alv[8];
        #pragma unroll
        for (int i=0;i<8;i++) tf32split(av[i], ahv[i], alv[i]);
        __syncthreads();
        *(uint4*)&Ah[arow*20 + akoff]     = make_uint4(ahv[0],ahv[1],ahv[2],ahv[3]);
        *(uint4*)&Ah[arow*20 + akoff + 4] = make_uint4(ahv[4],ahv[5],ahv[6],ahv[7]);
        *(uint4*)&Al[arow*20 + akoff]     = make_uint4(alv[0],alv[1],alv[2],alv[3]);
        *(uint4*)&Al[arow*20 + akoff + 4] = make_uint4(alv[4],alv[5],alv[6],alv[7]);
        *(uint4*)&Bh[brow*20 + bkoff] = pbh;
        if (mode == 0) *(uint4*)&Bl[brow*20 + bkoff] = pbl;
        __syncthreads();
        if (kc < 15){
            pa0 = *(const float4*)(aptr + kc*16 + 16);
            pa1 = *(const float4*)(aptr + kc*16 + 20);
            pbh = *(const uint4*)(bhp + kc*16 + 16);
            if (mode == 0) pbl = *(const uint4*)(blp + kc*16 + 16);
        }
        #pragma unroll
        for (int kk = 0; kk < 16; kk += 8){
            uint32_t ah[2][4], al[2][4];
            #pragma unroll
            for (int mi=0; mi<2; mi++){
                int r = wm*32 + mi*16 + qr;
                ah[mi][0] = Ah[r*20 + kk + ql];
                ah[mi][1] = Ah[(r+8)*20 + kk + ql];
                ah[mi][2] = Ah[r*20 + kk + ql + 4];
                ah[mi][3] = Ah[(r+8)*20 + kk + ql + 4];
                al[mi][0] = Al[r*20 + kk + ql];
                al[mi][1] = Al[(r+8)*20 + kk + ql];
                al[mi][2] = Al[r*20 + kk + ql + 4];
                al[mi][3] = Al[(r+8)*20 + kk + ql + 4];
            }
            #pragma unroll
            for (int nj=0; nj<4; nj++){
                int n = wn*32 + nj*8 + qr;
                uint32_t bhv[2] = { Bh[n*20 + kk + ql], Bh[n*20 + kk + ql + 4] };
                #pragma unroll
                for (int mi=0; mi<2; mi++){
                    mma_tf32(acc[mi][nj], al[mi], bhv);
                    mma_tf32(acc[mi][nj], ah[mi], bhv);
                }
                if (mode == 0){
                    uint32_t blv[2] = { Bl[n*20 + kk + ql], Bl[n*20 + kk + ql + 4] };
                    #pragma unroll
                    for (int mi=0; mi<2; mi++)
                        mma_tf32(acc[mi][nj], ah[mi], blv);
                }
            }
        }
    }
    // epilogue
    #pragma unroll
    for (int mi=0; mi<2; mi++){
        int r0 = bm + wm*32 + mi*16 + qr;
        int r1 = r0 + 8;
        float mk0 = 0.f, mk1 = 0.f;
        if (mode){ mk0 = __ldg(meanV + r0); mk1 = __ldg(meanV + r1); }
        #pragma unroll
        for (int nj=0; nj<4; nj++){
            int c0 = bn + wn*32 + nj*8 + ql*2;
            float v00 = acc[mi][nj][0], v01 = acc[mi][nj][1];
            float v10 = acc[mi][nj][2], v11 = acc[mi][nj][3];
            if (mode){
                float g0 = g_G1[c0], g1 = g_G1[c0+1];
                float u0 = g_Ub[c0], u1 = g_Ub[c0+1];
                v00 = v00 - mk0*g0 + u0; v01 = v01 - mk0*g1 + u1;
                v10 = v10 - mk1*g0 + u0; v11 = v11 - mk1*g1 + u1;
            }
            *(float2*)(Cm + (size_t)r0*N + c0) = make_float2(v00, v01);
            *(float2*)(Cm + (size_t)r1*N + c0) = make_float2(v10, v11);
        }
    }
}

// ---------------- stats (warp-per-row) ----------------
__global__ __launch_bounds__(512) void stats2(const float* __restrict__ gp_w, const float* __restrict__ gp_b)
{
    int r = blockIdx.x*16 + (threadIdx.x>>5);
    int lane = threadIdx.x & 31;
    float m0=g_cov[0], m1=g_cov[1], mb=g_cov[2];
    float Vbb=g_cov[5], C0b=g_cov[7], C1b=g_cov[8];
    float g0[8], g1[8], gbv[8];
    #pragma unroll
    for (int k=0;k<8;k++){
        int d = k*32+lane;
        g0[k]=gp_w[d]-m0; g1[k]=gp_w[D+d]-m1; gbv[k]=gp_b[d]-mb;
    }
    #pragma unroll
    for (int br=0; br<2; br++){
        const float* src = br ? g_V : g_K;
        float sK=0,sK2=0,s0=0,s1=0,sb=0;
        #pragma unroll
        for (int k=0;k<8;k++){
            float x = src[(size_t)r*D + k*32 + lane];
            sK+=x; sK2=fmaf(x,x,sK2); s0=fmaf(x,g0[k],s0); s1=fmaf(x,g1[k],s1); sb=fmaf(x,gbv[k],sb);
        }
        sK=warpSum(sK); sK2=warpSum(sK2); s0=warpSum(s0); s1=warpSum(s1); sb=warpSum(sb);
        if (lane == 0){
            float mk = sK*(1.f/D);
            float Vkk = sK2*(1.f/D) - mk*mk;
            float Ck0 = s0*(1.f/D), Ck1 = s1*(1.f/D), Ckb = sb*(1.f/D);
            float* st = br ? (g_statsV + r*4) : (g_statsK + r*4);
            st[0] = Vkk + Vbb + 2.f*Ckb;
            st[1] = 2.f*(Ck0 + C0b);
            st[2] = 2.f*(Ck1 + C1b);
            st[3] = 0.f;
            if (br) g_meanV[r]=mk; else g_meanK[r]=mk;
        }
    }
}

// ---------------- per-slot q/wtil/scalars (1024 threads) ----------------
__device__ __forceinline__ void slot_compute(
    int s, int t, const float* so,
    const float* __restrict__ ns_g, const float* __restrict__ ns_b,
    const float* __restrict__ wq,   const float* __restrict__ W2, const float* __restrict__ b2,
    float* sh, float* sq, float* qp, float* red)
{
    int w = t >> 5, lane = t & 31;
    float v = (t < 256) ? so[t] : 0.f;
    float ws = warpSum(v);
    if (lane == 0 && t < 256) red[w] = ws;
    __syncthreads();
    float m = 0.f;
    #pragma unroll
    for (int i=0;i<8;i++) m += red[i];
    m *= (1.f/D);
    float d = (t < 256) ? (v - m) : 0.f;
    ws = warpSum(d*d);
    __syncthreads();
    if (lane == 0 && t < 256) red[w] = ws;
    __syncthreads();
    float var = 0.f;
    #pragma unroll
    for (int i=0;i<8;i++) var += red[i];
    var *= (1.f/D);
    if (t < 256) sh[t] = d * rsqrtf(var + LNEPS) * ns_g[t] + ns_b[t];
    __syncthreads();

    {
        int cg = t & 63, ks = t >> 6;
        const float4* wq4 = (const float4*)wq;
        float4 a = make_float4(0.f,0.f,0.f,0.f);
        #pragma unroll 4
        for (int j = ks*16; j < ks*16 + 16; j++){
            float4 wv = __ldg(wq4 + j*64 + cg);
            float sv = sh[j];
            a.x = fmaf(sv, wv.x, a.x);
            a.y = fmaf(sv, wv.y, a.y);
            a.z = fmaf(sv, wv.z, a.z);
            a.w = fmaf(sv, wv.w, a.w);
        }
        *(float4*)(qp + ks*256 + cg*4) = a;
    }
    __syncthreads();
    if (t < 256){
        float vq = 0.f;
        #pragma unroll
        for (int ks=0; ks<16; ks++) vq += qp[ks*256 + t];
        sq[t] = vq;
    }
    __syncthreads();

    float p = (t < 256) ? sq[t]*b2[t] : 0.f;
    ws = warpSum(p);
    __syncthreads();
    if (lane == 0 && t < 256) red[w] = ws;
    __syncthreads();

    float4 qa = *(const float4*)(sq + lane*8);
    float4 qb = *(const float4*)(sq + lane*8 + 4);
    #pragma unroll 2
    for (int k = 0; k < 16; k++){
        int j = (k << 5) + w;
        const float4* w2r = (const float4*)(W2 + j*D);
        float4 wa = __ldg(w2r + lane*2);
        float4 wb = __ldg(w2r + lane*2 + 1);
        float acc = wa.x*qa.x + wa.y*qa.y + wa.z*qa.z + wa.w*qa.w
                  + wb.x*qb.x + wb.y*qb.y + wb.z*qb.z + wb.w*qb.w;
        acc = warpSum(acc);
        if (lane == 0) g_slot[s*520 + j] = acc;
    }
    if (t == 0){
        float qb2 = 0.f;
        #pragma unroll
        for (int i=0;i<8;i++) qb2 += red[i];
        float px = fminf(fmaxf(g_Cond[s*260+256], -1.f), 1.f);
        float py = fminf(fmaxf(g_Cond[s*260+257], -1.f), 1.f);
        float sx = fminf(fmaxf(g_Cond[s*260+258], 1e-3f), 2.f);
        float sy = fminf(fmaxf(g_Cond[s*260+259], 1e-3f), 2.f);
        float* o = g_slot + s*520 + 512;
        o[0]=qb2; o[1]=px; o[2]=py; o[3]=1.f/(5.f*sx); o[4]=1.f/(5.f*sy);
    }
}

__global__ __launch_bounds__(1024) void slot0(const float* __restrict__ ns_g, const float* __restrict__ ns_b,
                                              const float* __restrict__ wq,   const float* __restrict__ W2,
                                              const float* __restrict__ b2)
{
    __shared__ float so[256], sh[256], sq[256], qp[4096], red[16];
    int s = blockIdx.x, t = threadIdx.x;
    if (t < 256) so[t] = g_Cond[s*260 + t];
    __syncthreads();
    slot_compute(s, t, so, ns_g, ns_b, wq, W2, b2, sh, sq, qp, red);
}

// ---------------- fused: dots + softmax + attn0 + partials (2-px ILP) ----------------
__global__ __launch_bounds__(256) void iter1_kernel(int last, float* __restrict__ out)
{
    int b = blockIdx.y, chunk = blockIdx.x;
    int t = threadIdx.x, w = t >> 5, lane = t & 31;
    __shared__ float sPk[16*512];
    __shared__ float sdots[NS][16];
    __shared__ float sscal[NS][5];

    float* attnDst = last ? (out + 16640) : g_attn0;
    float* relOut  = out + 16640 + 65536;
    int n0 = chunk*16;

    {
        const float4* src = (const float4*)(g_Pk + (((size_t)(b<<10) + n0)<<9));
        float4* dst = (float4*)sPk;
        #pragma unroll
        for (int i=0;i<8;i++) dst[t + i*256] = __ldg(src + t + i*256);
    }

    float4 u0v[4], u1v[4], wtv[4], cv[4];
    const float* wts = g_slot + (b*NS + w)*520;
    #pragma unroll
    for (int jj=0; jj<4; jj++){
        int j = jj*128 + lane*4;
        u0v[jj] = *(const float4*)(g_U0 + j);
        u1v[jj] = *(const float4*)(g_U1 + j);
        cv[jj]  = *(const float4*)(g_C  + j);
        wtv[jj] = *(const float4*)(wts  + j);
    }
    if (t < 40) sscal[t/5][t%5] = g_slot[(b*NS + t/5)*520 + 512 + (t%5)];
    __syncthreads();

    float qb2=sscal[w][0], px=sscal[w][1], py=sscal[w][2], i5x=sscal[w][3], i5y=sscal[w][4];
    float V00=g_cov[3], V11=g_cov[4], C01_2=2.f*g_cov[6];

    for (int pp=0; pp<16; pp+=2){
        int nA = n0 + pp, nB = nA + 1;
        float gxA = -1.f + (float)(nA>>5)*GSTEP, gyA = -1.f + (float)(nA&31)*GSTEP;
        float gxB = -1.f + (float)(nB>>5)*GSTEP, gyB = -1.f + (float)(nB&31)*GSTEP;
        float aA = (gxA-px)*i5x, cA = (gyA-py)*i5y;
        float aB = (gxB-px)*i5x, cB = (gyB-py)*i5y;
        const float4 stA = *(const float4*)(g_statsK + ((b<<10)+nA)*4);
        const float4 stB = *(const float4*)(g_statsK + ((b<<10)+nB)*4);
        float varA = stA.x + aA*stA.y + cA*stA.z + aA*aA*V00 + cA*cA*V11 + aA*cA*C01_2;
        float varB = stB.x + aB*stB.y + cB*stB.z + aB*aB*V00 + cB*cB*V11 + aB*cB*C01_2;
        float isA = rsqrtf(varA + LNEPS);
        float isB = rsqrtf(varB + LNEPS);
        const float* pkA = sPk + pp*512;
        const float* pkB = pkA + 512;
        float acA0=0.f, acA1=0.f, acB0=0.f, acB1=0.f;
        #pragma unroll
        for (int jj=0; jj<4; jj++){
            float4 p4A = *(const float4*)(pkA + jj*128 + lane*4);
            float4 p4B = *(const float4*)(pkB + jj*128 + lane*4);
            float eA0 = fmaf(isA, fmaf(cA,u1v[jj].x, fmaf(aA,u0v[jj].x, p4A.x)), cv[jj].x);
            float eB0 = fmaf(isB, fmaf(cB,u1v[jj].x, fmaf(aB,u0v[jj].x, p4B.x)), cv[jj].x);
            float eA1 = fmaf(isA, fmaf(cA,u1v[jj].y, fmaf(aA,u0v[jj].y, p4A.y)), cv[jj].y);
            float eB1 = fmaf(isB, fmaf(cB,u1v[jj].y, fmaf(aB,u0v[jj].y, p4B.y)), cv[jj].y);
            float eA2 = fmaf(isA, fmaf(cA,u1v[jj].z, fmaf(aA,u0v[jj].z, p4A.z)), cv[jj].z);
            float eB2 = fmaf(isB, fmaf(cB,u1v[jj].z, fmaf(aB,u0v[jj].z, p4B.z)), cv[jj].z);
            float eA3 = fmaf(isA, fmaf(cA,u1v[jj].w, fmaf(aA,u0v[jj].w, p4A.w)), cv[jj].w);
            float eB3 = fmaf(isB, fmaf(cB,u1v[jj].w, fmaf(aB,u0v[jj].w, p4B.w)), cv[jj].w);
            acA0 = fmaf(fmaxf(eA0,0.f), wtv[jj].x, acA0);
            acB0 = fmaf(fmaxf(eB0,0.f), wtv[jj].x, acB0);
            acA1 = fmaf(fmaxf(eA1,0.f), wtv[jj].y, acA1);
            acB1 = fmaf(fmaxf(eB1,0.f), wtv[jj].y, acB1);
            acA0 = fmaf(fmaxf(eA2,0.f), wtv[jj].z, acA0);
            acB0 = fmaf(fmaxf(eB2,0.f), wtv[jj].z, acB0);
            acA1 = fmaf(fmaxf(eA3,0.f), wtv[jj].w, acA1);
            acB1 = fmaf(fmaxf(eB3,0.f), wtv[jj].w, acB1);
        }
        float sA = acA0 + acA1, sB = acB0 + acB1;
        #pragma unroll
        for (int o=16;o;o>>=1){
            sA += __shfl_xor_sync(0xffffffffu, sA, o);
            sB += __shfl_xor_sync(0xffffffffu, sB, o);
        }
        if (lane == 0){
            sdots[w][pp]   = ATTN_SCALE * (sA + qb2);
            sdots[w][pp+1] = ATTN_SCALE * (sB + qb2);
            if (last){
                float2* rpA = (float2*)(relOut + ((((size_t)(b*NS+w)<<10)+nA)<<1));
                float2* rpB = (float2*)(relOut + ((((size_t)(b*NS+w)<<10)+nB)<<1));
                *rpA = make_float2(aA, cA);
                *rpB = make_float2(aB, cB);
            }
        }
    }
    __syncthreads();

    float a0 = 0.f, gx = 0.f, gy = 0.f;
    if (lane < 16){
        int n = n0 + lane;
        float dd[NS]; float mx = -1e30f;
        #pragma unroll
        for (int k=0;k<NS;k++){ dd[k] = sdots[k][lane]; mx = fmaxf(mx, dd[k]); }
        float sum = 0.f;
        #pragma unroll
        for (int k=0;k<NS;k++){ dd[k] = expf(dd[k]-mx); sum += dd[k]; }
        a0 = dd[w] / sum;
        attnDst[((b*NS+w)<<10) + n] = a0;
        gx = -1.f + (float)(n>>5)*GSTEP;
        gy = -1.f + (float)(n&31)*GSTEP;
    }
    float S0 = warpSum(a0);
    float Sx = warpSum(a0*gx);
    float Sy = warpSum(a0*gy);
    float Sxx = warpSum(a0*gx*gx);
    float Syy = warpSum(a0*gy*gy);
    if (lane == 0){
        float* pp = g_part + ((size_t)((b*NS+w)*64 + chunk))*8;
        pp[0]=S0; pp[1]=Sx; pp[2]=Sy; pp[3]=Sxx; pp[4]=Syy;
    }
}

// ---------------- slot-fused vacc + finalize ----------------
__global__ __launch_bounds__(512) void vaccF_kernel()
{
    int chunk = blockIdx.x;
    int b = blockIdx.y;
    int t = threadIdx.x;
    __shared__ float4 sC4[NS][64];
    __shared__ float sden[NS];

    int sl = t >> 6, p = t & 63;
    int n = chunk*64 + p;
    int gs = b*NS + sl;
    float rawA;
    {
        float px = g_slot[gs*520+513], py = g_slot[gs*520+514];
        float i5x= g_slot[gs*520+515], i5y= g_slot[gs*520+516];
        float gx = -1.f + (float)(n>>5)*GSTEP;
        float gy = -1.f + (float)(n&31)*GSTEP;
        float a = (gx-px)*i5x, c = (gy-py)*i5y;
        const float4 st = *(const float4*)(g_statsV + ((b<<10)+n)*4);
        float var = st.x + a*st.y + c*st.z + a*a*g_cov[3] + c*c*g_cov[4] + a*c*2.f*g_cov[6];
        float is = rsqrtf(var + LNEPS);
        rawA = g_attn0[(gs<<10)+n];
        sC4[sl][p] = make_float4(is, is*a, is*c, 0.f);
    }
    if (t < 256){
        int w = t >> 5, lane = t & 31;
        const float* pp0 = g_part + ((size_t)((b*NS+w)*64 + lane))*8;
        const float* pp1 = pp0 + 32*8;
        float S0 = warpSum(pp0[0] + pp1[0]);
        if (chunk == 0){
            float Sx = warpSum(pp0[1] + pp1[1]);
            float Sy = warpSum(pp0[2] + pp1[2]);
            float Sxx = warpSum(pp0[3] + pp1[3]);
            float Syy = warpSum(pp0[4] + pp1[4]);
            if (lane == 0){
                float px = Sx, py = Sy, G2 = g_cov[9];
                float vx = Sxx - 2.f*px*Sx + px*px*S0 + EPSA*(G2 + 1024.f*px*px);
                float vy = Syy - 2.f*py*Sy + py*py*S0 + EPSA*(G2 + 1024.f*py*py);
                float sx = fminf(fmaxf(sqrtf(fmaxf(vx,0.f)), 1e-3f), 2.f);
                float sy = fminf(fmaxf(sqrtf(fmaxf(vy,0.f)), 1e-3f), 2.f);
                int s2 = b*NS + w;
                g_Cond[s2*260+256]=px; g_Cond[s2*260+257]=py;
                g_Cond[s2*260+258]=sx; g_Cond[s2*260+259]=sy;
            }
        }
        if (lane == 0) sden[w] = 1.f/(S0 + 1024.f*EPSA);
    }
    __syncthreads();
    sC4[sl][p].w = (rawA + EPSA) * sden[sl];
    __syncthreads();

    float u0 = g_U0[t], u1 = g_U1[t], C = g_C[t];
    const float* pvb = g_Pv + ((((size_t)(b<<10)) + (size_t)chunk*64) << 9) + t;
    float acc[NS] = {};
    #pragma unroll 4
    for (int q=0; q<64; q++){
        float pv = __ldg(pvb + ((size_t)q << 9));
        #pragma unroll
        for (int s2=0; s2<NS; s2++){
            float4 cf = sC4[s2][q];
            float pre = fmaf(cf.y, u0, fmaf(cf.z, u1, fmaf(cf.x, pv, C)));
            acc[s2] = fmaf(fmaxf(pre, 0.f), cf.w, acc[s2]);
        }
    }
    #pragma unroll
    for (int s2=0; s2<NS; s2++)
        g_spart[((size_t)((b*NS+s2)*16 + chunk))*H + t] = acc[s2];
}

// ---------------- GRU update + slot prep for next iter ----------------
__global__ __launch_bounds__(1024) void updslot_kernel(
    const float* __restrict__ W2,  const float* __restrict__ b2,
    const float* __restrict__ Wih, const float* __restrict__ Whh,
    const float* __restrict__ bih, const float* __restrict__ bhh,
    const float* __restrict__ ns_g, const float* __restrict__ ns_b,
    const float* __restrict__ wq)
{
    __shared__ float ss[H], so[256], su[256], qp[4096], sgx[768], sgh[768], sh[256], sq[256], red[16];
    int s = blockIdx.x, t = threadIdx.x, w = t >> 5, lane = t & 31;

    if (t < 512){
        float r0 = 0.f;
        #pragma unroll
        for (int c=0; c<16; c++) r0 += g_spart[((size_t)(s*16 + c))*H + t];
        ss[t] = r0;
    }
    if (t < 256) so[t] = g_Cond[s*260 + t];
    __syncthreads();

    {
        int cg = t & 63, ks = t >> 6;
        const float4* W24 = (const float4*)W2;
        float4 a = make_float4(0.f,0.f,0.f,0.f);
        #pragma unroll 4
        for (int j = ks*32; j < ks*32 + 32; j++){
            float4 wv = __ldg(W24 + j*64 + cg);
            float sv = ss[j];
            a.x = fmaf(sv, wv.x, a.x);
            a.y = fmaf(sv, wv.y, a.y);
            a.z = fmaf(sv, wv.z, a.z);
            a.w = fmaf(sv, wv.w, a.w);
        }
        *(float4*)(qp + ks*256 + cg*4) = a;
    }
    __syncthreads();
    if (t < 256){
        float u = b2[t];
        #pragma unroll
        for (int ks=0; ks<16; ks++) u += qp[ks*256 + t];
        su[t] = u;
    }
    __syncthreads();

    {
        float4 sua = *(const float4*)(su + lane*8);
        float4 sub = *(const float4*)(su + lane*8 + 4);
        float4 soa = *(const float4*)(so + lane*8);
        float4 sob = *(const float4*)(so + lane*8 + 4);
        #pragma unroll 2
        for (int k = 0; k < 24; k++){
            int i = (k << 5) + w;
            const float4* wi4 = (const float4*)(Wih + i*D);
            const float4* wh4 = (const float4*)(Whh + i*D);
            float4 wa = __ldg(wi4 + lane*2);
            float4 wb = __ldg(wi4 + lane*2 + 1);
            float4 ha = __ldg(wh4 + lane*2);
            float4 hb = __ldg(wh4 + lane*2 + 1);
            float ax = wa.x*sua.x + wa.y*sua.y + wa.z*sua.z + wa.w*sua.w
                     + wb.x*sub.x + wb.y*sub.y + wb.z*sub.z + wb.w*sub.w;
            float ah = ha.x*soa.x + ha.y*soa.y + ha.z*soa.z + ha.w*soa.w
                     + hb.x*sob.x + hb.y*sob.y + hb.z*sob.z + hb.w*sob.w;
            ax = warpSum(ax); ah = warpSum(ah);
            if (lane == 0){ sgx[i] = ax + bih[i]; sgh[i] = ah + bhh[i]; }
        }
    }
    __syncthreads();

    if (t < 256){
        float r = 1.f/(1.f + expf(-(sgx[t]     + sgh[t])));
        float z = 1.f/(1.f + expf(-(sgx[256+t] + sgh[256+t])));
        float nn = tanhf(sgx[512+t] + r*sgh[512+t]);
        float nv = (1.f - z)*nn + z*so[t];
        g_Cond[s*260 + t] = nv;
        so[t] = nv;
    }
    __syncthreads();

    slot_compute(s, t, so, ns_g, ns_b, wq, W2, b2, sh, sq, qp, red);
}

// ---------------- final: pos/scl + write conditioning to out ----------------
__global__ void finz3_kernel(float* __restrict__ out)
{
    __shared__ float sres[4];
    int s = blockIdx.x, t = threadIdx.x;
    if (t < 32){
        const float* pp0 = g_part + ((size_t)(s*64 + t))*8;
        const float* pp1 = pp0 + 32*8;
        float S0 = warpSum(pp0[0] + pp1[0]);
        float Sx = warpSum(pp0[1] + pp1[1]);
        float Sy = warpSum(pp0[2] + pp1[2]);
        float Sxx = warpSum(pp0[3] + pp1[3]);
        float Syy = warpSum(pp0[4] + pp1[4]);
        if (t == 0){
            float px = Sx, py = Sy, G2 = g_cov[9];
            float vx = Sxx - 2.f*px*Sx + px*px*S0 + EPSA*(G2 + 1024.f*px*px);
            float vy = Syy - 2.f*py*Sy + py*py*S0 + EPSA*(G2 + 1024.f*py*py);
            float sx = fminf(fmaxf(sqrtf(fmaxf(vx,0.f)), 1e-3f), 2.f);
            float sy = fminf(fmaxf(sqrtf(fmaxf(vy,0.f)), 1e-3f), 2.f);
            sres[0]=px; sres[1]=py; sres[2]=sx; sres[3]=sy;
        }
    }
    __syncthreads();
    for (int i = t; i < 260; i += 256)
        out[s*260 + i] = (i < 256) ? g_Cond[s*260 + i] : sres[i - 256];
}

// ---------------- launch ----------------
extern "C" void kernel_launch(void* const* d_in, const int* in_sizes, int n_in,
                              void* d_out, int out_size)
{
    const float* inputs = (const float*)d_in[0];
    const float* cond   = (const float*)d_in[1];
    const float* ni_g   = (const float*)d_in[2];
    const float* ni_b   = (const float*)d_in[3];
    const float* ns_g   = (const float*)d_in[4];
    const float* ns_b   = (const float*)d_in[5];
    const float* wq     = (const float*)d_in[6];
    const float* wk     = (const float*)d_in[7];
    const float* wv     = (const float*)d_in[8];
    const float* gp_w   = (const float*)d_in[9];
    const float* gp_b   = (const float*)d_in[10];
    const float* ge_ln_g= (const float*)d_in[11];
    const float* ge_ln_b= (const float*)d_in[12];
    const float* ge_w1  = (const float*)d_in[13];
    const float* ge_b1  = (const float*)d_in[14];
    const float* ge_w2  = (const float*)d_in[15];
    const float* ge_b2  = (const float*)d_in[16];
    const float* gru_wih= (const float*)d_in[17];
    const float* gru_whh= (const float*)d_in[18];
    const float* gru_bih= (const float*)d_in[19];
    const float* gru_bhh= (const float*)d_in[20];
    float* out = (float*)d_out;

    pre_kernel<<<1058, 512>>>(gp_w, gp_b, ge_ln_g, ge_ln_b, ge_w1, ge_b1, cond, inputs, wk, wv);
    gemmT<<<dim3(4,64,2), 256>>>(0, inputs, ni_g, ni_b, 256);
    stats2<<<512, 512>>>(gp_w, gp_b);
    gemmT<<<dim3(8,64,2), 256>>>(2, nullptr, nullptr, nullptr, 512);
    slot0<<<64, 1024>>>(ns_g, ns_b, wq, ge_w2, ge_b2);

    for (int it = 0; it < 3; it++) {
        iter1_kernel<<<dim3(64,8), 256>>>(0, out);
        vaccF_kernel<<<dim3(16,8), 512>>>();
        updslot_kernel<<<64, 1024>>>(ge_w2, ge_b2, gru_wih, gru_whh, gru_bih, gru_bhh,
                                     ns_g, ns_b, wq);
    }
    iter1_kernel<<<dim3(64,8), 256>>>(1, out);
    finz3_kernel<<<64, 256>>>(out);
}

// round 14
// speedup vs baseline: 1.6474x; 1.0144x over previous
#include <cuda_runtime.h>
#include <math.h>
#include <stdint.h>

// ---------------- problem constants ----------------
#define NB 8
#define NPIX 1024
#define NS 8
#define D 256
#define H 512
#define NROWS (NB*NPIX)
#define EPSA 1e-8f
#define LNEPS 1e-5f
#define ATTN_SCALE 0.0625f
#define GSTEP (2.0f/31.0f)

// ---------------- scratch ----------------
__device__ __align__(16) float g_K [NROWS*D];
__device__ __align__(16) float g_V [NROWS*D];
__device__ __align__(16) float g_Pk[NROWS*H];
__device__ __align__(16) float g_Pv[NROWS*H];
__device__ __align__(16) float g_statsK[NROWS*4];
__device__ __align__(16) float g_statsV[NROWS*4];
__device__ float g_meanK[NROWS];
__device__ float g_meanV[NROWS];
__device__ float g_lnM[NROWS];
__device__ float g_lnIS[NROWS];
__device__ __align__(16) float g_U0[H];
__device__ __align__(16) float g_U1[H];
__device__ __align__(16) float g_Ub[H];
__device__ __align__(16) float g_C[H];
__device__ __align__(16) float g_G1[H];
__device__ float g_cov[16];
__device__ float g_Cond[NB*NS*260];
__device__ __align__(16) float g_slot[NB*NS*520];
__device__ float g_attn0[NB*NS*NPIX];
__device__ float g_part[NB*NS*64*8];
__device__ float g_spart[NB*NS*16*H];
// transposed + tf32-split weights (n-major: [n][k])
__device__ __align__(16) uint32_t g_WkTh[65536], g_WkTl[65536];
__device__ __align__(16) uint32_t g_WvTh[65536], g_WvTl[65536];
__device__ __align__(16) uint32_t g_W1Th[131072], g_W1Tl[131072];

__device__ __forceinline__ float warpSum(float v) {
    #pragma unroll
    for (int o = 16; o; o >>= 1) v += __shfl_xor_sync(0xffffffffu, v, o);
    return v;
}

__device__ __forceinline__ void tf32split(float x, uint32_t& h, uint32_t& l){
    uint32_t hb; asm("cvt.rna.tf32.f32 %0, %1;" : "=r"(hb) : "f"(x));
    float lo = x - __uint_as_float(hb);
    uint32_t lb; asm("cvt.rna.tf32.f32 %0, %1;" : "=r"(lb) : "f"(lo));
    h = hb; l = lb;
}

__device__ __forceinline__ uint32_t tf32cvt(float x){
    uint32_t hb; asm("cvt.rna.tf32.f32 %0, %1;" : "=r"(hb) : "f"(x));
    return hb;
}

__device__ __forceinline__ void mma_tf32(float* d, const uint32_t* a, const uint32_t* b){
    asm volatile("mma.sync.aligned.m16n8k8.row.col.f32.tf32.tf32.f32 "
        "{%0,%1,%2,%3}, {%4,%5,%6,%7}, {%8,%9}, {%0,%1,%2,%3};"
        : "+f"(d[0]), "+f"(d[1]), "+f"(d[2]), "+f"(d[3])
        : "r"(a[0]), "r"(a[1]), "r"(a[2]), "r"(a[3]), "r"(b[0]), "r"(b[1]));
}

// ---------------- pre: constants + cond copy + LN row stats + weight transpose/split ----------------
__global__ __launch_bounds__(512) void pre_kernel(
    const float* __restrict__ gp_w, const float* __restrict__ gp_b,
    const float* __restrict__ lg,   const float* __restrict__ lb,
    const float* __restrict__ W1,   const float* __restrict__ b1,
    const float* __restrict__ cond, const float* __restrict__ inputs,
    const float* __restrict__ wk,   const float* __restrict__ wv)
{
    int bid = blockIdx.x;
    int t = threadIdx.x;
    if (bid >= 546){
        int idx = (bid - 546)*512 + t;
        if (idx < 65536){
            int k = idx >> 8, n = idx & 255;
            uint32_t h, l; tf32split(wk[idx], h, l);
            g_WkTh[n*256+k] = h; g_WkTl[n*256+k] = l;
        } else if (idx < 131072){
            int i2 = idx - 65536;
            int k = i2 >> 8, n = i2 & 255;
            uint32_t h, l; tf32split(wv[i2], h, l);
            g_WvTh[n*256+k] = h; g_WvTl[n*256+k] = l;
        } else {
            int i2 = idx - 131072;
            int k = i2 >> 9, n = i2 & 511;
            uint32_t h, l; tf32split(W1[i2] * lg[k], h, l);
            g_W1Th[n*256+k] = h; g_W1Tl[n*256+k] = l;
        }
        return;
    }
    if (bid >= 34) {
        int r = (bid - 34)*16 + (t>>5);
        int lane = t & 31;
        const float* row = inputs + (size_t)r*D;
        float v[8]; float s = 0.f;
        #pragma unroll
        for (int k=0;k<8;k++){ v[k]=row[k*32+lane]; s+=v[k]; }
        float m = warpSum(s) * (1.f/D);
        float q = 0.f;
        #pragma unroll
        for (int k=0;k<8;k++){ float d=v[k]-m; q += d*d; }
        float is = rsqrtf(warpSum(q)*(1.f/D) + LNEPS);
        if (lane == 0){ g_lnM[r]=m; g_lnIS[r]=is; }
        return;
    }
    if (bid > 0) {
        int i = (bid - 1)*512 + t;
        if (i < NB*NS*260) g_Cond[i] = cond[i];
        return;
    }
    __shared__ float sg0[D], sg1[D], sgb[D], slg[D], slb[D];
    __shared__ float sm[4];
    if (t < D) { sg0[t]=gp_w[t]; sg1[t]=gp_w[D+t]; sgb[t]=gp_b[t]; slg[t]=lg[t]; slb[t]=lb[t]; }
    __syncthreads();
    if (t == 0) {
        float m0=0,m1=0,mb=0;
        for (int d=0; d<D; d++){ m0+=sg0[d]; m1+=sg1[d]; mb+=sgb[d]; }
        m0*=(1.f/D); m1*=(1.f/D); mb*=(1.f/D);
        float V00=0,V11=0,Vbb=0,C01=0,C0b=0,C1b=0;
        for (int d=0; d<D; d++){
            float a=sg0[d]-m0, b_=sg1[d]-m1, c=sgb[d]-mb;
            V00+=a*a; V11+=b_*b_; Vbb+=c*c; C01+=a*b_; C0b+=a*c; C1b+=b_*c;
        }
        g_cov[0]=m0; g_cov[1]=m1; g_cov[2]=mb;
        g_cov[3]=V00/D; g_cov[4]=V11/D; g_cov[5]=Vbb/D;
        g_cov[6]=C01/D; g_cov[7]=C0b/D; g_cov[8]=C1b/D;
        float s2=0;
        for (int i=0;i<32;i++){ float x=-1.f + i*GSTEP; s2+=x*x; }
        g_cov[9]=s2*32.f;
        sm[0]=m0; sm[1]=m1; sm[2]=mb;
    }
    __syncthreads();
    float m0=sm[0], m1=sm[1], mb=sm[2];
    float U0=0,U1=0,Ub=0,Cc=0,G1=0;
    for (int d=0; d<D; d++){
        float w = W1[d*H + t];
        float gd = slg[d];
        U0 = fmaf((sg0[d]-m0)*gd, w, U0);
        U1 = fmaf((sg1[d]-m1)*gd, w, U1);
        Ub = fmaf((sgb[d]-mb)*gd, w, Ub);
        Cc = fmaf(slb[d], w, Cc);
        G1 = fmaf(gd, w, G1);
    }
    g_U0[t]=U0; g_U1[t]=U1; g_Ub[t]=Ub; g_C[t]=Cc + b1[t]; g_G1[t]=G1;
}

// ---------------- tensor-core GEMM: tf32, 128x64 tile ----------------
// mode 0: C = LN(inputs)@wk / @wv  (3-term split; N=256)
// mode 2: C = K@(diag(sg)W1) - mk*G1 + Ub  (pure tf32, single term; N=512)
__global__ __launch_bounds__(256,2) void gemmT(int mode, const float* __restrict__ A0,
                                               const float* __restrict__ sgv,
                                               const float* __restrict__ sbv, int N)
{
    int z = blockIdx.z;
    const float* A = (mode==0) ? A0 : (z ? g_V : g_K);
    const uint32_t* BTh = (mode==0) ? (z ? g_WvTh : g_WkTh) : g_W1Th;
    const uint32_t* BTl = (mode==0) ? (z ? g_WvTl : g_WkTl) : g_W1Tl;
    float* Cm = (mode==0) ? (z ? g_V : g_K) : (z ? g_Pv : g_Pk);
    const float* meanV = (mode==0) ? nullptr : (z ? g_meanV : g_meanK);

    __shared__ __align__(16) uint32_t Ah[128*20], Al[128*20];
    __shared__ __align__(16) uint32_t Bh[64*20],  Bl[64*20];
    __shared__ float SG[256], SB[256];

    int bm = blockIdx.y*128, bn = blockIdx.x*64;
    int tid = threadIdx.x, lane = tid & 31, wrp = tid >> 5;
    int wm = wrp & 3, wn = wrp >> 2;       // warp grid 4(M) x 2(N), warp tile 32x32
    int qr = lane >> 2, ql = lane & 3;

    if (mode == 0){ SG[tid] = sgv[tid]; SB[tid] = sbv[tid]; }

    int arow = tid >> 1, akoff = (tid & 1) * 8;
    int brow = tid >> 2, bkoff = (tid & 3) * 4;
    float rm = 0.f, ris = 1.f;
    if (mode == 0){ rm = g_lnM[bm+arow]; ris = g_lnIS[bm+arow]; }
    __syncthreads();

    float acc[2][4][4] = {};
    const float* aptr = A + (size_t)(bm+arow)*256 + akoff;
    const uint32_t* bhp = BTh + (size_t)(bn+brow)*256 + bkoff;
    const uint32_t* blp = BTl + (size_t)(bn+brow)*256 + bkoff;

    float4 pa0 = *(const float4*)aptr;
    float4 pa1 = *(const float4*)(aptr + 4);
    uint4 pbh = *(const uint4*)bhp;
    uint4 pbl = make_uint4(0,0,0,0);
    if (mode == 0) pbl = *(const uint4*)blp;

    #pragma unroll 1
    for (int kc = 0; kc < 16; kc++){
        float av[8] = {pa0.x,pa0.y,pa0.z,pa0.w,pa1.x,pa1.y,pa1.z,pa1.w};
        uint32_t ahv[8], alv[8];
        if (mode == 0){
            int kb = kc*16 + akoff;
            #pragma unroll
            for (int i=0;i<8;i++) av[i] = fmaf((av[i]-rm)*ris, SG[kb+i], SB[kb+i]);
            #pragma unroll
            for (int i=0;i<8;i++) tf32split(av[i], ahv[i], alv[i]);
        } else {
            #pragma unroll
            for (int i=0;i<8;i++) ahv[i] = tf32cvt(av[i]);
        }
        __syncthreads();
        *(uint4*)&Ah[arow*20 + akoff]     = make_uint4(ahv[0],ahv[1],ahv[2],ahv[3]);
        *(uint4*)&Ah[arow*20 + akoff + 4] = make_uint4(ahv[4],ahv[5],ahv[6],ahv[7]);
        if (mode == 0){
            *(uint4*)&Al[arow*20 + akoff]     = make_uint4(alv[0],alv[1],alv[2],alv[3]);
            *(uint4*)&Al[arow*20 + akoff + 4] = make_uint4(alv[4],alv[5],alv[6],alv[7]);
        }
        *(uint4*)&Bh[brow*20 + bkoff] = pbh;
        if (mode == 0) *(uint4*)&Bl[brow*20 + bkoff] = pbl;
        __syncthreads();
        if (kc < 15){
            pa0 = *(const float4*)(aptr + kc*16 + 16);
            pa1 = *(const float4*)(aptr + kc*16 + 20);
            pbh = *(const uint4*)(bhp + kc*16 + 16);
            if (mode == 0) pbl = *(const uint4*)(blp + kc*16 + 16);
        }
        #pragma unroll
        for (int kk = 0; kk < 16; kk += 8){
            uint32_t ah[2][4], al[2][4];
            #pragma unroll
            for (int mi=0; mi<2; mi++){
                int r = wm*32 + mi*16 + qr;
                ah[mi][0] = Ah[r*20 + kk + ql];
                ah[mi][1] = Ah[(r+8)*20 + kk + ql];
                ah[mi][2] = Ah[r*20 + kk + ql + 4];
                ah[mi][3] = Ah[(r+8)*20 + kk + ql + 4];
                if (mode == 0){
                    al[mi][0] = Al[r*20 + kk + ql];
                    al[mi][1] = Al[(r+8)*20 + kk + ql];
                    al[mi][2] = Al[r*20 + kk + ql + 4];
                    al[mi][3] = Al[(r+8)*20 + kk + ql + 4];
                }
            }
            #pragma unroll
            for (int nj=0; nj<4; nj++){
                int n = wn*32 + nj*8 + qr;
                uint32_t bhv[2] = { Bh[n*20 + kk + ql], Bh[n*20 + kk + ql + 4] };
                #pragma unroll
                for (int mi=0; mi<2; mi++)
                    mma_tf32(acc[mi][nj], ah[mi], bhv);
                if (mode == 0){
                    uint32_t blv[2] = { Bl[n*20 + kk + ql], Bl[n*20 + kk + ql + 4] };
                    #pragma unroll
                    for (int mi=0; mi<2; mi++){
                        mma_tf32(acc[mi][nj], al[mi], bhv);
                        mma_tf32(acc[mi][nj], ah[mi], blv);
                    }
                }
            }
        }
    }
    // epilogue
    #pragma unroll
    for (int mi=0; mi<2; mi++){
        int r0 = bm + wm*32 + mi*16 + qr;
        int r1 = r0 + 8;
        float mk0 = 0.f, mk1 = 0.f;
        if (mode){ mk0 = __ldg(meanV + r0); mk1 = __ldg(meanV + r1); }
        #pragma unroll
        for (int nj=0; nj<4; nj++){
            int c0 = bn + wn*32 + nj*8 + ql*2;
            float v00 = acc[mi][nj][0], v01 = acc[mi][nj][1];
            float v10 = acc[mi][nj][2], v11 = acc[mi][nj][3];
            if (mode){
                float g0 = g_G1[c0], g1 = g_G1[c0+1];
                float u0 = g_Ub[c0], u1 = g_Ub[c0+1];
                v00 = v00 - mk0*g0 + u0; v01 = v01 - mk0*g1 + u1;
                v10 = v10 - mk1*g0 + u0; v11 = v11 - mk1*g1 + u1;
            }
            *(float2*)(Cm + (size_t)r0*N + c0) = make_float2(v00, v01);
            *(float2*)(Cm + (size_t)r1*N + c0) = make_float2(v10, v11);
        }
    }
}

// ---------------- stats (warp-per-row) ----------------
__global__ __launch_bounds__(512) void stats2(const float* __restrict__ gp_w, const float* __restrict__ gp_b)
{
    int r = blockIdx.x*16 + (threadIdx.x>>5);
    int lane = threadIdx.x & 31;
    float m0=g_cov[0], m1=g_cov[1], mb=g_cov[2];
    float Vbb=g_cov[5], C0b=g_cov[7], C1b=g_cov[8];
    float g0[8], g1[8], gbv[8];
    #pragma unroll
    for (int k=0;k<8;k++){
        int d = k*32+lane;
        g0[k]=gp_w[d]-m0; g1[k]=gp_w[D+d]-m1; gbv[k]=gp_b[d]-mb;
    }
    #pragma unroll
    for (int br=0; br<2; br++){
        const float* src = br ? g_V : g_K;
        float sK=0,sK2=0,s0=0,s1=0,sb=0;
        #pragma unroll
        for (int k=0;k<8;k++){
            float x = src[(size_t)r*D + k*32 + lane];
            sK+=x; sK2=fmaf(x,x,sK2); s0=fmaf(x,g0[k],s0); s1=fmaf(x,g1[k],s1); sb=fmaf(x,gbv[k],sb);
        }
        sK=warpSum(sK); sK2=warpSum(sK2); s0=warpSum(s0); s1=warpSum(s1); sb=warpSum(sb);
        if (lane == 0){
            float mk = sK*(1.f/D);
            float Vkk = sK2*(1.f/D) - mk*mk;
            float Ck0 = s0*(1.f/D), Ck1 = s1*(1.f/D), Ckb = sb*(1.f/D);
            float* st = br ? (g_statsV + r*4) : (g_statsK + r*4);
            st[0] = Vkk + Vbb + 2.f*Ckb;
            st[1] = 2.f*(Ck0 + C0b);
            st[2] = 2.f*(Ck1 + C1b);
            st[3] = 0.f;
            if (br) g_meanV[r]=mk; else g_meanK[r]=mk;
        }
    }
}

// ---------------- per-slot q/wtil/scalars (1024 threads) ----------------
__device__ __forceinline__ void slot_compute(
    int s, int t, const float* so,
    const float* __restrict__ ns_g, const float* __restrict__ ns_b,
    const float* __restrict__ wq,   const float* __restrict__ W2, const float* __restrict__ b2,
    float* sh, float* sq, float* qp, float* red)
{
    int w = t >> 5, lane = t & 31;
    float v = (t < 256) ? so[t] : 0.f;
    float ws = warpSum(v);
    if (lane == 0 && t < 256) red[w] = ws;
    __syncthreads();
    float m = 0.f;
    #pragma unroll
    for (int i=0;i<8;i++) m += red[i];
    m *= (1.f/D);
    float d = (t < 256) ? (v - m) : 0.f;
    ws = warpSum(d*d);
    __syncthreads();
    if (lane == 0 && t < 256) red[w] = ws;
    __syncthreads();
    float var = 0.f;
    #pragma unroll
    for (int i=0;i<8;i++) var += red[i];
    var *= (1.f/D);
    if (t < 256) sh[t] = d * rsqrtf(var + LNEPS) * ns_g[t] + ns_b[t];
    __syncthreads();

    {
        int cg = t & 63, ks = t >> 6;
        const float4* wq4 = (const float4*)wq;
        float4 a = make_float4(0.f,0.f,0.f,0.f);
        #pragma unroll 4
        for (int j = ks*16; j < ks*16 + 16; j++){
            float4 wv = __ldg(wq4 + j*64 + cg);
            float sv = sh[j];
            a.x = fmaf(sv, wv.x, a.x);
            a.y = fmaf(sv, wv.y, a.y);
            a.z = fmaf(sv, wv.z, a.z);
            a.w = fmaf(sv, wv.w, a.w);
        }
        *(float4*)(qp + ks*256 + cg*4) = a;
    }
    __syncthreads();
    if (t < 256){
        float vq = 0.f;
        #pragma unroll
        for (int ks=0; ks<16; ks++) vq += qp[ks*256 + t];
        sq[t] = vq;
    }
    __syncthreads();

    float p = (t < 256) ? sq[t]*b2[t] : 0.f;
    ws = warpSum(p);
    __syncthreads();
    if (lane == 0 && t < 256) red[w] = ws;
    __syncthreads();

    float4 qa = *(const float4*)(sq + lane*8);
    float4 qb = *(const float4*)(sq + lane*8 + 4);
    #pragma unroll 2
    for (int k = 0; k < 16; k++){
        int j = (k << 5) + w;
        const float4* w2r = (const float4*)(W2 + j*D);
        float4 wa = __ldg(w2r + lane*2);
        float4 wb = __ldg(w2r + lane*2 + 1);
        float acc = wa.x*qa.x + wa.y*qa.y + wa.z*qa.z + wa.w*qa.w
                  + wb.x*qb.x + wb.y*qb.y + wb.z*qb.z + wb.w*qb.w;
        acc = warpSum(acc);
        if (lane == 0) g_slot[s*520 + j] = acc;
    }
    if (t == 0){
        float qb2 = 0.f;
        #pragma unroll
        for (int i=0;i<8;i++) qb2 += red[i];
        float px = fminf(fmaxf(g_Cond[s*260+256], -1.f), 1.f);
        float py = fminf(fmaxf(g_Cond[s*260+257], -1.f), 1.f);
        float sx = fminf(fmaxf(g_Cond[s*260+258], 1e-3f), 2.f);
        float sy = fminf(fmaxf(g_Cond[s*260+259], 1e-3f), 2.f);
        float* o = g_slot + s*520 + 512;
        o[0]=qb2; o[1]=px; o[2]=py; o[3]=1.f/(5.f*sx); o[4]=1.f/(5.f*sy);
    }
}

__global__ __launch_bounds__(1024) void slot0(const float* __restrict__ ns_g, const float* __restrict__ ns_b,
                                              const float* __restrict__ wq,   const float* __restrict__ W2,
                                              const float* __restrict__ b2)
{
    __shared__ float so[256], sh[256], sq[256], qp[4096], red[16];
    int s = blockIdx.x, t = threadIdx.x;
    if (t < 256) so[t] = g_Cond[s*260 + t];
    __syncthreads();
    slot_compute(s, t, so, ns_g, ns_b, wq, W2, b2, sh, sq, qp, red);
}

// ---------------- fused: dots + softmax + attn0 + partials (2-px ILP) ----------------
__global__ __launch_bounds__(256) void iter1_kernel(int last, float* __restrict__ out)
{
    int b = blockIdx.y, chunk = blockIdx.x;
    int t = threadIdx.x, w = t >> 5, lane = t & 31;
    __shared__ float sPk[16*512];
    __shared__ float sdots[NS][16];
    __shared__ float sscal[NS][5];

    float* attnDst = last ? (out + 16640) : g_attn0;
    float* relOut  = out + 16640 + 65536;
    int n0 = chunk*16;

    {
        const float4* src = (const float4*)(g_Pk + (((size_t)(b<<10) + n0)<<9));
        float4* dst = (float4*)sPk;
        #pragma unroll
        for (int i=0;i<8;i++) dst[t + i*256] = __ldg(src + t + i*256);
    }

    float4 u0v[4], u1v[4], wtv[4], cv[4];
    const float* wts = g_slot + (b*NS + w)*520;
    #pragma unroll
    for (int jj=0; jj<4; jj++){
        int j = jj*128 + lane*4;
        u0v[jj] = *(const float4*)(g_U0 + j);
        u1v[jj] = *(const float4*)(g_U1 + j);
        cv[jj]  = *(const float4*)(g_C  + j);
        wtv[jj] = *(const float4*)(wts  + j);
    }
    if (t < 40) sscal[t/5][t%5] = g_slot[(b*NS + t/5)*520 + 512 + (t%5)];
    __syncthreads();

    float qb2=sscal[w][0], px=sscal[w][1], py=sscal[w][2], i5x=sscal[w][3], i5y=sscal[w][4];
    float V00=g_cov[3], V11=g_cov[4], C01_2=2.f*g_cov[6];

    for (int pp=0; pp<16; pp+=2){
        int nA = n0 + pp, nB = nA + 1;
        float gxA = -1.f + (float)(nA>>5)*GSTEP, gyA = -1.f + (float)(nA&31)*GSTEP;
        float gxB = -1.f + (float)(nB>>5)*GSTEP, gyB = -1.f + (float)(nB&31)*GSTEP;
        float aA = (gxA-px)*i5x, cA = (gyA-py)*i5y;
        float aB = (gxB-px)*i5x, cB = (gyB-py)*i5y;
        const float4 stA = *(const float4*)(g_statsK + ((b<<10)+nA)*4);
        const float4 stB = *(const float4*)(g_statsK + ((b<<10)+nB)*4);
        float varA = stA.x + aA*stA.y + cA*stA.z + aA*aA*V00 + cA*cA*V11 + aA*cA*C01_2;
        float varB = stB.x + aB*stB.y + cB*stB.z + aB*aB*V00 + cB*cB*V11 + aB*cB*C01_2;
        float isA = rsqrtf(varA + LNEPS);
        float isB = rsqrtf(varB + LNEPS);
        const float* pkA = sPk + pp*512;
        const float* pkB = pkA + 512;
        float acA0=0.f, acA1=0.f, acB0=0.f, acB1=0.f;
        #pragma unroll
        for (int jj=0; jj<4; jj++){
            float4 p4A = *(const float4*)(pkA + jj*128 + lane*4);
            float4 p4B = *(const float4*)(pkB + jj*128 + lane*4);
            float eA0 = fmaf(isA, fmaf(cA,u1v[jj].x, fmaf(aA,u0v[jj].x, p4A.x)), cv[jj].x);
            float eB0 = fmaf(isB, fmaf(cB,u1v[jj].x, fmaf(aB,u0v[jj].x, p4B.x)), cv[jj].x);
            float eA1 = fmaf(isA, fmaf(cA,u1v[jj].y, fmaf(aA,u0v[jj].y, p4A.y)), cv[jj].y);
            float eB1 = fmaf(isB, fmaf(cB,u1v[jj].y, fmaf(aB,u0v[jj].y, p4B.y)), cv[jj].y);
            float eA2 = fmaf(isA, fmaf(cA,u1v[jj].z, fmaf(aA,u0v[jj].z, p4A.z)), cv[jj].z);
            float eB2 = fmaf(isB, fmaf(cB,u1v[jj].z, fmaf(aB,u0v[jj].z, p4B.z)), cv[jj].z);
            float eA3 = fmaf(isA, fmaf(cA,u1v[jj].w, fmaf(aA,u0v[jj].w, p4A.w)), cv[jj].w);
            float eB3 = fmaf(isB, fmaf(cB,u1v[jj].w, fmaf(aB,u0v[jj].w, p4B.w)), cv[jj].w);
            acA0 = fmaf(fmaxf(eA0,0.f), wtv[jj].x, acA0);
            acB0 = fmaf(fmaxf(eB0,0.f), wtv[jj].x, acB0);
            acA1 = fmaf(fmaxf(eA1,0.f), wtv[jj].y, acA1);
            acB1 = fmaf(fmaxf(eB1,0.f), wtv[jj].y, acB1);
            acA0 = fmaf(fmaxf(eA2,0.f), wtv[jj].z, acA0);
            acB0 = fmaf(fmaxf(eB2,0.f), wtv[jj].z, acB0);
            acA1 = fmaf(fmaxf(eA3,0.f), wtv[jj].w, acA1);
            acB1 = fmaf(fmaxf(eB3,0.f), wtv[jj].w, acB1);
        }
        float sA = acA0 + acA1, sB = acB0 + acB1;
        #pragma unroll
        for (int o=16;o;o>>=1){
            sA += __shfl_xor_sync(0xffffffffu, sA, o);
            sB += __shfl_xor_sync(0xffffffffu, sB, o);
        }
        if (lane == 0){
            sdots[w][pp]   = ATTN_SCALE * (sA + qb2);
            sdots[w][pp+1] = ATTN_SCALE * (sB + qb2);
            if (last){
                float2* rpA = (float2*)(relOut + ((((size_t)(b*NS+w)<<10)+nA)<<1));
                float2* rpB = (float2*)(relOut + ((((size_t)(b*NS+w)<<10)+nB)<<1));
                *rpA = make_float2(aA, cA);
                *rpB = make_float2(aB, cB);
            }
        }
    }
    __syncthreads();

    float a0 = 0.f, gx = 0.f, gy = 0.f;
    if (lane < 16){
        int n = n0 + lane;
        float dd[NS]; float mx = -1e30f;
        #pragma unroll
        for (int k=0;k<NS;k++){ dd[k] = sdots[k][lane]; mx = fmaxf(mx, dd[k]); }
        float sum = 0.f;
        #pragma unroll
        for (int k=0;k<NS;k++){ dd[k] = expf(dd[k]-mx); sum += dd[k]; }
        a0 = dd[w] / sum;
        attnDst[((b*NS+w)<<10) + n] = a0;
        gx = -1.f + (float)(n>>5)*GSTEP;
        gy = -1.f + (float)(n&31)*GSTEP;
    }
    float S0 = warpSum(a0);
    float Sx = warpSum(a0*gx);
    float Sy = warpSum(a0*gy);
    float Sxx = warpSum(a0*gx*gx);
    float Syy = warpSum(a0*gy*gy);
    if (lane == 0){
        float* pp = g_part + ((size_t)((b*NS+w)*64 + chunk))*8;
        pp[0]=S0; pp[1]=Sx; pp[2]=Sy; pp[3]=Sxx; pp[4]=Syy;
    }
}

// ---------------- slot-fused vacc + finalize ----------------
__global__ __launch_bounds__(512) void vaccF_kernel()
{
    int chunk = blockIdx.x;
    int b = blockIdx.y;
    int t = threadIdx.x;
    __shared__ float4 sC4[NS][64];
    __shared__ float sden[NS];

    int sl = t >> 6, p = t & 63;
    int n = chunk*64 + p;
    int gs = b*NS + sl;
    float rawA;
    {
        float px = g_slot[gs*520+513], py = g_slot[gs*520+514];
        float i5x= g_slot[gs*520+515], i5y= g_slot[gs*520+516];
        float gx = -1.f + (float)(n>>5)*GSTEP;
        float gy = -1.f + (float)(n&31)*GSTEP;
        float a = (gx-px)*i5x, c = (gy-py)*i5y;
        const float4 st = *(const float4*)(g_statsV + ((b<<10)+n)*4);
        float var = st.x + a*st.y + c*st.z + a*a*g_cov[3] + c*c*g_cov[4] + a*c*2.f*g_cov[6];
        float is = rsqrtf(var + LNEPS);
        rawA = g_attn0[(gs<<10)+n];
        sC4[sl][p] = make_float4(is, is*a, is*c, 0.f);
    }
    if (t < 256){
        int w = t >> 5, lane = t & 31;
        const float* pp0 = g_part + ((size_t)((b*NS+w)*64 + lane))*8;
        const float* pp1 = pp0 + 32*8;
        float S0 = warpSum(pp0[0] + pp1[0]);
        if (chunk == 0){
            float Sx = warpSum(pp0[1] + pp1[1]);
            float Sy = warpSum(pp0[2] + pp1[2]);
            float Sxx = warpSum(pp0[3] + pp1[3]);
            float Syy = warpSum(pp0[4] + pp1[4]);
            if (lane == 0){
                float px = Sx, py = Sy, G2 = g_cov[9];
                float vx = Sxx - 2.f*px*Sx + px*px*S0 + EPSA*(G2 + 1024.f*px*px);
                float vy = Syy - 2.f*py*Sy + py*py*S0 + EPSA*(G2 + 1024.f*py*py);
                float sx = fminf(fmaxf(sqrtf(fmaxf(vx,0.f)), 1e-3f), 2.f);
                float sy = fminf(fmaxf(sqrtf(fmaxf(vy,0.f)), 1e-3f), 2.f);
                int s2 = b*NS + w;
                g_Cond[s2*260+256]=px; g_Cond[s2*260+257]=py;
                g_Cond[s2*260+258]=sx; g_Cond[s2*260+259]=sy;
            }
        }
        if (lane == 0) sden[w] = 1.f/(S0 + 1024.f*EPSA);
    }
    __syncthreads();
    sC4[sl][p].w = (rawA + EPSA) * sden[sl];
    __syncthreads();

    float u0 = g_U0[t], u1 = g_U1[t], C = g_C[t];
    const float* pvb = g_Pv + ((((size_t)(b<<10)) + (size_t)chunk*64) << 9) + t;
    float acc[NS] = {};
    #pragma unroll 4
    for (int q=0; q<64; q++){
        float pv = __ldg(pvb + ((size_t)q << 9));
        #pragma unroll
        for (int s2=0; s2<NS; s2++){
            float4 cf = sC4[s2][q];
            float pre = fmaf(cf.y, u0, fmaf(cf.z, u1, fmaf(cf.x, pv, C)));
            acc[s2] = fmaf(fmaxf(pre, 0.f), cf.w, acc[s2]);
        }
    }
    #pragma unroll
    for (int s2=0; s2<NS; s2++)
        g_spart[((size_t)((b*NS+s2)*16 + chunk))*H + t] = acc[s2];
}

// ---------------- GRU update + slot prep for next iter ----------------
__global__ __launch_bounds__(1024) void updslot_kernel(
    const float* __restrict__ W2,  const float* __restrict__ b2,
    const float* __restrict__ Wih, const float* __restrict__ Whh,
    const float* __restrict__ bih, const float* __restrict__ bhh,
    const float* __restrict__ ns_g, const float* __restrict__ ns_b,
    const float* __restrict__ wq)
{
    __shared__ float ss[H], so[256], su[256], qp[4096], sgx[768], sgh[768], sh[256], sq[256], red[16];
    int s = blockIdx.x, t = threadIdx.x, w = t >> 5, lane = t & 31;

    if (t < 512){
        float r0 = 0.f;
        #pragma unroll
        for (int c=0; c<16; c++) r0 += g_spart[((size_t)(s*16 + c))*H + t];
        ss[t] = r0;
    }
    if (t < 256) so[t] = g_Cond[s*260 + t];
    __syncthreads();

    {
        int cg = t & 63, ks = t >> 6;
        const float4* W24 = (const float4*)W2;
        float4 a = make_float4(0.f,0.f,0.f,0.f);
        #pragma unroll 4
        for (int j = ks*32; j < ks*32 + 32; j++){
            float4 wv = __ldg(W24 + j*64 + cg);
            float sv = ss[j];
            a.x = fmaf(sv, wv.x, a.x);
            a.y = fmaf(sv, wv.y, a.y);
            a.z = fmaf(sv, wv.z, a.z);
            a.w = fmaf(sv, wv.w, a.w);
        }
        *(float4*)(qp + ks*256 + cg*4) = a;
    }
    __syncthreads();
    if (t < 256){
        float u = b2[t];
        #pragma unroll
        for (int ks=0; ks<16; ks++) u += qp[ks*256 + t];
        su[t] = u;
    }
    __syncthreads();

    {
        float4 sua = *(const float4*)(su + lane*8);
        float4 sub = *(const float4*)(su + lane*8 + 4);
        float4 soa = *(const float4*)(so + lane*8);
        float4 sob = *(const float4*)(so + lane*8 + 4);
        #pragma unroll 2
        for (int k = 0; k < 24; k++){
            int i = (k << 5) + w;
            const float4* wi4 = (const float4*)(Wih + i*D);
            const float4* wh4 = (const float4*)(Whh + i*D);
            float4 wa = __ldg(wi4 + lane*2);
            float4 wb = __ldg(wi4 + lane*2 + 1);
            float4 ha = __ldg(wh4 + lane*2);
            float4 hb = __ldg(wh4 + lane*2 + 1);
            float ax = wa.x*sua.x + wa.y*sua.y + wa.z*sua.z + wa.w*sua.w
                     + wb.x*sub.x + wb.y*sub.y + wb.z*sub.z + wb.w*sub.w;
            float ah = ha.x*soa.x + ha.y*soa.y + ha.z*soa.z + ha.w*soa.w
                     + hb.x*sob.x + hb.y*sob.y + hb.z*sob.z + hb.w*sob.w;
            ax = warpSum(ax); ah = warpSum(ah);
            if (lane == 0){ sgx[i] = ax + bih[i]; sgh[i] = ah + bhh[i]; }
        }
    }
    __syncthreads();

    if (t < 256){
        float r = 1.f/(1.f + expf(-(sgx[t]     + sgh[t])));
        float z = 1.f/(1.f + expf(-(sgx[256+t] + sgh[256+t])));
        float nn = tanhf(sgx[512+t] + r*sgh[512+t]);
        float nv = (1.f - z)*nn + z*so[t];
        g_Cond[s*260 + t] = nv;
        so[t] = nv;
    }
    __syncthreads();

    slot_compute(s, t, so, ns_g, ns_b, wq, W2, b2, sh, sq, qp, red);
}

// ---------------- final: pos/scl + write conditioning to out ----------------
__global__ void finz3_kernel(float* __restrict__ out)
{
    __shared__ float sres[4];
    int s = blockIdx.x, t = threadIdx.x;
    if (t < 32){
        const float* pp0 = g_part + ((size_t)(s*64 + t))*8;
        const float* pp1 = pp0 + 32*8;
        float S0 = warpSum(pp0[0] + pp1[0]);
        float Sx = warpSum(pp0[1] + pp1[1]);
        float Sy = warpSum(pp0[2] + pp1[2]);
        float Sxx = warpSum(pp0[3] + pp1[3]);
        float Syy = warpSum(pp0[4] + pp1[4]);
        if (t == 0){
            float px = Sx, py = Sy, G2 = g_cov[9];
            float vx = Sxx - 2.f*px*Sx + px*px*S0 + EPSA*(G2 + 1024.f*px*px);
            float vy = Syy - 2.f*py*Sy + py*py*S0 + EPSA*(G2 + 1024.f*py*py);
            float sx = fminf(fmaxf(sqrtf(fmaxf(vx,0.f)), 1e-3f), 2.f);
            float sy = fminf(fmaxf(sqrtf(fmaxf(vy,0.f)), 1e-3f), 2.f);
            sres[0]=px; sres[1]=py; sres[2]=sx; sres[3]=sy;
        }
    }
    __syncthreads();
    for (int i = t; i < 260; i += 256)
        out[s*260 + i] = (i < 256) ? g_Cond[s*260 + i] : sres[i - 256];
}

// ---------------- launch ----------------
extern "C" void kernel_launch(void* const* d_in, const int* in_sizes, int n_in,
                              void* d_out, int out_size)
{
    const float* inputs = (const float*)d_in[0];
    const float* cond   = (const float*)d_in[1];
    const float* ni_g   = (const float*)d_in[2];
    const float* ni_b   = (const float*)d_in[3];
    const float* ns_g   = (const float*)d_in[4];
    const float* ns_b   = (const float*)d_in[5];
    const float* wq     = (const float*)d_in[6];
    const float* wk     = (const float*)d_in[7];
    const float* wv     = (const float*)d_in[8];
    const float* gp_w   = (const float*)d_in[9];
    const float* gp_b   = (const float*)d_in[10];
    const float* ge_ln_g= (const float*)d_in[11];
    const float* ge_ln_b= (const float*)d_in[12];
    const float* ge_w1  = (const float*)d_in[13];
    const float* ge_b1  = (const float*)d_in[14];
    const float* ge_w2  = (const float*)d_in[15];
    const float* ge_b2  = (const float*)d_in[16];
    const float* gru_wih= (const float*)d_in[17];
    const float* gru_whh= (const float*)d_in[18];
    const float* gru_bih= (const float*)d_in[19];
    const float* gru_bhh= (const float*)d_in[20];
    float* out = (float*)d_out;

    pre_kernel<<<1058, 512>>>(gp_w, gp_b, ge_ln_g, ge_ln_b, ge_w1, ge_b1, cond, inputs, wk, wv);
    gemmT<<<dim3(4,64,2), 256>>>(0, inputs, ni_g, ni_b, 256);
    stats2<<<512, 512>>>(gp_w, gp_b);
    gemmT<<<dim3(8,64,2), 256>>>(2, nullptr, nullptr, nullptr, 512);
    slot0<<<64, 1024>>>(ns_g, ns_b, wq, ge_w2, ge_b2);

    for (int it = 0; it < 3; it++) {
        iter1_kernel<<<dim3(64,8), 256>>>(0, out);
        vaccF_kernel<<<dim3(16,8), 512>>>();
        updslot_kernel<<<64, 1024>>>(ge_w2, ge_b2, gru_wih, gru_whh, gru_bih, gru_bhh,
                                     ns_g, ns_b, wq);
    }
    iter1_kernel<<<dim3(64,8), 256>>>(1, out);
    finz3_kernel<<<64, 256>>>(out);
}

// round 15
// speedup vs baseline: 1.6807x; 1.0202x over previous
#include <cuda_runtime.h>
#include <math.h>
#include <stdint.h>

// ---------------- problem constants ----------------
#define NB 8
#define NPIX 1024
#define NS 8
#define D 256
#define H 512
#define NROWS (NB*NPIX)
#define EPSA 1e-8f
#define LNEPS 1e-5f
#define ATTN_SCALE 0.0625f
#define GSTEP (2.0f/31.0f)

// ---------------- scratch ----------------
__device__ __align__(16) float g_K [NROWS*D];
__device__ __align__(16) float g_V [NROWS*D];
__device__ __align__(16) float g_Pk[NROWS*H];
__device__ __align__(16) float g_Pv[NROWS*H];
__device__ __align__(16) float g_statsK[NROWS*4];
__device__ __align__(16) float g_statsV[NROWS*4];
__device__ float g_meanK[NROWS];
__device__ float g_meanV[NROWS];
__device__ float g_lnM[NROWS];
__device__ float g_lnIS[NROWS];
__device__ __align__(16) float g_U0[H];
__device__ __align__(16) float g_U1[H];
__device__ __align__(16) float g_Ub[H];
__device__ __align__(16) float g_C[H];
__device__ __align__(16) float g_G1[H];
__device__ float g_cov[16];
__device__ float g_Cond[NB*NS*260];
__device__ __align__(16) float g_slot[NB*NS*520];
__device__ float g_attn0[NB*NS*NPIX];
__device__ float g_part[NB*NS*64*8];
__device__ float g_spart[NB*NS*16*H];
// transposed + tf32-split weights (n-major: [n][k])
__device__ __align__(16) uint32_t g_WkTh[65536], g_WkTl[65536];
__device__ __align__(16) uint32_t g_WvTh[65536], g_WvTl[65536];
__device__ __align__(16) uint32_t g_W1Th[131072], g_W1Tl[131072];

__device__ __forceinline__ float warpSum(float v) {
    #pragma unroll
    for (int o = 16; o; o >>= 1) v += __shfl_xor_sync(0xffffffffu, v, o);
    return v;
}

__device__ __forceinline__ void tf32split(float x, uint32_t& h, uint32_t& l){
    uint32_t hb; asm("cvt.rna.tf32.f32 %0, %1;" : "=r"(hb) : "f"(x));
    float lo = x - __uint_as_float(hb);
    uint32_t lb; asm("cvt.rna.tf32.f32 %0, %1;" : "=r"(lb) : "f"(lo));
    h = hb; l = lb;
}

__device__ __forceinline__ uint32_t tf32cvt(float x){
    uint32_t hb; asm("cvt.rna.tf32.f32 %0, %1;" : "=r"(hb) : "f"(x));
    return hb;
}

__device__ __forceinline__ void mma_tf32(float* d, const uint32_t* a, const uint32_t* b){
    asm volatile("mma.sync.aligned.m16n8k8.row.col.f32.tf32.tf32.f32 "
        "{%0,%1,%2,%3}, {%4,%5,%6,%7}, {%8,%9}, {%0,%1,%2,%3};"
        : "+f"(d[0]), "+f"(d[1]), "+f"(d[2]), "+f"(d[3])
        : "r"(a[0]), "r"(a[1]), "r"(a[2]), "r"(a[3]), "r"(b[0]), "r"(b[1]));
}

// ---------------- pre: constants + cond copy + LN row stats + tiled weight transpose/split ----------------
__global__ __launch_bounds__(512) void pre_kernel(
    const float* __restrict__ gp_w, const float* __restrict__ gp_b,
    const float* __restrict__ lg,   const float* __restrict__ lb,
    const float* __restrict__ W1,   const float* __restrict__ b1,
    const float* __restrict__ cond, const float* __restrict__ inputs,
    const float* __restrict__ wk,   const float* __restrict__ wv)
{
    int bid = blockIdx.x;
    int t = threadIdx.x;
    if (bid >= 546){
        // 64 transpose tiles of 64x64: 0-15 wk, 16-31 wv, 32-63 W1 (lg-folded)
        __shared__ float tile[64][65];
        int tt = bid - 546;
        const float* src; uint32_t *dsth, *dstl;
        int K0, N0, srcN; int foldLg = 0;
        if (tt < 16){ src = wk; dsth = g_WkTh; dstl = g_WkTl;
                      K0 = (tt>>2)*64; N0 = (tt&3)*64; srcN = 256; }
        else if (tt < 32){ tt -= 16; src = wv; dsth = g_WvTh; dstl = g_WvTl;
                      K0 = (tt>>2)*64; N0 = (tt&3)*64; srcN = 256; }
        else { tt -= 32; src = W1; dsth = g_W1Th; dstl = g_W1Tl;
                      K0 = (tt>>3)*64; N0 = (tt&7)*64; srcN = 512; foldLg = 1; }
        #pragma unroll
        for (int i = t; i < 4096; i += 512){
            int kk = i >> 6, nn = i & 63;
            float v = src[(size_t)(K0+kk)*srcN + N0+nn];
            if (foldLg) v *= lg[K0+kk];
            tile[kk][nn] = v;
        }
        __syncthreads();
        #pragma unroll
        for (int i = t; i < 4096; i += 512){
            int nn = i >> 6, kk = i & 63;
            uint32_t h, l; tf32split(tile[kk][nn], h, l);
            dsth[(size_t)(N0+nn)*256 + K0+kk] = h;
            dstl[(size_t)(N0+nn)*256 + K0+kk] = l;
        }
        return;
    }
    if (bid >= 34) {
        int r = (bid - 34)*16 + (t>>5);
        int lane = t & 31;
        const float* row = inputs + (size_t)r*D;
        float v[8]; float s = 0.f;
        #pragma unroll
        for (int k=0;k<8;k++){ v[k]=row[k*32+lane]; s+=v[k]; }
        float m = warpSum(s) * (1.f/D);
        float q = 0.f;
        #pragma unroll
        for (int k=0;k<8;k++){ float d=v[k]-m; q += d*d; }
        float is = rsqrtf(warpSum(q)*(1.f/D) + LNEPS);
        if (lane == 0){ g_lnM[r]=m; g_lnIS[r]=is; }
        return;
    }
    if (bid > 0) {
        int i = (bid - 1)*512 + t;
        if (i < NB*NS*260) g_Cond[i] = cond[i];
        return;
    }
    __shared__ float sg0[D], sg1[D], sgb[D], slg[D], slb[D];
    __shared__ float sm[4];
    if (t < D) { sg0[t]=gp_w[t]; sg1[t]=gp_w[D+t]; sgb[t]=gp_b[t]; slg[t]=lg[t]; slb[t]=lb[t]; }
    __syncthreads();
    if (t == 0) {
        float m0=0,m1=0,mb=0;
        for (int d=0; d<D; d++){ m0+=sg0[d]; m1+=sg1[d]; mb+=sgb[d]; }
        m0*=(1.f/D); m1*=(1.f/D); mb*=(1.f/D);
        float V00=0,V11=0,Vbb=0,C01=0,C0b=0,C1b=0;
        for (int d=0; d<D; d++){
            float a=sg0[d]-m0, b_=sg1[d]-m1, c=sgb[d]-mb;
            V00+=a*a; V11+=b_*b_; Vbb+=c*c; C01+=a*b_; C0b+=a*c; C1b+=b_*c;
        }
        g_cov[0]=m0; g_cov[1]=m1; g_cov[2]=mb;
        g_cov[3]=V00/D; g_cov[4]=V11/D; g_cov[5]=Vbb/D;
        g_cov[6]=C01/D; g_cov[7]=C0b/D; g_cov[8]=C1b/D;
        float s2=0;
        for (int i=0;i<32;i++){ float x=-1.f + i*GSTEP; s2+=x*x; }
        g_cov[9]=s2*32.f;
        sm[0]=m0; sm[1]=m1; sm[2]=mb;
    }
    __syncthreads();
    float m0=sm[0], m1=sm[1], mb=sm[2];
    float U0=0,U1=0,Ub=0,Cc=0,G1=0;
    for (int d=0; d<D; d++){
        float w = W1[d*H + t];
        float gd = slg[d];
        U0 = fmaf((sg0[d]-m0)*gd, w, U0);
        U1 = fmaf((sg1[d]-m1)*gd, w, U1);
        Ub = fmaf((sgb[d]-mb)*gd, w, Ub);
        Cc = fmaf(slb[d], w, Cc);
        G1 = fmaf(gd, w, G1);
    }
    g_U0[t]=U0; g_U1[t]=U1; g_Ub[t]=Ub; g_C[t]=Cc + b1[t]; g_G1[t]=G1;
}

// ---------------- tensor-core GEMM: tf32, 128x64 tile, smem double-buffer ----------------
// mode 0: C = LN(inputs)@wk / @wv  (3-term split; N=256); dyn smem 61440 B
// mode 2: C = K@(diag(sg)W1) - mk*G1 + Ub  (pure tf32; N=512); dyn smem 30720 B
// dyn layout per buffer: Ah[2560], Bh[1280], (mode0 only:) Al[2560], Bl[1280]
__global__ __launch_bounds__(256,2) void gemmT(int mode, const float* __restrict__ A0,
                                               const float* __restrict__ sgv,
                                               const float* __restrict__ sbv, int N)
{
    extern __shared__ uint32_t dsm[];
    int z = blockIdx.z;
    const float* A = (mode==0) ? A0 : (z ? g_V : g_K);
    const uint32_t* BTh = (mode==0) ? (z ? g_WvTh : g_WkTh) : g_W1Th;
    const uint32_t* BTl = (mode==0) ? (z ? g_WvTl : g_WkTl) : g_W1Tl;
    float* Cm = (mode==0) ? (z ? g_V : g_K) : (z ? g_Pv : g_Pk);
    const float* meanV = (mode==0) ? nullptr : (z ? g_meanV : g_meanK);

    __shared__ float SG[256], SB[256];
    const int bufStride = (mode==0) ? 7680 : 3840;

    int bm = blockIdx.y*128, bn = blockIdx.x*64;
    int tid = threadIdx.x, lane = tid & 31, wrp = tid >> 5;
    int wm = wrp & 3, wn = wrp >> 2;       // warp grid 4(M) x 2(N), warp tile 32x32
    int qr = lane >> 2, ql = lane & 3;

    if (mode == 0){ SG[tid] = sgv[tid]; SB[tid] = sbv[tid]; }

    int arow = tid >> 1, akoff = (tid & 1) * 8;
    int brow = tid >> 2, bkoff = (tid & 3) * 4;
    float rm = 0.f, ris = 1.f;
    if (mode == 0){ rm = g_lnM[bm+arow]; ris = g_lnIS[bm+arow]; }
    __syncthreads();

    float acc[2][4][4] = {};
    const float* aptr = A + (size_t)(bm+arow)*256 + akoff;
    const uint32_t* bhp = BTh + (size_t)(bn+brow)*256 + bkoff;
    const uint32_t* blp = BTl + (size_t)(bn+brow)*256 + bkoff;

    float4 pa0 = *(const float4*)aptr;
    float4 pa1 = *(const float4*)(aptr + 4);
    uint4 pbh = *(const uint4*)bhp;
    uint4 pbl = make_uint4(0,0,0,0);
    if (mode == 0) pbl = *(const uint4*)blp;

    // prologue: convert + store tile 0 into buf 0
    {
        uint32_t* Ah = dsm;
        uint32_t* Bh = dsm + 2560;
        float av[8] = {pa0.x,pa0.y,pa0.z,pa0.w,pa1.x,pa1.y,pa1.z,pa1.w};
        uint32_t ahv[8], alv[8];
        if (mode == 0){
            #pragma unroll
            for (int i=0;i<8;i++) av[i] = fmaf((av[i]-rm)*ris, SG[akoff+i], SB[akoff+i]);
            #pragma unroll
            for (int i=0;i<8;i++) tf32split(av[i], ahv[i], alv[i]);
        } else {
            #pragma unroll
            for (int i=0;i<8;i++) ahv[i] = tf32cvt(av[i]);
        }
        *(uint4*)&Ah[arow*20 + akoff]     = make_uint4(ahv[0],ahv[1],ahv[2],ahv[3]);
        *(uint4*)&Ah[arow*20 + akoff + 4] = make_uint4(ahv[4],ahv[5],ahv[6],ahv[7]);
        *(uint4*)&Bh[brow*20 + bkoff] = pbh;
        if (mode == 0){
            uint32_t* Al = dsm + 3840;
            uint32_t* Bl = dsm + 6400;
            *(uint4*)&Al[arow*20 + akoff]     = make_uint4(alv[0],alv[1],alv[2],alv[3]);
            *(uint4*)&Al[arow*20 + akoff + 4] = make_uint4(alv[4],alv[5],alv[6],alv[7]);
            *(uint4*)&Bl[brow*20 + bkoff] = pbl;
        }
    }
    __syncthreads();

    int buf = 0;
    #pragma unroll 1
    for (int kc = 0; kc < 16; kc++){
        if (kc < 15){
            pa0 = *(const float4*)(aptr + kc*16 + 16);
            pa1 = *(const float4*)(aptr + kc*16 + 20);
            pbh = *(const uint4*)(bhp + kc*16 + 16);
            if (mode == 0) pbl = *(const uint4*)(blp + kc*16 + 16);
        }
        // compute from current buffer
        {
            const uint32_t* Ah = dsm + buf*bufStride;
            const uint32_t* Bh = Ah + 2560;
            const uint32_t* Al = Ah + 3840;
            const uint32_t* Bl = Ah + 6400;
            #pragma unroll
            for (int kk = 0; kk < 16; kk += 8){
                uint32_t ah[2][4], al[2][4];
                #pragma unroll
                for (int mi=0; mi<2; mi++){
                    int r = wm*32 + mi*16 + qr;
                    ah[mi][0] = Ah[r*20 + kk + ql];
                    ah[mi][1] = Ah[(r+8)*20 + kk + ql];
                    ah[mi][2] = Ah[r*20 + kk + ql + 4];
                    ah[mi][3] = Ah[(r+8)*20 + kk + ql + 4];
                    if (mode == 0){
                        al[mi][0] = Al[r*20 + kk + ql];
                        al[mi][1] = Al[(r+8)*20 + kk + ql];
                        al[mi][2] = Al[r*20 + kk + ql + 4];
                        al[mi][3] = Al[(r+8)*20 + kk + ql + 4];
                    }
                }
                #pragma unroll
                for (int nj=0; nj<4; nj++){
                    int n = wn*32 + nj*8 + qr;
                    uint32_t bhv[2] = { Bh[n*20 + kk + ql], Bh[n*20 + kk + ql + 4] };
                    #pragma unroll
                    for (int mi=0; mi<2; mi++)
                        mma_tf32(acc[mi][nj], ah[mi], bhv);
                    if (mode == 0){
                        uint32_t blv[2] = { Bl[n*20 + kk + ql], Bl[n*20 + kk + ql + 4] };
                        #pragma unroll
                        for (int mi=0; mi<2; mi++){
                            mma_tf32(acc[mi][nj], al[mi], bhv);
                            mma_tf32(acc[mi][nj], ah[mi], blv);
                        }
                    }
                }
            }
        }
        // convert + store next tile into other buffer
        if (kc < 15){
            int nb = buf ^ 1;
            uint32_t* Ah = dsm + nb*bufStride;
            uint32_t* Bh = Ah + 2560;
            float av[8] = {pa0.x,pa0.y,pa0.z,pa0.w,pa1.x,pa1.y,pa1.z,pa1.w};
            uint32_t ahv[8], alv[8];
            if (mode == 0){
                int kb = (kc+1)*16 + akoff;
                #pragma unroll
                for (int i=0;i<8;i++) av[i] = fmaf((av[i]-rm)*ris, SG[kb+i], SB[kb+i]);
                #pragma unroll
                for (int i=0;i<8;i++) tf32split(av[i], ahv[i], alv[i]);
            } else {
                #pragma unroll
                for (int i=0;i<8;i++) ahv[i] = tf32cvt(av[i]);
            }
            *(uint4*)&Ah[arow*20 + akoff]     = make_uint4(ahv[0],ahv[1],ahv[2],ahv[3]);
            *(uint4*)&Ah[arow*20 + akoff + 4] = make_uint4(ahv[4],ahv[5],ahv[6],ahv[7]);
            *(uint4*)&Bh[brow*20 + bkoff] = pbh;
            if (mode == 0){
                uint32_t* Al = Ah + 3840;
                uint32_t* Bl = Ah + 6400;
                *(uint4*)&Al[arow*20 + akoff]     = make_uint4(alv[0],alv[1],alv[2],alv[3]);
                *(uint4*)&Al[arow*20 + akoff + 4] = make_uint4(alv[4],alv[5],alv[6],alv[7]);
                *(uint4*)&Bl[brow*20 + bkoff] = pbl;
            }
            __syncthreads();
            buf = nb;
        }
    }
    // epilogue
    #pragma unroll
    for (int mi=0; mi<2; mi++){
        int r0 = bm + wm*32 + mi*16 + qr;
        int r1 = r0 + 8;
        float mk0 = 0.f, mk1 = 0.f;
        if (mode){ mk0 = __ldg(meanV + r0); mk1 = __ldg(meanV + r1); }
        #pragma unroll
        for (int nj=0; nj<4; nj++){
            int c0 = bn + wn*32 + nj*8 + ql*2;
            float v00 = acc[mi][nj][0], v01 = acc[mi][nj][1];
            float v10 = acc[mi][nj][2], v11 = acc[mi][nj][3];
            if (mode){
                float g0 = g_G1[c0], g1 = g_G1[c0+1];
                float u0 = g_Ub[c0], u1 = g_Ub[c0+1];
                v00 = v00 - mk0*g0 + u0; v01 = v01 - mk0*g1 + u1;
                v10 = v10 - mk1*g0 + u0; v11 = v11 - mk1*g1 + u1;
            }
            *(float2*)(Cm + (size_t)r0*N + c0) = make_float2(v00, v01);
            *(float2*)(Cm + (size_t)r1*N + c0) = make_float2(v10, v11);
        }
    }
}

// ---------------- stats (warp-per-row) ----------------
__global__ __launch_bounds__(512) void stats2(const float* __restrict__ gp_w, const float* __restrict__ gp_b)
{
    int r = blockIdx.x*16 + (threadIdx.x>>5);
    int lane = threadIdx.x & 31;
    float m0=g_cov[0], m1=g_cov[1], mb=g_cov[2];
    float Vbb=g_cov[5], C0b=g_cov[7], C1b=g_cov[8];
    float g0[8], g1[8], gbv[8];
    #pragma unroll
    for (int k=0;k<8;k++){
        int d = k*32+lane;
        g0[k]=gp_w[d]-m0; g1[k]=gp_w[D+d]-m1; gbv[k]=gp_b[d]-mb;
    }
    #pragma unroll
    for (int br=0; br<2; br++){
        const float* src = br ? g_V : g_K;
        float sK=0,sK2=0,s0=0,s1=0,sb=0;
        #pragma unroll
        for (int k=0;k<8;k++){
            float x = src[(size_t)r*D + k*32 + lane];
            sK+=x; sK2=fmaf(x,x,sK2); s0=fmaf(x,g0[k],s0); s1=fmaf(x,g1[k],s1); sb=fmaf(x,gbv[k],sb);
        }
        sK=warpSum(sK); sK2=warpSum(sK2); s0=warpSum(s0); s1=warpSum(s1); sb=warpSum(sb);
        if (lane == 0){
            float mk = sK*(1.f/D);
            float Vkk = sK2*(1.f/D) - mk*mk;
            float Ck0 = s0*(1.f/D), Ck1 = s1*(1.f/D), Ckb = sb*(1.f/D);
            float* st = br ? (g_statsV + r*4) : (g_statsK + r*4);
            st[0] = Vkk + Vbb + 2.f*Ckb;
            st[1] = 2.f*(Ck0 + C0b);
            st[2] = 2.f*(Ck1 + C1b);
            st[3] = 0.f;
            if (br) g_meanV[r]=mk; else g_meanK[r]=mk;
        }
    }
}

// ---------------- per-slot q/wtil/scalars (1024 threads) ----------------
__device__ __forceinline__ void slot_compute(
    int s, int t, const float* so,
    const float* __restrict__ ns_g, const float* __restrict__ ns_b,
    const float* __restrict__ wq,   const float* __restrict__ W2, const float* __restrict__ b2,
    float* sh, float* sq, float* qp, float* red)
{
    int w = t >> 5, lane = t & 31;
    float v = (t < 256) ? so[t] : 0.f;
    float ws = warpSum(v);
    if (lane == 0 && t < 256) red[w] = ws;
    __syncthreads();
    float m = 0.f;
    #pragma unroll
    for (int i=0;i<8;i++) m += red[i];
    m *= (1.f/D);
    float d = (t < 256) ? (v - m) : 0.f;
    ws = warpSum(d*d);
    __syncthreads();
    if (lane == 0 && t < 256) red[w] = ws;
    __syncthreads();
    float var = 0.f;
    #pragma unroll
    for (int i=0;i<8;i++) var += red[i];
    var *= (1.f/D);
    if (t < 256) sh[t] = d * rsqrtf(var + LNEPS) * ns_g[t] + ns_b[t];
    __syncthreads();

    {
        int cg = t & 63, ks = t >> 6;
        const float4* wq4 = (const float4*)wq;
        float4 a = make_float4(0.f,0.f,0.f,0.f);
        #pragma unroll 4
        for (int j = ks*16; j < ks*16 + 16; j++){
            float4 wv = __ldg(wq4 + j*64 + cg);
            float sv = sh[j];
            a.x = fmaf(sv, wv.x, a.x);
            a.y = fmaf(sv, wv.y, a.y);
            a.z = fmaf(sv, wv.z, a.z);
            a.w = fmaf(sv, wv.w, a.w);
        }
        *(float4*)(qp + ks*256 + cg*4) = a;
    }
    __syncthreads();
    if (t < 256){
        float vq = 0.f;
        #pragma unroll
        for (int ks=0; ks<16; ks++) vq += qp[ks*256 + t];
        sq[t] = vq;
    }
    __syncthreads();

    float p = (t < 256) ? sq[t]*b2[t] : 0.f;
    ws = warpSum(p);
    __syncthreads();
    if (lane == 0 && t < 256) red[w] = ws;
    __syncthreads();

    float4 qa = *(const float4*)(sq + lane*8);
    float4 qb = *(const float4*)(sq + lane*8 + 4);
    #pragma unroll 2
    for (int k = 0; k < 16; k++){
        int j = (k << 5) + w;
        const float4* w2r = (const float4*)(W2 + j*D);
        float4 wa = __ldg(w2r + lane*2);
        float4 wb = __ldg(w2r + lane*2 + 1);
        float acc = wa.x*qa.x + wa.y*qa.y + wa.z*qa.z + wa.w*qa.w
                  + wb.x*qb.x + wb.y*qb.y + wb.z*qb.z + wb.w*qb.w;
        acc = warpSum(acc);
        if (lane == 0) g_slot[s*520 + j] = acc;
    }
    if (t == 0){
        float qb2 = 0.f;
        #pragma unroll
        for (int i=0;i<8;i++) qb2 += red[i];
        float px = fminf(fmaxf(g_Cond[s*260+256], -1.f), 1.f);
        float py = fminf(fmaxf(g_Cond[s*260+257], -1.f), 1.f);
        float sx = fminf(fmaxf(g_Cond[s*260+258], 1e-3f), 2.f);
        float sy = fminf(fmaxf(g_Cond[s*260+259], 1e-3f), 2.f);
        float* o = g_slot + s*520 + 512;
        o[0]=qb2; o[1]=px; o[2]=py; o[3]=1.f/(5.f*sx); o[4]=1.f/(5.f*sy);
    }
}

__global__ __launch_bounds__(1024) void slot0(const float* __restrict__ ns_g, const float* __restrict__ ns_b,
                                              const float* __restrict__ wq,   const float* __restrict__ W2,
                                              const float* __restrict__ b2)
{
    __shared__ float so[256], sh[256], sq[256], qp[4096], red[16];
    int s = blockIdx.x, t = threadIdx.x;
    if (t < 256) so[t] = g_Cond[s*260 + t];
    __syncthreads();
    slot_compute(s, t, so, ns_g, ns_b, wq, W2, b2, sh, sq, qp, red);
}

// ---------------- fused: dots + softmax + attn0 + partials (2-px ILP) ----------------
__global__ __launch_bounds__(256) void iter1_kernel(int last, float* __restrict__ out)
{
    int b = blockIdx.y, chunk = blockIdx.x;
    int t = threadIdx.x, w = t >> 5, lane = t & 31;
    __shared__ float sPk[16*512];
    __shared__ float sdots[NS][16];
    __shared__ float sscal[NS][5];

    float* attnDst = last ? (out + 16640) : g_attn0;
    float* relOut  = out + 16640 + 65536;
    int n0 = chunk*16;

    {
        const float4* src = (const float4*)(g_Pk + (((size_t)(b<<10) + n0)<<9));
        float4* dst = (float4*)sPk;
        #pragma unroll
        for (int i=0;i<8;i++) dst[t + i*256] = __ldg(src + t + i*256);
    }

    float4 u0v[4], u1v[4], wtv[4], cv[4];
    const float* wts = g_slot + (b*NS + w)*520;
    #pragma unroll
    for (int jj=0; jj<4; jj++){
        int j = jj*128 + lane*4;
        u0v[jj] = *(const float4*)(g_U0 + j);
        u1v[jj] = *(const float4*)(g_U1 + j);
        cv[jj]  = *(const float4*)(g_C  + j);
        wtv[jj] = *(const float4*)(wts  + j);
    }
    if (t < 40) sscal[t/5][t%5] = g_slot[(b*NS + t/5)*520 + 512 + (t%5)];
    __syncthreads();

    float qb2=sscal[w][0], px=sscal[w][1], py=sscal[w][2], i5x=sscal[w][3], i5y=sscal[w][4];
    float V00=g_cov[3], V11=g_cov[4], C01_2=2.f*g_cov[6];

    for (int pp=0; pp<16; pp+=2){
        int nA = n0 + pp, nB = nA + 1;
        float gxA = -1.f + (float)(nA>>5)*GSTEP, gyA = -1.f + (float)(nA&31)*GSTEP;
        float gxB = -1.f + (float)(nB>>5)*GSTEP, gyB = -1.f + (float)(nB&31)*GSTEP;
        float aA = (gxA-px)*i5x, cA = (gyA-py)*i5y;
        float aB = (gxB-px)*i5x, cB = (gyB-py)*i5y;
        const float4 stA = *(const float4*)(g_statsK + ((b<<10)+nA)*4);
        const float4 stB = *(const float4*)(g_statsK + ((b<<10)+nB)*4);
        float varA = stA.x + aA*stA.y + cA*stA.z + aA*aA*V00 + cA*cA*V11 + aA*cA*C01_2;
        float varB = stB.x + aB*stB.y + cB*stB.z + aB*aB*V00 + cB*cB*V11 + aB*cB*C01_2;
        float isA = rsqrtf(varA + LNEPS);
        float isB = rsqrtf(varB + LNEPS);
        const float* pkA = sPk + pp*512;
        const float* pkB = pkA + 512;
        float acA0=0.f, acA1=0.f, acB0=0.f, acB1=0.f;
        #pragma unroll
        for (int jj=0; jj<4; jj++){
            float4 p4A = *(const float4*)(pkA + jj*128 + lane*4);
            float4 p4B = *(const float4*)(pkB + jj*128 + lane*4);
            float eA0 = fmaf(isA, fmaf(cA,u1v[jj].x, fmaf(aA,u0v[jj].x, p4A.x)), cv[jj].x);
            float eB0 = fmaf(isB, fmaf(cB,u1v[jj].x, fmaf(aB,u0v[jj].x, p4B.x)), cv[jj].x);
            float eA1 = fmaf(isA, fmaf(cA,u1v[jj].y, fmaf(aA,u0v[jj].y, p4A.y)), cv[jj].y);
            float eB1 = fmaf(isB, fmaf(cB,u1v[jj].y, fmaf(aB,u0v[jj].y, p4B.y)), cv[jj].y);
            float eA2 = fmaf(isA, fmaf(cA,u1v[jj].z, fmaf(aA,u0v[jj].z, p4A.z)), cv[jj].z);
            float eB2 = fmaf(isB, fmaf(cB,u1v[jj].z, fmaf(aB,u0v[jj].z, p4B.z)), cv[jj].z);
            float eA3 = fmaf(isA, fmaf(cA,u1v[jj].w, fmaf(aA,u0v[jj].w, p4A.w)), cv[jj].w);
            float eB3 = fmaf(isB, fmaf(cB,u1v[jj].w, fmaf(aB,u0v[jj].w, p4B.w)), cv[jj].w);
            acA0 = fmaf(fmaxf(eA0,0.f), wtv[jj].x, acA0);
            acB0 = fmaf(fmaxf(eB0,0.f), wtv[jj].x, acB0);
            acA1 = fmaf(fmaxf(eA1,0.f), wtv[jj].y, acA1);
            acB1 = fmaf(fmaxf(eB1,0.f), wtv[jj].y, acB1);
            acA0 = fmaf(fmaxf(eA2,0.f), wtv[jj].z, acA0);
            acB0 = fmaf(fmaxf(eB2,0.f), wtv[jj].z, acB0);
            acA1 = fmaf(fmaxf(eA3,0.f), wtv[jj].w, acA1);
            acB1 = fmaf(fmaxf(eB3,0.f), wtv[jj].w, acB1);
        }
        float sA = acA0 + acA1, sB = acB0 + acB1;
        #pragma unroll
        for (int o=16;o;o>>=1){
            sA += __shfl_xor_sync(0xffffffffu, sA, o);
            sB += __shfl_xor_sync(0xffffffffu, sB, o);
        }
        if (lane == 0){
            sdots[w][pp]   = ATTN_SCALE * (sA + qb2);
            sdots[w][pp+1] = ATTN_SCALE * (sB + qb2);
            if (last){
                float2* rpA = (float2*)(relOut + ((((size_t)(b*NS+w)<<10)+nA)<<1));
                float2* rpB = (float2*)(relOut + ((((size_t)(b*NS+w)<<10)+nB)<<1));
                *rpA = make_float2(aA, cA);
                *rpB = make_float2(aB, cB);
            }
        }
    }
    __syncthreads();

    float a0 = 0.f, gx = 0.f, gy = 0.f;
    if (lane < 16){
        int n = n0 + lane;
        float dd[NS]; float mx = -1e30f;
        #pragma unroll
        for (int k=0;k<NS;k++){ dd[k] = sdots[k][lane]; mx = fmaxf(mx, dd[k]); }
        float sum = 0.f;
        #pragma unroll
        for (int k=0;k<NS;k++){ dd[k] = expf(dd[k]-mx); sum += dd[k]; }
        a0 = dd[w] / sum;
        attnDst[((b*NS+w)<<10) + n] = a0;
        gx = -1.f + (float)(n>>5)*GSTEP;
        gy = -1.f + (float)(n&31)*GSTEP;
    }
    float S0 = warpSum(a0);
    float Sx = warpSum(a0*gx);
    float Sy = warpSum(a0*gy);
    float Sxx = warpSum(a0*gx*gx);
    float Syy = warpSum(a0*gy*gy);
    if (lane == 0){
        float* pp = g_part + ((size_t)((b*NS+w)*64 + chunk))*8;
        pp[0]=S0; pp[1]=Sx; pp[2]=Sy; pp[3]=Sxx; pp[4]=Syy;
    }
}

// ---------------- slot-fused vacc + finalize ----------------
__global__ __launch_bounds__(512) void vaccF_kernel()
{
    int chunk = blockIdx.x;
    int b = blockIdx.y;
    int t = threadIdx.x;
    __shared__ float4 sC4[NS][64];
    __shared__ float sden[NS];

    int sl = t >> 6, p = t & 63;
    int n = chunk*64 + p;
    int gs = b*NS + sl;
    float rawA;
    {
        float px = g_slot[gs*520+513], py = g_slot[gs*520+514];
        float i5x= g_slot[gs*520+515], i5y= g_slot[gs*520+516];
        float gx = -1.f + (float)(n>>5)*GSTEP;
        float gy = -1.f + (float)(n&31)*GSTEP;
        float a = (gx-px)*i5x, c = (gy-py)*i5y;
        const float4 st = *(const float4*)(g_statsV + ((b<<10)+n)*4);
        float var = st.x + a*st.y + c*st.z + a*a*g_cov[3] + c*c*g_cov[4] + a*c*2.f*g_cov[6];
        float is = rsqrtf(var + LNEPS);
        rawA = g_attn0[(gs<<10)+n];
        sC4[sl][p] = make_float4(is, is*a, is*c, 0.f);
    }
    if (t < 256){
        int w = t >> 5, lane = t & 31;
        const float* pp0 = g_part + ((size_t)((b*NS+w)*64 + lane))*8;
        const float* pp1 = pp0 + 32*8;
        float S0 = warpSum(pp0[0] + pp1[0]);
        if (chunk == 0){
            float Sx = warpSum(pp0[1] + pp1[1]);
            float Sy = warpSum(pp0[2] + pp1[2]);
            float Sxx = warpSum(pp0[3] + pp1[3]);
            float Syy = warpSum(pp0[4] + pp1[4]);
            if (lane == 0){
                float px = Sx, py = Sy, G2 = g_cov[9];
                float vx = Sxx - 2.f*px*Sx + px*px*S0 + EPSA*(G2 + 1024.f*px*px);
                float vy = Syy - 2.f*py*Sy + py*py*S0 + EPSA*(G2 + 1024.f*py*py);
                float sx = fminf(fmaxf(sqrtf(fmaxf(vx,0.f)), 1e-3f), 2.f);
                float sy = fminf(fmaxf(sqrtf(fmaxf(vy,0.f)), 1e-3f), 2.f);
                int s2 = b*NS + w;
                g_Cond[s2*260+256]=px; g_Cond[s2*260+257]=py;
                g_Cond[s2*260+258]=sx; g_Cond[s2*260+259]=sy;
            }
        }
        if (lane == 0) sden[w] = 1.f/(S0 + 1024.f*EPSA);
    }
    __syncthreads();
    sC4[sl][p].w = (rawA + EPSA) * sden[sl];
    __syncthreads();

    float u0 = g_U0[t], u1 = g_U1[t], C = g_C[t];
    const float* pvb = g_Pv + ((((size_t)(b<<10)) + (size_t)chunk*64) << 9) + t;
    float acc[NS] = {};
    #pragma unroll 4
    for (int q=0; q<64; q++){
        float pv = __ldg(pvb + ((size_t)q << 9));
        #pragma unroll
        for (int s2=0; s2<NS; s2++){
            float4 cf = sC4[s2][q];
            float pre = fmaf(cf.y, u0, fmaf(cf.z, u1, fmaf(cf.x, pv, C)));
            acc[s2] = fmaf(fmaxf(pre, 0.f), cf.w, acc[s2]);
        }
    }
    #pragma unroll
    for (int s2=0; s2<NS; s2++)
        g_spart[((size_t)((b*NS+s2)*16 + chunk))*H + t] = acc[s2];
}

// ---------------- GRU update + slot prep for next iter ----------------
__global__ __launch_bounds__(1024) void updslot_kernel(
    const float* __restrict__ W2,  const float* __restrict__ b2,
    const float* __restrict__ Wih, const float* __restrict__ Whh,
    const float* __restrict__ bih, const float* __restrict__ bhh,
    const float* __restrict__ ns_g, const float* __restrict__ ns_b,
    const float* __restrict__ wq)
{
    __shared__ float ss[H], so[256], su[256], qp[4096], sgx[768], sgh[768], sh[256], sq[256], red[16];
    int s = blockIdx.x, t = threadIdx.x, w = t >> 5, lane = t & 31;

    if (t < 512){
        float r0 = 0.f;
        #pragma unroll
        for (int c=0; c<16; c++) r0 += g_spart[((size_t)(s*16 + c))*H + t];
        ss[t] = r0;
    }
    if (t < 256) so[t] = g_Cond[s*260 + t];
    __syncthreads();

    {
        int cg = t & 63, ks = t >> 6;
        const float4* W24 = (const float4*)W2;
        float4 a = make_float4(0.f,0.f,0.f,0.f);
        #pragma unroll 4
        for (int j = ks*32; j < ks*32 + 32; j++){
            float4 wv = __ldg(W24 + j*64 + cg);
            float sv = ss[j];
            a.x = fmaf(sv, wv.x, a.x);
            a.y = fmaf(sv, wv.y, a.y);
            a.z = fmaf(sv, wv.z, a.z);
            a.w = fmaf(sv, wv.w, a.w);
        }
        *(float4*)(qp + ks*256 + cg*4) = a;
    }
    __syncthreads();
    if (t < 256){
        float u = b2[t];
        #pragma unroll
        for (int ks=0; ks<16; ks++) u += qp[ks*256 + t];
        su[t] = u;
    }
    __syncthreads();

    {
        float4 sua = *(const float4*)(su + lane*8);
        float4 sub = *(const float4*)(su + lane*8 + 4);
        float4 soa = *(const float4*)(so + lane*8);
        float4 sob = *(const float4*)(so + lane*8 + 4);
        #pragma unroll 2
        for (int k = 0; k < 24; k++){
            int i = (k << 5) + w;
            const float4* wi4 = (const float4*)(Wih + i*D);
            const float4* wh4 = (const float4*)(Whh + i*D);
            float4 wa = __ldg(wi4 + lane*2);
            float4 wb = __ldg(wi4 + lane*2 + 1);
            float4 ha = __ldg(wh4 + lane*2);
            float4 hb = __ldg(wh4 + lane*2 + 1);
            float ax = wa.x*sua.x + wa.y*sua.y + wa.z*sua.z + wa.w*sua.w
                     + wb.x*sub.x + wb.y*sub.y + wb.z*sub.z + wb.w*sub.w;
            float ah = ha.x*soa.x + ha.y*soa.y + ha.z*soa.z + ha.w*soa.w
                     + hb.x*sob.x + hb.y*sob.y + hb.z*sob.z + hb.w*sob.w;
            ax = warpSum(ax); ah = warpSum(ah);
            if (lane == 0){ sgx[i] = ax + bih[i]; sgh[i] = ah + bhh[i]; }
        }
    }
    __syncthreads();

    if (t < 256){
        float r = 1.f/(1.f + expf(-(sgx[t]     + sgh[t])));
        float z = 1.f/(1.f + expf(-(sgx[256+t] + sgh[256+t])));
        float nn = tanhf(sgx[512+t] + r*sgh[512+t]);
        float nv = (1.f - z)*nn + z*so[t];
        g_Cond[s*260 + t] = nv;
        so[t] = nv;
    }
    __syncthreads();

    slot_compute(s, t, so, ns_g, ns_b, wq, W2, b2, sh, sq, qp, red);
}

// ---------------- final: pos/scl + write conditioning to out ----------------
__global__ void finz3_kernel(float* __restrict__ out)
{
    __shared__ float sres[4];
    int s = blockIdx.x, t = threadIdx.x;
    if (t < 32){
        const float* pp0 = g_part + ((size_t)(s*64 + t))*8;
        const float* pp1 = pp0 + 32*8;
        float S0 = warpSum(pp0[0] + pp1[0]);
        float Sx = warpSum(pp0[1] + pp1[1]);
        float Sy = warpSum(pp0[2] + pp1[2]);
        float Sxx = warpSum(pp0[3] + pp1[3]);
        float Syy = warpSum(pp0[4] + pp1[4]);
        if (t == 0){
            float px = Sx, py = Sy, G2 = g_cov[9];
            float vx = Sxx - 2.f*px*Sx + px*px*S0 + EPSA*(G2 + 1024.f*px*px);
            float vy = Syy - 2.f*py*Sy + py*py*S0 + EPSA*(G2 + 1024.f*py*py);
            float sx = fminf(fmaxf(sqrtf(fmaxf(vx,0.f)), 1e-3f), 2.f);
            float sy = fminf(fmaxf(sqrtf(fmaxf(vy,0.f)), 1e-3f), 2.f);
            sres[0]=px; sres[1]=py; sres[2]=sx; sres[3]=sy;
        }
    }
    __syncthreads();
    for (int i = t; i < 260; i += 256)
        out[s*260 + i] = (i < 256) ? g_Cond[s*260 + i] : sres[i - 256];
}

// ---------------- launch ----------------
extern "C" void kernel_launch(void* const* d_in, const int* in_sizes, int n_in,
                              void* d_out, int out_size)
{
    const float* inputs = (const float*)d_in[0];
    const float* cond   = (const float*)d_in[1];
    const float* ni_g   = (const float*)d_in[2];
    const float* ni_b   = (const float*)d_in[3];
    const float* ns_g   = (const float*)d_in[4];
    const float* ns_b   = (const float*)d_in[5];
    const float* wq     = (const float*)d_in[6];
    const float* wk     = (const float*)d_in[7];
    const float* wv     = (const float*)d_in[8];
    const float* gp_w   = (const float*)d_in[9];
    const float* gp_b   = (const float*)d_in[10];
    const float* ge_ln_g= (const float*)d_in[11];
    const float* ge_ln_b= (const float*)d_in[12];
    const float* ge_w1  = (const float*)d_in[13];
    const float* ge_b1  = (const float*)d_in[14];
    const float* ge_w2  = (const float*)d_in[15];
    const float* ge_b2  = (const float*)d_in[16];
    const float* gru_wih= (const float*)d_in[17];
    const float* gru_whh= (const float*)d_in[18];
    const float* gru_bih= (const float*)d_in[19];
    const float* gru_bhh= (const float*)d_in[20];
    float* out = (float*)d_out;

    static int s_attr = 0;
    if (!s_attr){
        cudaFuncSetAttribute(gemmT, cudaFuncAttributeMaxDynamicSharedMemorySize, 61440);
        s_attr = 1;
    }

    pre_kernel<<<610, 512>>>(gp_w, gp_b, ge_ln_g, ge_ln_b, ge_w1, ge_b1, cond, inputs, wk, wv);
    gemmT<<<dim3(4,64,2), 256, 61440>>>(0, inputs, ni_g, ni_b, 256);
    stats2<<<512, 512>>>(gp_w, gp_b);
    gemmT<<<dim3(8,64,2), 256, 30720>>>(2, nullptr, nullptr, nullptr, 512);
    slot0<<<64, 1024>>>(ns_g, ns_b, wq, ge_w2, ge_b2);

    for (int it = 0; it < 3; it++) {
        iter1_kernel<<<dim3(64,8), 256>>>(0, out);
        vaccF_kernel<<<dim3(16,8), 512>>>();
        updslot_kernel<<<64, 1024>>>(ge_w2, ge_b2, gru_wih, gru_whh, gru_bih, gru_bhh,
                                     ns_g, ns_b, wq);
    }
    iter1_kernel<<<dim3(64,8), 256>>>(1, out);
    finz3_kernel<<<64, 256>>>(out);
}

// round 16
// speedup vs baseline: 1.7067x; 1.0154x over previous
#include <cuda_runtime.h>
#include <math.h>
#include <stdint.h>

// ---------------- problem constants ----------------
#define NB 8
#define NPIX 1024
#define NS 8
#define D 256
#define H 512
#define NROWS (NB*NPIX)
#define EPSA 1e-8f
#define LNEPS 1e-5f
#define ATTN_SCALE 0.0625f
#define GSTEP (2.0f/31.0f)

// ---------------- scratch ----------------
__device__ __align__(16) float g_K [NROWS*D];
__device__ __align__(16) float g_V [NROWS*D];
__device__ __align__(16) float g_Pk[NROWS*H];
__device__ __align__(16) float g_Pv[NROWS*H];
__device__ __align__(16) float g_statsK[NROWS*4];
__device__ __align__(16) float g_statsV[NROWS*4];
__device__ float g_meanK[NROWS];
__device__ float g_meanV[NROWS];
__device__ float g_lnM[NROWS];
__device__ float g_lnIS[NROWS];
__device__ __align__(16) float g_U0[H];
__device__ __align__(16) float g_U1[H];
__device__ __align__(16) float g_Ub[H];
__device__ __align__(16) float g_C[H];
__device__ __align__(16) float g_G1[H];
__device__ float g_cov[16];
__device__ float g_Cond[NB*NS*260];
__device__ __align__(16) float g_slot[NB*NS*520];
__device__ float g_attn0[NB*NS*NPIX];
__device__ float g_part[NB*NS*64*8];
__device__ float g_spart[NB*NS*16*H];
// transposed + tf32-split weights (n-major: [n][k])
__device__ __align__(16) uint32_t g_WkTh[65536], g_WkTl[65536];
__device__ __align__(16) uint32_t g_WvTh[65536], g_WvTl[65536];
__device__ __align__(16) uint32_t g_W1Th[131072], g_W1Tl[131072];

__device__ __forceinline__ float warpSum(float v) {
    #pragma unroll
    for (int o = 16; o; o >>= 1) v += __shfl_xor_sync(0xffffffffu, v, o);
    return v;
}

__device__ __forceinline__ void tf32split(float x, uint32_t& h, uint32_t& l){
    uint32_t hb; asm("cvt.rna.tf32.f32 %0, %1;" : "=r"(hb) : "f"(x));
    float lo = x - __uint_as_float(hb);
    uint32_t lb; asm("cvt.rna.tf32.f32 %0, %1;" : "=r"(lb) : "f"(lo));
    h = hb; l = lb;
}

__device__ __forceinline__ uint32_t tf32cvt(float x){
    uint32_t hb; asm("cvt.rna.tf32.f32 %0, %1;" : "=r"(hb) : "f"(x));
    return hb;
}

__device__ __forceinline__ void mma_tf32(float* d, const uint32_t* a, const uint32_t* b){
    asm volatile("mma.sync.aligned.m16n8k8.row.col.f32.tf32.tf32.f32 "
        "{%0,%1,%2,%3}, {%4,%5,%6,%7}, {%8,%9}, {%0,%1,%2,%3};"
        : "+f"(d[0]), "+f"(d[1]), "+f"(d[2]), "+f"(d[3])
        : "r"(a[0]), "r"(a[1]), "r"(a[2]), "r"(a[3]), "r"(b[0]), "r"(b[1]));
}

// ---------------- pre: constants + cond copy + LN row stats + tiled weight transpose/split ----------------
__global__ __launch_bounds__(512) void pre_kernel(
    const float* __restrict__ gp_w, const float* __restrict__ gp_b,
    const float* __restrict__ lg,   const float* __restrict__ lb,
    const float* __restrict__ W1,   const float* __restrict__ b1,
    const float* __restrict__ cond, const float* __restrict__ inputs,
    const float* __restrict__ wk,   const float* __restrict__ wv)
{
    int bid = blockIdx.x;
    int t = threadIdx.x;
    if (bid >= 546){
        __shared__ float tile[64][65];
        int tt = bid - 546;
        const float* src; uint32_t *dsth, *dstl;
        int K0, N0, srcN; int foldLg = 0;
        if (tt < 16){ src = wk; dsth = g_WkTh; dstl = g_WkTl;
                      K0 = (tt>>2)*64; N0 = (tt&3)*64; srcN = 256; }
        else if (tt < 32){ tt -= 16; src = wv; dsth = g_WvTh; dstl = g_WvTl;
                      K0 = (tt>>2)*64; N0 = (tt&3)*64; srcN = 256; }
        else { tt -= 32; src = W1; dsth = g_W1Th; dstl = g_W1Tl;
                      K0 = (tt>>3)*64; N0 = (tt&7)*64; srcN = 512; foldLg = 1; }
        #pragma unroll
        for (int i = t; i < 4096; i += 512){
            int kk = i >> 6, nn = i & 63;
            float v = src[(size_t)(K0+kk)*srcN + N0+nn];
            if (foldLg) v *= lg[K0+kk];
            tile[kk][nn] = v;
        }
        __syncthreads();
        #pragma unroll
        for (int i = t; i < 4096; i += 512){
            int nn = i >> 6, kk = i & 63;
            uint32_t h, l; tf32split(tile[kk][nn], h, l);
            dsth[(size_t)(N0+nn)*256 + K0+kk] = h;
            dstl[(size_t)(N0+nn)*256 + K0+kk] = l;
        }
        return;
    }
    if (bid >= 34) {
        int r = (bid - 34)*16 + (t>>5);
        int lane = t & 31;
        const float* row = inputs + (size_t)r*D;
        float v[8]; float s1 = 0.f, s2 = 0.f;
        #pragma unroll
        for (int k=0;k<8;k++){ v[k]=row[k*32+lane]; s1+=v[k]; s2=fmaf(v[k],v[k],s2); }
        #pragma unroll
        for (int o = 16; o; o >>= 1){
            s1 += __shfl_xor_sync(0xffffffffu, s1, o);
            s2 += __shfl_xor_sync(0xffffffffu, s2, o);
        }
        float m = s1 * (1.f/D);
        float var = s2 * (1.f/D) - m*m;
        float is = rsqrtf(var + LNEPS);
        if (lane == 0){ g_lnM[r]=m; g_lnIS[r]=is; }
        return;
    }
    if (bid > 0) {
        int i = (bid - 1)*512 + t;
        if (i < NB*NS*260) g_Cond[i] = cond[i];
        return;
    }
    __shared__ float sg0[D], sg1[D], sgb[D], slg[D], slb[D];
    __shared__ float sm[4];
    if (t < D) { sg0[t]=gp_w[t]; sg1[t]=gp_w[D+t]; sgb[t]=gp_b[t]; slg[t]=lg[t]; slb[t]=lb[t]; }
    __syncthreads();
    if (t == 0) {
        float m0=0,m1=0,mb=0;
        for (int d=0; d<D; d++){ m0+=sg0[d]; m1+=sg1[d]; mb+=sgb[d]; }
        m0*=(1.f/D); m1*=(1.f/D); mb*=(1.f/D);
        float V00=0,V11=0,Vbb=0,C01=0,C0b=0,C1b=0;
        for (int d=0; d<D; d++){
            float a=sg0[d]-m0, b_=sg1[d]-m1, c=sgb[d]-mb;
            V00+=a*a; V11+=b_*b_; Vbb+=c*c; C01+=a*b_; C0b+=a*c; C1b+=b_*c;
        }
        g_cov[0]=m0; g_cov[1]=m1; g_cov[2]=mb;
        g_cov[3]=V00/D; g_cov[4]=V11/D; g_cov[5]=Vbb/D;
        g_cov[6]=C01/D; g_cov[7]=C0b/D; g_cov[8]=C1b/D;
        float s2=0;
        for (int i=0;i<32;i++){ float x=-1.f + i*GSTEP; s2+=x*x; }
        g_cov[9]=s2*32.f;
        sm[0]=m0; sm[1]=m1; sm[2]=mb;
    }
    __syncthreads();
    float m0=sm[0], m1=sm[1], mb=sm[2];
    float U0=0,U1=0,Ub=0,Cc=0,G1=0;
    for (int d=0; d<D; d++){
        float w = W1[d*H + t];
        float gd = slg[d];
        U0 = fmaf((sg0[d]-m0)*gd, w, U0);
        U1 = fmaf((sg1[d]-m1)*gd, w, U1);
        Ub = fmaf((sgb[d]-mb)*gd, w, Ub);
        Cc = fmaf(slb[d], w, Cc);
        G1 = fmaf(gd, w, G1);
    }
    g_U0[t]=U0; g_U1[t]=U1; g_Ub[t]=Ub; g_C[t]=Cc + b1[t]; g_G1[t]=G1;
}

// ---------------- tensor-core GEMM: tf32, 128x64 tile, smem double-buffer ----------------
__global__ __launch_bounds__(256,2) void gemmT(int mode, const float* __restrict__ A0,
                                               const float* __restrict__ sgv,
                                               const float* __restrict__ sbv, int N)
{
    extern __shared__ uint32_t dsm[];
    int z = blockIdx.z;
    const float* A = (mode==0) ? A0 : (z ? g_V : g_K);
    const uint32_t* BTh = (mode==0) ? (z ? g_WvTh : g_WkTh) : g_W1Th;
    const uint32_t* BTl = (mode==0) ? (z ? g_WvTl : g_WkTl) : g_W1Tl;
    float* Cm = (mode==0) ? (z ? g_V : g_K) : (z ? g_Pv : g_Pk);
    const float* meanV = (mode==0) ? nullptr : (z ? g_meanV : g_meanK);

    __shared__ float SG[256], SB[256];
    const int bufStride = (mode==0) ? 7680 : 3840;

    int bm = blockIdx.y*128, bn = blockIdx.x*64;
    int tid = threadIdx.x, lane = tid & 31, wrp = tid >> 5;
    int wm = wrp & 3, wn = wrp >> 2;
    int qr = lane >> 2, ql = lane & 3;

    if (mode == 0){ SG[tid] = sgv[tid]; SB[tid] = sbv[tid]; }

    int arow = tid >> 1, akoff = (tid & 1) * 8;
    int brow = tid >> 2, bkoff = (tid & 3) * 4;
    float rm = 0.f, ris = 1.f;
    if (mode == 0){ rm = g_lnM[bm+arow]; ris = g_lnIS[bm+arow]; }
    __syncthreads();

    float acc[2][4][4] = {};
    const float* aptr = A + (size_t)(bm+arow)*256 + akoff;
    const uint32_t* bhp = BTh + (size_t)(bn+brow)*256 + bkoff;
    const uint32_t* blp = BTl + (size_t)(bn+brow)*256 + bkoff;

    float4 pa0 = *(const float4*)aptr;
    float4 pa1 = *(const float4*)(aptr + 4);
    uint4 pbh = *(const uint4*)bhp;
    uint4 pbl = make_uint4(0,0,0,0);
    if (mode == 0) pbl = *(const uint4*)blp;

    {
        uint32_t* Ah = dsm;
        uint32_t* Bh = dsm + 2560;
        float av[8] = {pa0.x,pa0.y,pa0.z,pa0.w,pa1.x,pa1.y,pa1.z,pa1.w};
        uint32_t ahv[8], alv[8];
        if (mode == 0){
            #pragma unroll
            for (int i=0;i<8;i++) av[i] = fmaf((av[i]-rm)*ris, SG[akoff+i], SB[akoff+i]);
            #pragma unroll
            for (int i=0;i<8;i++) tf32split(av[i], ahv[i], alv[i]);
        } else {
            #pragma unroll
            for (int i=0;i<8;i++) ahv[i] = tf32cvt(av[i]);
        }
        *(uint4*)&Ah[arow*20 + akoff]     = make_uint4(ahv[0],ahv[1],ahv[2],ahv[3]);
        *(uint4*)&Ah[arow*20 + akoff + 4] = make_uint4(ahv[4],ahv[5],ahv[6],ahv[7]);
        *(uint4*)&Bh[brow*20 + bkoff] = pbh;
        if (mode == 0){
            uint32_t* Al = dsm + 3840;
            uint32_t* Bl = dsm + 6400;
            *(uint4*)&Al[arow*20 + akoff]     = make_uint4(alv[0],alv[1],alv[2],alv[3]);
            *(uint4*)&Al[arow*20 + akoff + 4] = make_uint4(alv[4],alv[5],alv[6],alv[7]);
            *(uint4*)&Bl[brow*20 + bkoff] = pbl;
        }
    }
    __syncthreads();

    int buf = 0;
    #pragma unroll 1
    for (int kc = 0; kc < 16; kc++){
        if (kc < 15){
            pa0 = *(const float4*)(aptr + kc*16 + 16);
            pa1 = *(const float4*)(aptr + kc*16 + 20);
            pbh = *(const uint4*)(bhp + kc*16 + 16);
            if (mode == 0) pbl = *(const uint4*)(blp + kc*16 + 16);
        }
        {
            const uint32_t* Ah = dsm + buf*bufStride;
            const uint32_t* Bh = Ah + 2560;
            const uint32_t* Al = Ah + 3840;
            const uint32_t* Bl = Ah + 6400;
            #pragma unroll
            for (int kk = 0; kk < 16; kk += 8){
                uint32_t ah[2][4], al[2][4];
                #pragma unroll
                for (int mi=0; mi<2; mi++){
                    int r = wm*32 + mi*16 + qr;
                    ah[mi][0] = Ah[r*20 + kk + ql];
                    ah[mi][1] = Ah[(r+8)*20 + kk + ql];
                    ah[mi][2] = Ah[r*20 + kk + ql + 4];
                    ah[mi][3] = Ah[(r+8)*20 + kk + ql + 4];
                    if (mode == 0){
                        al[mi][0] = Al[r*20 + kk + ql];
                        al[mi][1] = Al[(r+8)*20 + kk + ql];
                        al[mi][2] = Al[r*20 + kk + ql + 4];
                        al[mi][3] = Al[(r+8)*20 + kk + ql + 4];
                    }
                }
                #pragma unroll
                for (int nj=0; nj<4; nj++){
                    int n = wn*32 + nj*8 + qr;
                    uint32_t bhv[2] = { Bh[n*20 + kk + ql], Bh[n*20 + kk + ql + 4] };
                    #pragma unroll
                    for (int mi=0; mi<2; mi++)
                        mma_tf32(acc[mi][nj], ah[mi], bhv);
                    if (mode == 0){
                        uint32_t blv[2] = { Bl[n*20 + kk + ql], Bl[n*20 + kk + ql + 4] };
                        #pragma unroll
                        for (int mi=0; mi<2; mi++){
                            mma_tf32(acc[mi][nj], al[mi], bhv);
                            mma_tf32(acc[mi][nj], ah[mi], blv);
                        }
                    }
                }
            }
        }
        if (kc < 15){
            int nb = buf ^ 1;
            uint32_t* Ah = dsm + nb*bufStride;
            uint32_t* Bh = Ah + 2560;
            float av[8] = {pa0.x,pa0.y,pa0.z,pa0.w,pa1.x,pa1.y,pa1.z,pa1.w};
            uint32_t ahv[8], alv[8];
            if (mode == 0){
                int kb = (kc+1)*16 + akoff;
                #pragma unroll
                for (int i=0;i<8;i++) av[i] = fmaf((av[i]-rm)*ris, SG[kb+i], SB[kb+i]);
                #pragma unroll
                for (int i=0;i<8;i++) tf32split(av[i], ahv[i], alv[i]);
            } else {
                #pragma unroll
                for (int i=0;i<8;i++) ahv[i] = tf32cvt(av[i]);
            }
            *(uint4*)&Ah[arow*20 + akoff]     = make_uint4(ahv[0],ahv[1],ahv[2],ahv[3]);
            *(uint4*)&Ah[arow*20 + akoff + 4] = make_uint4(ahv[4],ahv[5],ahv[6],ahv[7]);
            *(uint4*)&Bh[brow*20 + bkoff] = pbh;
            if (mode == 0){
                uint32_t* Al = Ah + 3840;
                uint32_t* Bl = Ah + 6400;
                *(uint4*)&Al[arow*20 + akoff]     = make_uint4(alv[0],alv[1],alv[2],alv[3]);
                *(uint4*)&Al[arow*20 + akoff + 4] = make_uint4(alv[4],alv[5],alv[6],alv[7]);
                *(uint4*)&Bl[brow*20 + bkoff] = pbl;
            }
            __syncthreads();
            buf = nb;
        }
    }
    #pragma unroll
    for (int mi=0; mi<2; mi++){
        int r0 = bm + wm*32 + mi*16 + qr;
        int r1 = r0 + 8;
        float mk0 = 0.f, mk1 = 0.f;
        if (mode){ mk0 = __ldg(meanV + r0); mk1 = __ldg(meanV + r1); }
        #pragma unroll
        for (int nj=0; nj<4; nj++){
            int c0 = bn + wn*32 + nj*8 + ql*2;
            float v00 = acc[mi][nj][0], v01 = acc[mi][nj][1];
            float v10 = acc[mi][nj][2], v11 = acc[mi][nj][3];
            if (mode){
                float g0 = g_G1[c0], g1 = g_G1[c0+1];
                float u0 = g_Ub[c0], u1 = g_Ub[c0+1];
                v00 = v00 - mk0*g0 + u0; v01 = v01 - mk0*g1 + u1;
                v10 = v10 - mk1*g0 + u0; v11 = v11 - mk1*g1 + u1;
            }
            *(float2*)(Cm + (size_t)r0*N + c0) = make_float2(v00, v01);
            *(float2*)(Cm + (size_t)r1*N + c0) = make_float2(v10, v11);
        }
    }
}

// ---------------- stats (warp-per-row, single pass K+V, 10 interleaved chains) ----------------
__global__ __launch_bounds__(512) void stats2(const float* __restrict__ gp_w, const float* __restrict__ gp_b)
{
    int r = blockIdx.x*16 + (threadIdx.x>>5);
    int lane = threadIdx.x & 31;
    float m0=g_cov[0], m1=g_cov[1], mb=g_cov[2];
    float Vbb=g_cov[5], C0b=g_cov[7], C1b=g_cov[8];
    float aK=0,aK2=0,a0=0,a1=0,ab=0;
    float bK=0,bK2=0,b0=0,b1=0,bb=0;
    #pragma unroll
    for (int k=0;k<8;k++){
        int d = k*32+lane;
        float g0 = gp_w[d]-m0, g1 = gp_w[D+d]-m1, gb = gp_b[d]-mb;
        float xk = g_K[(size_t)r*D + d];
        float xv = g_V[(size_t)r*D + d];
        aK+=xk; aK2=fmaf(xk,xk,aK2); a0=fmaf(xk,g0,a0); a1=fmaf(xk,g1,a1); ab=fmaf(xk,gb,ab);
        bK+=xv; bK2=fmaf(xv,xv,bK2); b0=fmaf(xv,g0,b0); b1=fmaf(xv,g1,b1); bb=fmaf(xv,gb,bb);
    }
    #pragma unroll
    for (int o=16;o;o>>=1){
        aK  += __shfl_xor_sync(0xffffffffu, aK,  o);
        aK2 += __shfl_xor_sync(0xffffffffu, aK2, o);
        a0  += __shfl_xor_sync(0xffffffffu, a0,  o);
        a1  += __shfl_xor_sync(0xffffffffu, a1,  o);
        ab  += __shfl_xor_sync(0xffffffffu, ab,  o);
        bK  += __shfl_xor_sync(0xffffffffu, bK,  o);
        bK2 += __shfl_xor_sync(0xffffffffu, bK2, o);
        b0  += __shfl_xor_sync(0xffffffffu, b0,  o);
        b1  += __shfl_xor_sync(0xffffffffu, b1,  o);
        bb  += __shfl_xor_sync(0xffffffffu, bb,  o);
    }
    if (lane == 0){
        float mk = aK*(1.f/D);
        float Vkk = aK2*(1.f/D) - mk*mk;
        g_statsK[r*4+0] = Vkk + Vbb + 2.f*(ab*(1.f/D) + C1b*0.f + ab*0.f) + 2.f*C1b*0.f;  // placeholder fixed below
        // recompute cleanly:
        float Ck0 = a0*(1.f/D), Ck1 = a1*(1.f/D), Ckb = ab*(1.f/D);
        g_statsK[r*4+0] = Vkk + Vbb + 2.f*Ckb;
        g_statsK[r*4+1] = 2.f*(Ck0 + C0b);
        g_statsK[r*4+2] = 2.f*(Ck1 + C1b);
        g_statsK[r*4+3] = 0.f;
        g_meanK[r] = mk;
        float mv = bK*(1.f/D);
        float Vvv = bK2*(1.f/D) - mv*mv;
        float Cv0 = b0*(1.f/D), Cv1 = b1*(1.f/D), Cvb = bb*(1.f/D);
        g_statsV[r*4+0] = Vvv + Vbb + 2.f*Cvb;
        g_statsV[r*4+1] = 2.f*(Cv0 + C0b);
        g_statsV[r*4+2] = 2.f*(Cv1 + C1b);
        g_statsV[r*4+3] = 0.f;
        g_meanV[r] = mv;
    }
}

// ---------------- per-slot q/wtil/scalars (1024 threads, single-pass LN) ----------------
__device__ __forceinline__ void slot_compute(
    int s, int t, const float* so,
    const float* __restrict__ ns_g, const float* __restrict__ ns_b,
    const float* __restrict__ wq,   const float* __restrict__ W2, const float* __restrict__ b2,
    float* sh, float* sq, float* qp, float* red)
{
    int w = t >> 5, lane = t & 31;
    float v = (t < 256) ? so[t] : 0.f;
    float s1 = v, s2 = v*v;
    #pragma unroll
    for (int o = 16; o; o >>= 1){
        s1 += __shfl_xor_sync(0xffffffffu, s1, o);
        s2 += __shfl_xor_sync(0xffffffffu, s2, o);
    }
    if (lane == 0 && t < 256){ red[w] = s1; red[w+8] = s2; }
    __syncthreads();
    float m = 0.f, e2 = 0.f;
    #pragma unroll
    for (int i=0;i<8;i++){ m += red[i]; e2 += red[i+8]; }
    m *= (1.f/D); e2 *= (1.f/D);
    float var = e2 - m*m;
    if (t < 256) sh[t] = (v - m) * rsqrtf(var + LNEPS) * ns_g[t] + ns_b[t];
    __syncthreads();

    {
        int cg = t & 63, ks = t >> 6;
        const float4* wq4 = (const float4*)wq;
        float4 a = make_float4(0.f,0.f,0.f,0.f);
        #pragma unroll 4
        for (int j = ks*16; j < ks*16 + 16; j++){
            float4 wv = __ldg(wq4 + j*64 + cg);
            float sv = sh[j];
            a.x = fmaf(sv, wv.x, a.x);
            a.y = fmaf(sv, wv.y, a.y);
            a.z = fmaf(sv, wv.z, a.z);
            a.w = fmaf(sv, wv.w, a.w);
        }
        *(float4*)(qp + ks*256 + cg*4) = a;
    }
    __syncthreads();
    if (t < 256){
        float vq = 0.f;
        #pragma unroll
        for (int ks=0; ks<16; ks++) vq += qp[ks*256 + t];
        sq[t] = vq;
    }
    __syncthreads();

    float p = (t < 256) ? sq[t]*b2[t] : 0.f;
    float ws = warpSum(p);
    __syncthreads();
    if (lane == 0 && t < 256) red[w] = ws;
    __syncthreads();

    float4 qa = *(const float4*)(sq + lane*8);
    float4 qb = *(const float4*)(sq + lane*8 + 4);
    #pragma unroll 2
    for (int k = 0; k < 16; k++){
        int j = (k << 5) + w;
        const float4* w2r = (const float4*)(W2 + j*D);
        float4 wa = __ldg(w2r + lane*2);
        float4 wb = __ldg(w2r + lane*2 + 1);
        float acc = wa.x*qa.x + wa.y*qa.y + wa.z*qa.z + wa.w*qa.w
                  + wb.x*qb.x + wb.y*qb.y + wb.z*qb.z + wb.w*qb.w;
        acc = warpSum(acc);
        if (lane == 0) g_slot[s*520 + j] = acc;
    }
    if (t == 0){
        float qb2 = 0.f;
        #pragma unroll
        for (int i=0;i<8;i++) qb2 += red[i];
        float px = fminf(fmaxf(g_Cond[s*260+256], -1.f), 1.f);
        float py = fminf(fmaxf(g_Cond[s*260+257], -1.f), 1.f);
        float sx = fminf(fmaxf(g_Cond[s*260+258], 1e-3f), 2.f);
        float sy = fminf(fmaxf(g_Cond[s*260+259], 1e-3f), 2.f);
        float* o = g_slot + s*520 + 512;
        o[0]=qb2; o[1]=px; o[2]=py; o[3]=1.f/(5.f*sx); o[4]=1.f/(5.f*sy);
    }
}

__global__ __launch_bounds__(1024) void slot0(const float* __restrict__ ns_g, const float* __restrict__ ns_b,
                                              const float* __restrict__ wq,   const float* __restrict__ W2,
                                              const float* __restrict__ b2)
{
    __shared__ float so[256], sh[256], sq[256], qp[4096], red[16];
    int s = blockIdx.x, t = threadIdx.x;
    if (t < 256) so[t] = g_Cond[s*260 + t];
    __syncthreads();
    slot_compute(s, t, so, ns_g, ns_b, wq, W2, b2, sh, sq, qp, red);
}

// ---------------- fused: dots + softmax + attn0 + partials (2-px ILP) ----------------
__global__ __launch_bounds__(256) void iter1_kernel(int last, float* __restrict__ out)
{
    int b = blockIdx.y, chunk = blockIdx.x;
    int t = threadIdx.x, w = t >> 5, lane = t & 31;
    __shared__ float sPk[16*512];
    __shared__ float sdots[NS][16];
    __shared__ float sscal[NS][5];

    float* attnDst = last ? (out + 16640) : g_attn0;
    float* relOut  = out + 16640 + 65536;
    int n0 = chunk*16;

    {
        const float4* src = (const float4*)(g_Pk + (((size_t)(b<<10) + n0)<<9));
        float4* dst = (float4*)sPk;
        #pragma unroll
        for (int i=0;i<8;i++) dst[t + i*256] = __ldg(src + t + i*256);
    }

    float4 u0v[4], u1v[4], wtv[4], cv[4];
    const float* wts = g_slot + (b*NS + w)*520;
    #pragma unroll
    for (int jj=0; jj<4; jj++){
        int j = jj*128 + lane*4;
        u0v[jj] = *(const float4*)(g_U0 + j);
        u1v[jj] = *(const float4*)(g_U1 + j);
        cv[jj]  = *(const float4*)(g_C  + j);
        wtv[jj] = *(const float4*)(wts  + j);
    }
    if (t < 40) sscal[t/5][t%5] = g_slot[(b*NS + t/5)*520 + 512 + (t%5)];
    __syncthreads();

    float qb2=sscal[w][0], px=sscal[w][1], py=sscal[w][2], i5x=sscal[w][3], i5y=sscal[w][4];
    float V00=g_cov[3], V11=g_cov[4], C01_2=2.f*g_cov[6];

    for (int pp=0; pp<16; pp+=2){
        int nA = n0 + pp, nB = nA + 1;
        float gxA = -1.f + (float)(nA>>5)*GSTEP, gyA = -1.f + (float)(nA&31)*GSTEP;
        float gxB = -1.f + (float)(nB>>5)*GSTEP, gyB = -1.f + (float)(nB&31)*GSTEP;
        float aA = (gxA-px)*i5x, cA = (gyA-py)*i5y;
        float aB = (gxB-px)*i5x, cB = (gyB-py)*i5y;
        const float4 stA = *(const float4*)(g_statsK + ((b<<10)+nA)*4);
        const float4 stB = *(const float4*)(g_statsK + ((b<<10)+nB)*4);
        float varA = stA.x + aA*stA.y + cA*stA.z + aA*aA*V00 + cA*cA*V11 + aA*cA*C01_2;
        float varB = stB.x + aB*stB.y + cB*stB.z + aB*aB*V00 + cB*cB*V11 + aB*cB*C01_2;
        float isA = rsqrtf(varA + LNEPS);
        float isB = rsqrtf(varB + LNEPS);
        const float* pkA = sPk + pp*512;
        const float* pkB = pkA + 512;
        float acA0=0.f, acA1=0.f, acB0=0.f, acB1=0.f;
        #pragma unroll
        for (int jj=0; jj<4; jj++){
            float4 p4A = *(const float4*)(pkA + jj*128 + lane*4);
            float4 p4B = *(const float4*)(pkB + jj*128 + lane*4);
            float eA0 = fmaf(isA, fmaf(cA,u1v[jj].x, fmaf(aA,u0v[jj].x, p4A.x)), cv[jj].x);
            float eB0 = fmaf(isB, fmaf(cB,u1v[jj].x, fmaf(aB,u0v[jj].x, p4B.x)), cv[jj].x);
            float eA1 = fmaf(isA, fmaf(cA,u1v[jj].y, fmaf(aA,u0v[jj].y, p4A.y)), cv[jj].y);
            float eB1 = fmaf(isB, fmaf(cB,u1v[jj].y, fmaf(aB,u0v[jj].y, p4B.y)), cv[jj].y);
            float eA2 = fmaf(isA, fmaf(cA,u1v[jj].z, fmaf(aA,u0v[jj].z, p4A.z)), cv[jj].z);
            float eB2 = fmaf(isB, fmaf(cB,u1v[jj].z, fmaf(aB,u0v[jj].z, p4B.z)), cv[jj].z);
            float eA3 = fmaf(isA, fmaf(cA,u1v[jj].w, fmaf(aA,u0v[jj].w, p4A.w)), cv[jj].w);
            float eB3 = fmaf(isB, fmaf(cB,u1v[jj].w, fmaf(aB,u0v[jj].w, p4B.w)), cv[jj].w);
            acA0 = fmaf(fmaxf(eA0,0.f), wtv[jj].x, acA0);
            acB0 = fmaf(fmaxf(eB0,0.f), wtv[jj].x, acB0);
            acA1 = fmaf(fmaxf(eA1,0.f), wtv[jj].y, acA1);
            acB1 = fmaf(fmaxf(eB1,0.f), wtv[jj].y, acB1);
            acA0 = fmaf(fmaxf(eA2,0.f), wtv[jj].z, acA0);
            acB0 = fmaf(fmaxf(eB2,0.f), wtv[jj].z, acB0);
            acA1 = fmaf(fmaxf(eA3,0.f), wtv[jj].w, acA1);
            acB1 = fmaf(fmaxf(eB3,0.f), wtv[jj].w, acB1);
        }
        float sA = acA0 + acA1, sB = acB0 + acB1;
        #pragma unroll
        for (int o=16;o;o>>=1){
            sA += __shfl_xor_sync(0xffffffffu, sA, o);
            sB += __shfl_xor_sync(0xffffffffu, sB, o);
        }
        if (lane == 0){
            sdots[w][pp]   = ATTN_SCALE * (sA + qb2);
            sdots[w][pp+1] = ATTN_SCALE * (sB + qb2);
            if (last){
                float2* rpA = (float2*)(relOut + ((((size_t)(b*NS+w)<<10)+nA)<<1));
                float2* rpB = (float2*)(relOut + ((((size_t)(b*NS+w)<<10)+nB)<<1));
                *rpA = make_float2(aA, cA);
                *rpB = make_float2(aB, cB);
            }
        }
    }
    __syncthreads();

    float a0 = 0.f, gx = 0.f, gy = 0.f;
    if (lane < 16){
        int n = n0 + lane;
        float dd[NS]; float mx = -1e30f;
        #pragma unroll
        for (int k=0;k<NS;k++){ dd[k] = sdots[k][lane]; mx = fmaxf(mx, dd[k]); }
        float sum = 0.f;
        #pragma unroll
        for (int k=0;k<NS;k++){ dd[k] = expf(dd[k]-mx); sum += dd[k]; }
        a0 = dd[w] / sum;
        attnDst[((b*NS+w)<<10) + n] = a0;
        gx = -1.f + (float)(n>>5)*GSTEP;
        gy = -1.f + (float)(n&31)*GSTEP;
    }
    float S0 = warpSum(a0);
    float Sx = warpSum(a0*gx);
    float Sy = warpSum(a0*gy);
    float Sxx = warpSum(a0*gx*gx);
    float Syy = warpSum(a0*gy*gy);
    if (lane == 0){
        float* pp = g_part + ((size_t)((b*NS+w)*64 + chunk))*8;
        pp[0]=S0; pp[1]=Sx; pp[2]=Sy; pp[3]=Sxx; pp[4]=Syy;
    }
}

// ---------------- slot-fused vacc + finalize ----------------
__global__ __launch_bounds__(512) void vaccF_kernel()
{
    int chunk = blockIdx.x;
    int b = blockIdx.y;
    int t = threadIdx.x;
    __shared__ float4 sC4[NS][64];
    __shared__ float sden[NS];

    int sl = t >> 6, p = t & 63;
    int n = chunk*64 + p;
    int gs = b*NS + sl;
    float rawA;
    {
        float px = g_slot[gs*520+513], py = g_slot[gs*520+514];
        float i5x= g_slot[gs*520+515], i5y= g_slot[gs*520+516];
        float gx = -1.f + (float)(n>>5)*GSTEP;
        float gy = -1.f + (float)(n&31)*GSTEP;
        float a = (gx-px)*i5x, c = (gy-py)*i5y;
        const float4 st = *(const float4*)(g_statsV + ((b<<10)+n)*4);
        float var = st.x + a*st.y + c*st.z + a*a*g_cov[3] + c*c*g_cov[4] + a*c*2.f*g_cov[6];
        float is = rsqrtf(var + LNEPS);
        rawA = g_attn0[(gs<<10)+n];
        sC4[sl][p] = make_float4(is, is*a, is*c, 0.f);
    }
    if (t < 256){
        int w = t >> 5, lane = t & 31;
        const float* pp0 = g_part + ((size_t)((b*NS+w)*64 + lane))*8;
        const float* pp1 = pp0 + 32*8;
        float S0 = warpSum(pp0[0] + pp1[0]);
        if (chunk == 0){
            float Sx = warpSum(pp0[1] + pp1[1]);
            float Sy = warpSum(pp0[2] + pp1[2]);
            float Sxx = warpSum(pp0[3] + pp1[3]);
            float Syy = warpSum(pp0[4] + pp1[4]);
            if (lane == 0){
                float px = Sx, py = Sy, G2 = g_cov[9];
                float vx = Sxx - 2.f*px*Sx + px*px*S0 + EPSA*(G2 + 1024.f*px*px);
                float vy = Syy - 2.f*py*Sy + py*py*S0 + EPSA*(G2 + 1024.f*py*py);
                float sx = fminf(fmaxf(sqrtf(fmaxf(vx,0.f)), 1e-3f), 2.f);
                float sy = fminf(fmaxf(sqrtf(fmaxf(vy,0.f)), 1e-3f), 2.f);
                int s2 = b*NS + w;
                g_Cond[s2*260+256]=px; g_Cond[s2*260+257]=py;
                g_Cond[s2*260+258]=sx; g_Cond[s2*260+259]=sy;
            }
        }
        if (lane == 0) sden[w] = 1.f/(S0 + 1024.f*EPSA);
    }
    __syncthreads();
    sC4[sl][p].w = (rawA + EPSA) * sden[sl];
    __syncthreads();

    float u0 = g_U0[t], u1 = g_U1[t], C = g_C[t];
    const float* pvb = g_Pv + ((((size_t)(b<<10)) + (size_t)chunk*64) << 9) + t;
    float acc[NS] = {};
    #pragma unroll 4
    for (int q=0; q<64; q++){
        float pv = __ldg(pvb + ((size_t)q << 9));
        #pragma unroll
        for (int s2=0; s2<NS; s2++){
            float4 cf = sC4[s2][q];
            float pre = fmaf(cf.y, u0, fmaf(cf.z, u1, fmaf(cf.x, pv, C)));
            acc[s2] = fmaf(fmaxf(pre, 0.f), cf.w, acc[s2]);
        }
    }
    #pragma unroll
    for (int s2=0; s2<NS; s2++)
        g_spart[((size_t)((b*NS+s2)*16 + chunk))*H + t] = acc[s2];
}

// ---------------- GRU update + slot prep for next iter ----------------
__global__ __launch_bounds__(1024) void updslot_kernel(
    const float* __restrict__ W2,  const float* __restrict__ b2,
    const float* __restrict__ Wih, const float* __restrict__ Whh,
    const float* __restrict__ bih, const float* __restrict__ bhh,
    const float* __restrict__ ns_g, const float* __restrict__ ns_b,
    const float* __restrict__ wq)
{
    __shared__ float ss[H], so[256], su[256], qp[4096], sgx[768], sgh[768], sh[256], sq[256], red[16];
    int s = blockIdx.x, t = threadIdx.x, w = t >> 5, lane = t & 31;

    if (t < 512){
        float r0 = 0.f;
        #pragma unroll
        for (int c=0; c<16; c++) r0 += g_spart[((size_t)(s*16 + c))*H + t];
        ss[t] = r0;
    }
    if (t < 256) so[t] = g_Cond[s*260 + t];
    __syncthreads();

    {
        int cg = t & 63, ks = t >> 6;
        const float4* W24 = (const float4*)W2;
        float4 a = make_float4(0.f,0.f,0.f,0.f);
        #pragma unroll 4
        for (int j = ks*32; j < ks*32 + 32; j++){
            float4 wv = __ldg(W24 + j*64 + cg);
            float sv = ss[j];
            a.x = fmaf(sv, wv.x, a.x);
            a.y = fmaf(sv, wv.y, a.y);
            a.z = fmaf(sv, wv.z, a.z);
            a.w = fmaf(sv, wv.w, a.w);
        }
        *(float4*)(qp + ks*256 + cg*4) = a;
    }
    __syncthreads();
    if (t < 256){
        float u = b2[t];
        #pragma unroll
        for (int ks=0; ks<16; ks++) u += qp[ks*256 + t];
        su[t] = u;
    }
    __syncthreads();

    {
        float4 sua = *(const float4*)(su + lane*8);
        float4 sub = *(const float4*)(su + lane*8 + 4);
        float4 soa = *(const float4*)(so + lane*8);
        float4 sob = *(const float4*)(so + lane*8 + 4);
        #pragma unroll 2
        for (int k = 0; k < 24; k++){
            int i = (k << 5) + w;
            const float4* wi4 = (const float4*)(Wih + i*D);
            const float4* wh4 = (const float4*)(Whh + i*D);
            float4 wa = __ldg(wi4 + lane*2);
            float4 wb = __ldg(wi4 + lane*2 + 1);
            float4 ha = __ldg(wh4 + lane*2);
            float4 hb = __ldg(wh4 + lane*2 + 1);
            float ax = wa.x*sua.x + wa.y*sua.y + wa.z*sua.z + wa.w*sua.w
                     + wb.x*sub.x + wb.y*sub.y + wb.z*sub.z + wb.w*sub.w;
            float ah = ha.x*soa.x + ha.y*soa.y + ha.z*soa.z + ha.w*soa.w
                     + hb.x*sob.x + hb.y*sob.y + hb.z*sob.z + hb.w*sob.w;
            #pragma unroll
            for (int o=16;o;o>>=1){
                ax += __shfl_xor_sync(0xffffffffu, ax, o);
                ah += __shfl_xor_sync(0xffffffffu, ah, o);
            }
            if (lane == 0){ sgx[i] = ax + bih[i]; sgh[i] = ah + bhh[i]; }
        }
    }
    __syncthreads();

    if (t < 256){
        float r = 1.f/(1.f + expf(-(sgx[t]     + sgh[t])));
        float z = 1.f/(1.f + expf(-(sgx[256+t] + sgh[256+t])));
        float nn = tanhf(sgx[512+t] + r*sgh[512+t]);
        float nv = (1.f - z)*nn + z*so[t];
        g_Cond[s*260 + t] = nv;
        so[t] = nv;
    }
    __syncthreads();

    slot_compute(s, t, so, ns_g, ns_b, wq, W2, b2, sh, sq, qp, red);
}

// ---------------- final: pos/scl + write conditioning to out ----------------
__global__ void finz3_kernel(float* __restrict__ out)
{
    __shared__ float sres[4];
    int s = blockIdx.x, t = threadIdx.x;
    if (t < 32){
        const float* pp0 = g_part + ((size_t)(s*64 + t))*8;
        const float* pp1 = pp0 + 32*8;
        float S0 = warpSum(pp0[0] + pp1[0]);
        float Sx = warpSum(pp0[1] + pp1[1]);
        float Sy = warpSum(pp0[2] + pp1[2]);
        float Sxx = warpSum(pp0[3] + pp1[3]);
        float Syy = warpSum(pp0[4] + pp1[4]);
        if (t == 0){
            float px = Sx, py = Sy, G2 = g_cov[9];
            float vx = Sxx - 2.f*px*Sx + px*px*S0 + EPSA*(G2 + 1024.f*px*px);
            float vy = Syy - 2.f*py*Sy + py*py*S0 + EPSA*(G2 + 1024.f*py*py);
            float sx = fminf(fmaxf(sqrtf(fmaxf(vx,0.f)), 1e-3f), 2.f);
            float sy = fminf(fmaxf(sqrtf(fmaxf(vy,0.f)), 1e-3f), 2.f);
            sres[0]=px; sres[1]=py; sres[2]=sx; sres[3]=sy;
        }
    }
    __syncthreads();
    for (int i = t; i < 260; i += 256)
        out[s*260 + i] = (i < 256) ? g_Cond[s*260 + i] : sres[i - 256];
}

// ---------------- launch ----------------
extern "C" void kernel_launch(void* const* d_in, const int* in_sizes, int n_in,
                              void* d_out, int out_size)
{
    const float* inputs = (const float*)d_in[0];
    const float* cond   = (const float*)d_in[1];
    const float* ni_g   = (const float*)d_in[2];
    const float* ni_b   = (const float*)d_in[3];
    const float* ns_g   = (const float*)d_in[4];
    const float* ns_b   = (const float*)d_in[5];
    const float* wq     = (const float*)d_in[6];
    const float* wk     = (const float*)d_in[7];
    const float* wv     = (const float*)d_in[8];
    const float* gp_w   = (const float*)d_in[9];
    const float* gp_b   = (const float*)d_in[10];
    const float* ge_ln_g= (const float*)d_in[11];
    const float* ge_ln_b= (const float*)d_in[12];
    const float* ge_w1  = (const float*)d_in[13];
    const float* ge_b1  = (const float*)d_in[14];
    const float* ge_w2  = (const float*)d_in[15];
    const float* ge_b2  = (const float*)d_in[16];
    const float* gru_wih= (const float*)d_in[17];
    const float* gru_whh= (const float*)d_in[18];
    const float* gru_bih= (const float*)d_in[19];
    const float* gru_bhh= (const float*)d_in[20];
    float* out = (float*)d_out;

    static int s_attr = 0;
    if (!s_attr){
        cudaFuncSetAttribute(gemmT, cudaFuncAttributeMaxDynamicSharedMemorySize, 61440);
        s_attr = 1;
    }

    pre_kernel<<<610, 512>>>(gp_w, gp_b, ge_ln_g, ge_ln_b, ge_w1, ge_b1, cond, inputs, wk, wv);
    gemmT<<<dim3(4,64,2), 256, 61440>>>(0, inputs, ni_g, ni_b, 256);
    stats2<<<512, 512>>>(gp_w, gp_b);
    gemmT<<<dim3(8,64,2), 256, 30720>>>(2, nullptr, nullptr, nullptr, 512);
    slot0<<<64, 1024>>>(ns_g, ns_b, wq, ge_w2, ge_b2);

    for (int it = 0; it < 3; it++) {
        iter1_kernel<<<dim3(64,8), 256>>>(0, out);
        vaccF_kernel<<<dim3(16,8), 512>>>();
        updslot_kernel<<<64, 1024>>>(ge_w2, ge_b2, gru_wih, gru_whh, gru_bih, gru_bhh,
                                     ns_g, ns_b, wq);
    }
    iter1_kernel<<<dim3(64,8), 256>>>(1, out);
    finz3_kernel<<<64, 256>>>(out);
}

// round 17
// speedup vs baseline: 1.9123x; 1.1205x over previous
#include <cuda_runtime.h>
#include <math.h>
#include <stdint.h>

// ---------------- problem constants ----------------
#define NB 8
#define NPIX 1024
#define NS 8
#define D 256
#define H 512
#define NROWS (NB*NPIX)
#define EPSA 1e-8f
#define LNEPS 1e-5f
#define ATTN_SCALE 0.0625f
#define GSTEP (2.0f/31.0f)

// ---------------- scratch ----------------
__device__ __align__(16) float g_K [NROWS*D];
__device__ __align__(16) float g_V [NROWS*D];
__device__ __align__(16) float g_Pk[NROWS*H];
__device__ __align__(16) float g_Pv[NROWS*H];
__device__ __align__(16) float g_statsK[NROWS*4];
__device__ __align__(16) float g_statsV[NROWS*4];
__device__ float g_meanK[NROWS];
__device__ float g_meanV[NROWS];
__device__ float g_lnM[NROWS];
__device__ float g_lnIS[NROWS];
__device__ __align__(16) float g_U0[H];
__device__ __align__(16) float g_U1[H];
__device__ __align__(16) float g_Ub[H];
__device__ __align__(16) float g_C[H];
__device__ __align__(16) float g_G1[H];
__device__ float g_cov[16];
__device__ float g_Cond[NB*NS*260];
__device__ __align__(16) float g_slot[NB*NS*520];
__device__ float g_attn0[NB*NS*NPIX];
__device__ float g_part[NB*NS*64*8];
__device__ float g_spart[NB*NS*16*H];
// transposed + tf32-split weights (n-major: [n][k])
__device__ __align__(16) uint32_t g_WkTh[65536], g_WkTl[65536];
__device__ __align__(16) uint32_t g_WvTh[65536], g_WvTl[65536];
__device__ __align__(16) uint32_t g_W1Th[131072], g_W1Tl[131072];

__device__ __forceinline__ float warpSum(float v) {
    #pragma unroll
    for (int o = 16; o; o >>= 1) v += __shfl_xor_sync(0xffffffffu, v, o);
    return v;
}

__device__ __forceinline__ void tf32split(float x, uint32_t& h, uint32_t& l){
    uint32_t hb; asm("cvt.rna.tf32.f32 %0, %1;" : "=r"(hb) : "f"(x));
    float lo = x - __uint_as_float(hb);
    uint32_t lb; asm("cvt.rna.tf32.f32 %0, %1;" : "=r"(lb) : "f"(lo));
    h = hb; l = lb;
}

__device__ __forceinline__ uint32_t tf32cvt(float x){
    uint32_t hb; asm("cvt.rna.tf32.f32 %0, %1;" : "=r"(hb) : "f"(x));
    return hb;
}

__device__ __forceinline__ void mma_tf32(float* d, const uint32_t* a, const uint32_t* b){
    asm volatile("mma.sync.aligned.m16n8k8.row.col.f32.tf32.tf32.f32 "
        "{%0,%1,%2,%3}, {%4,%5,%6,%7}, {%8,%9}, {%0,%1,%2,%3};"
        : "+f"(d[0]), "+f"(d[1]), "+f"(d[2]), "+f"(d[3])
        : "r"(a[0]), "r"(a[1]), "r"(a[2]), "r"(a[3]), "r"(b[0]), "r"(b[1]));
}

// ---------------- pre: constants + cond copy + LN row stats + tiled weight transpose/split ----------------
__global__ __launch_bounds__(512) void pre_kernel(
    const float* __restrict__ gp_w, const float* __restrict__ gp_b,
    const float* __restrict__ lg,   const float* __restrict__ lb,
    const float* __restrict__ W1,   const float* __restrict__ b1,
    const float* __restrict__ cond, const float* __restrict__ inputs,
    const float* __restrict__ wk,   const float* __restrict__ wv)
{
    int bid = blockIdx.x;
    int t = threadIdx.x;
    if (bid >= 546){
        __shared__ float tile[64][65];
        int tt = bid - 546;
        const float* src; uint32_t *dsth, *dstl;
        int K0, N0, srcN; int foldLg = 0;
        if (tt < 16){ src = wk; dsth = g_WkTh; dstl = g_WkTl;
                      K0 = (tt>>2)*64; N0 = (tt&3)*64; srcN = 256; }
        else if (tt < 32){ tt -= 16; src = wv; dsth = g_WvTh; dstl = g_WvTl;
                      K0 = (tt>>2)*64; N0 = (tt&3)*64; srcN = 256; }
        else { tt -= 32; src = W1; dsth = g_W1Th; dstl = g_W1Tl;
                      K0 = (tt>>3)*64; N0 = (tt&7)*64; srcN = 512; foldLg = 1; }
        #pragma unroll
        for (int i = t; i < 4096; i += 512){
            int kk = i >> 6, nn = i & 63;
            float v = src[(size_t)(K0+kk)*srcN + N0+nn];
            if (foldLg) v *= lg[K0+kk];
            tile[kk][nn] = v;
        }
        __syncthreads();
        #pragma unroll
        for (int i = t; i < 4096; i += 512){
            int nn = i >> 6, kk = i & 63;
            uint32_t h, l; tf32split(tile[kk][nn], h, l);
            dsth[(size_t)(N0+nn)*256 + K0+kk] = h;
            dstl[(size_t)(N0+nn)*256 + K0+kk] = l;
        }
        return;
    }
    if (bid >= 34) {
        int r = (bid - 34)*16 + (t>>5);
        int lane = t & 31;
        const float* row = inputs + (size_t)r*D;
        float v[8]; float s1 = 0.f, s2 = 0.f;
        #pragma unroll
        for (int k=0;k<8;k++){ v[k]=row[k*32+lane]; s1+=v[k]; s2=fmaf(v[k],v[k],s2); }
        #pragma unroll
        for (int o = 16; o; o >>= 1){
            s1 += __shfl_xor_sync(0xffffffffu, s1, o);
            s2 += __shfl_xor_sync(0xffffffffu, s2, o);
        }
        float m = s1 * (1.f/D);
        float var = s2 * (1.f/D) - m*m;
        float is = rsqrtf(var + LNEPS);
        if (lane == 0){ g_lnM[r]=m; g_lnIS[r]=is; }
        return;
    }
    if (bid > 0) {
        int i = (bid - 1)*512 + t;
        if (i < NB*NS*260) g_Cond[i] = cond[i];
        return;
    }
    __shared__ float sg0[D], sg1[D], sgb[D], slg[D], slb[D];
    __shared__ float sm[4];
    if (t < D) { sg0[t]=gp_w[t]; sg1[t]=gp_w[D+t]; sgb[t]=gp_b[t]; slg[t]=lg[t]; slb[t]=lb[t]; }
    __syncthreads();
    if (t == 0) {
        float m0=0,m1=0,mb=0;
        for (int d=0; d<D; d++){ m0+=sg0[d]; m1+=sg1[d]; mb+=sgb[d]; }
        m0*=(1.f/D); m1*=(1.f/D); mb*=(1.f/D);
        float V00=0,V11=0,Vbb=0,C01=0,C0b=0,C1b=0;
        for (int d=0; d<D; d++){
            float a=sg0[d]-m0, b_=sg1[d]-m1, c=sgb[d]-mb;
            V00+=a*a; V11+=b_*b_; Vbb+=c*c; C01+=a*b_; C0b+=a*c; C1b+=b_*c;
        }
        g_cov[0]=m0; g_cov[1]=m1; g_cov[2]=mb;
        g_cov[3]=V00/D; g_cov[4]=V11/D; g_cov[5]=Vbb/D;
        g_cov[6]=C01/D; g_cov[7]=C0b/D; g_cov[8]=C1b/D;
        float s2=0;
        for (int i=0;i<32;i++){ float x=-1.f + i*GSTEP; s2+=x*x; }
        g_cov[9]=s2*32.f;
        sm[0]=m0; sm[1]=m1; sm[2]=mb;
    }
    __syncthreads();
    float m0=sm[0], m1=sm[1], mb=sm[2];
    float U0=0,U1=0,Ub=0,Cc=0,G1=0;
    for (int d=0; d<D; d++){
        float w = W1[d*H + t];
        float gd = slg[d];
        U0 = fmaf((sg0[d]-m0)*gd, w, U0);
        U1 = fmaf((sg1[d]-m1)*gd, w, U1);
        Ub = fmaf((sgb[d]-mb)*gd, w, Ub);
        Cc = fmaf(slb[d], w, Cc);
        G1 = fmaf(gd, w, G1);
    }
    g_U0[t]=U0; g_U1[t]=U1; g_Ub[t]=Ub; g_C[t]=Cc + b1[t]; g_G1[t]=G1;
}

// ---------------- gemmT0: mode-0 (LN(inputs)@wk/@wv), 2-term tf32 split ----------------
// dyn smem: 2 bufs x (Ah 2560 + Bh 1280 + Al 2560) = 51200 B
__global__ __launch_bounds__(256,2) void gemmT0(const float* __restrict__ A0,
                                                const float* __restrict__ sgv,
                                                const float* __restrict__ sbv)
{
    extern __shared__ uint32_t dsm[];
    const int N = 256;
    int z = blockIdx.z;
    const uint32_t* BTh = z ? g_WvTh : g_WkTh;
    float* Cm = z ? g_V : g_K;

    __shared__ float SG[256], SB[256];
    const int bufStride = 6400;

    int bm = blockIdx.y*128, bn = blockIdx.x*64;
    int tid = threadIdx.x, lane = tid & 31, wrp = tid >> 5;
    int wm = wrp & 3, wn = wrp >> 2;
    int qr = lane >> 2, ql = lane & 3;

    SG[tid] = sgv[tid]; SB[tid] = sbv[tid];

    int arow = tid >> 1, akoff = (tid & 1) * 8;
    int brow = tid >> 2, bkoff = (tid & 3) * 4;
    float rm = g_lnM[bm+arow], ris = g_lnIS[bm+arow];
    __syncthreads();

    float acc[2][4][4] = {};
    const float* aptr = A0 + (size_t)(bm+arow)*256 + akoff;
    const uint32_t* bhp = BTh + (size_t)(bn+brow)*256 + bkoff;

    float4 pa0 = *(const float4*)aptr;
    float4 pa1 = *(const float4*)(aptr + 4);
    uint4 pbh = *(const uint4*)bhp;

    {
        uint32_t* Ah = dsm;
        uint32_t* Bh = dsm + 2560;
        uint32_t* Al = dsm + 3840;
        float av[8] = {pa0.x,pa0.y,pa0.z,pa0.w,pa1.x,pa1.y,pa1.z,pa1.w};
        uint32_t ahv[8], alv[8];
        #pragma unroll
        for (int i=0;i<8;i++){
            av[i] = fmaf((av[i]-rm)*ris, SG[akoff+i], SB[akoff+i]);
            tf32split(av[i], ahv[i], alv[i]);
        }
        *(uint4*)&Ah[arow*20 + akoff]     = make_uint4(ahv[0],ahv[1],ahv[2],ahv[3]);
        *(uint4*)&Ah[arow*20 + akoff + 4] = make_uint4(ahv[4],ahv[5],ahv[6],ahv[7]);
        *(uint4*)&Al[arow*20 + akoff]     = make_uint4(alv[0],alv[1],alv[2],alv[3]);
        *(uint4*)&Al[arow*20 + akoff + 4] = make_uint4(alv[4],alv[5],alv[6],alv[7]);
        *(uint4*)&Bh[brow*20 + bkoff] = pbh;
    }
    __syncthreads();

    int buf = 0;
    #pragma unroll 1
    for (int kc = 0; kc < 16; kc++){
        if (kc < 15){
            pa0 = *(const float4*)(aptr + kc*16 + 16);
            pa1 = *(const float4*)(aptr + kc*16 + 20);
            pbh = *(const uint4*)(bhp + kc*16 + 16);
        }
        {
            const uint32_t* Ah = dsm + buf*bufStride;
            const uint32_t* Bh = Ah + 2560;
            const uint32_t* Al = Ah + 3840;
            #pragma unroll
            for (int kk = 0; kk < 16; kk += 8){
                uint32_t ah[2][4], al[2][4];
                #pragma unroll
                for (int mi=0; mi<2; mi++){
                    int r = wm*32 + mi*16 + qr;
                    ah[mi][0] = Ah[r*20 + kk + ql];
                    ah[mi][1] = Ah[(r+8)*20 + kk + ql];
                    ah[mi][2] = Ah[r*20 + kk + ql + 4];
                    ah[mi][3] = Ah[(r+8)*20 + kk + ql + 4];
                    al[mi][0] = Al[r*20 + kk + ql];
                    al[mi][1] = Al[(r+8)*20 + kk + ql];
                    al[mi][2] = Al[r*20 + kk + ql + 4];
                    al[mi][3] = Al[(r+8)*20 + kk + ql + 4];
                }
                #pragma unroll
                for (int nj=0; nj<4; nj++){
                    int n = wn*32 + nj*8 + qr;
                    uint32_t bhv[2] = { Bh[n*20 + kk + ql], Bh[n*20 + kk + ql + 4] };
                    #pragma unroll
                    for (int mi=0; mi<2; mi++){
                        mma_tf32(acc[mi][nj], al[mi], bhv);
                        mma_tf32(acc[mi][nj], ah[mi], bhv);
                    }
                }
            }
        }
        if (kc < 15){
            int nb = buf ^ 1;
            uint32_t* Ah = dsm + nb*bufStride;
            uint32_t* Bh = Ah + 2560;
            uint32_t* Al = Ah + 3840;
            float av[8] = {pa0.x,pa0.y,pa0.z,pa0.w,pa1.x,pa1.y,pa1.z,pa1.w};
            uint32_t ahv[8], alv[8];
            int kb = (kc+1)*16 + akoff;
            #pragma unroll
            for (int i=0;i<8;i++){
                av[i] = fmaf((av[i]-rm)*ris, SG[kb+i], SB[kb+i]);
                tf32split(av[i], ahv[i], alv[i]);
            }
            *(uint4*)&Ah[arow*20 + akoff]     = make_uint4(ahv[0],ahv[1],ahv[2],ahv[3]);
            *(uint4*)&Ah[arow*20 + akoff + 4] = make_uint4(ahv[4],ahv[5],ahv[6],ahv[7]);
            *(uint4*)&Al[arow*20 + akoff]     = make_uint4(alv[0],alv[1],alv[2],alv[3]);
            *(uint4*)&Al[arow*20 + akoff + 4] = make_uint4(alv[4],alv[5],alv[6],alv[7]);
            *(uint4*)&Bh[brow*20 + bkoff] = pbh;
            __syncthreads();
            buf = nb;
        }
    }
    #pragma unroll
    for (int mi=0; mi<2; mi++){
        int r0 = bm + wm*32 + mi*16 + qr;
        int r1 = r0 + 8;
        #pragma unroll
        for (int nj=0; nj<4; nj++){
            int c0 = bn + wn*32 + nj*8 + ql*2;
            *(float2*)(Cm + (size_t)r0*N + c0) = make_float2(acc[mi][nj][0], acc[mi][nj][1]);
            *(float2*)(Cm + (size_t)r1*N + c0) = make_float2(acc[mi][nj][2], acc[mi][nj][3]);
        }
    }
}

// ---------------- gemmT2: mode-2 (K/V @ W1T), pure tf32, 3 CTAs/SM ----------------
// dyn smem: 2 bufs x (Ah 2560 + Bh 1280) = 30720 B
__global__ __launch_bounds__(256,3) void gemmT2()
{
    extern __shared__ uint32_t dsm[];
    const int N = 512;
    int z = blockIdx.z;
    const float* A = z ? g_V : g_K;
    const uint32_t* BTh = g_W1Th;
    float* Cm = z ? g_Pv : g_Pk;
    const float* meanV = z ? g_meanV : g_meanK;

    const int bufStride = 3840;

    int bm = blockIdx.y*128, bn = blockIdx.x*64;
    int tid = threadIdx.x, lane = tid & 31, wrp = tid >> 5;
    int wm = wrp & 3, wn = wrp >> 2;
    int qr = lane >> 2, ql = lane & 3;

    int arow = tid >> 1, akoff = (tid & 1) * 8;
    int brow = tid >> 2, bkoff = (tid & 3) * 4;

    float acc[2][4][4] = {};
    const float* aptr = A + (size_t)(bm+arow)*256 + akoff;
    const uint32_t* bhp = BTh + (size_t)(bn+brow)*256 + bkoff;

    float4 pa0 = *(const float4*)aptr;
    float4 pa1 = *(const float4*)(aptr + 4);
    uint4 pbh = *(const uint4*)bhp;

    {
        uint32_t* Ah = dsm;
        uint32_t* Bh = dsm + 2560;
        uint32_t ahv[8];
        ahv[0]=tf32cvt(pa0.x); ahv[1]=tf32cvt(pa0.y); ahv[2]=tf32cvt(pa0.z); ahv[3]=tf32cvt(pa0.w);
        ahv[4]=tf32cvt(pa1.x); ahv[5]=tf32cvt(pa1.y); ahv[6]=tf32cvt(pa1.z); ahv[7]=tf32cvt(pa1.w);
        *(uint4*)&Ah[arow*20 + akoff]     = make_uint4(ahv[0],ahv[1],ahv[2],ahv[3]);
        *(uint4*)&Ah[arow*20 + akoff + 4] = make_uint4(ahv[4],ahv[5],ahv[6],ahv[7]);
        *(uint4*)&Bh[brow*20 + bkoff] = pbh;
    }
    __syncthreads();

    int buf = 0;
    #pragma unroll 1
    for (int kc = 0; kc < 16; kc++){
        if (kc < 15){
            pa0 = *(const float4*)(aptr + kc*16 + 16);
            pa1 = *(const float4*)(aptr + kc*16 + 20);
            pbh = *(const uint4*)(bhp + kc*16 + 16);
        }
        {
            const uint32_t* Ah = dsm + buf*bufStride;
            const uint32_t* Bh = Ah + 2560;
            #pragma unroll
            for (int kk = 0; kk < 16; kk += 8){
                uint32_t ah[2][4];
                #pragma unroll
                for (int mi=0; mi<2; mi++){
                    int r = wm*32 + mi*16 + qr;
                    ah[mi][0] = Ah[r*20 + kk + ql];
                    ah[mi][1] = Ah[(r+8)*20 + kk + ql];
                    ah[mi][2] = Ah[r*20 + kk + ql + 4];
                    ah[mi][3] = Ah[(r+8)*20 + kk + ql + 4];
                }
                #pragma unroll
                for (int nj=0; nj<4; nj++){
                    int n = wn*32 + nj*8 + qr;
                    uint32_t bhv[2] = { Bh[n*20 + kk + ql], Bh[n*20 + kk + ql + 4] };
                    #pragma unroll
                    for (int mi=0; mi<2; mi++)
                        mma_tf32(acc[mi][nj], ah[mi], bhv);
                }
            }
        }
        if (kc < 15){
            int nb = buf ^ 1;
            uint32_t* Ah = dsm + nb*bufStride;
            uint32_t* Bh = Ah + 2560;
            uint32_t ahv[8];
            ahv[0]=tf32cvt(pa0.x); ahv[1]=tf32cvt(pa0.y); ahv[2]=tf32cvt(pa0.z); ahv[3]=tf32cvt(pa0.w);
            ahv[4]=tf32cvt(pa1.x); ahv[5]=tf32cvt(pa1.y); ahv[6]=tf32cvt(pa1.z); ahv[7]=tf32cvt(pa1.w);
            *(uint4*)&Ah[arow*20 + akoff]     = make_uint4(ahv[0],ahv[1],ahv[2],ahv[3]);
            *(uint4*)&Ah[arow*20 + akoff + 4] = make_uint4(ahv[4],ahv[5],ahv[6],ahv[7]);
            *(uint4*)&Bh[brow*20 + bkoff] = pbh;
            __syncthreads();
            buf = nb;
        }
    }
    #pragma unroll
    for (int mi=0; mi<2; mi++){
        int r0 = bm + wm*32 + mi*16 + qr;
        int r1 = r0 + 8;
        float mk0 = __ldg(meanV + r0), mk1 = __ldg(meanV + r1);
        #pragma unroll
        for (int nj=0; nj<4; nj++){
            int c0 = bn + wn*32 + nj*8 + ql*2;
            float g0 = g_G1[c0], g1 = g_G1[c0+1];
            float u0 = g_Ub[c0], u1 = g_Ub[c0+1];
            float v00 = acc[mi][nj][0] - mk0*g0 + u0;
            float v01 = acc[mi][nj][1] - mk0*g1 + u1;
            float v10 = acc[mi][nj][2] - mk1*g0 + u0;
            float v11 = acc[mi][nj][3] - mk1*g1 + u1;
            *(float2*)(Cm + (size_t)r0*N + c0) = make_float2(v00, v01);
            *(float2*)(Cm + (size_t)r1*N + c0) = make_float2(v10, v11);
        }
    }
}

// ---------------- stats (warp-per-row, single pass K+V) ----------------
__global__ __launch_bounds__(512) void stats2(const float* __restrict__ gp_w, const float* __restrict__ gp_b)
{
    int r = blockIdx.x*16 + (threadIdx.x>>5);
    int lane = threadIdx.x & 31;
    float m0=g_cov[0], m1=g_cov[1], mb=g_cov[2];
    float Vbb=g_cov[5], C0b=g_cov[7], C1b=g_cov[8];
    float aK=0,aK2=0,a0=0,a1=0,ab=0;
    float bK=0,bK2=0,b0=0,b1=0,bb=0;
    #pragma unroll
    for (int k=0;k<8;k++){
        int d = k*32+lane;
        float g0 = gp_w[d]-m0, g1 = gp_w[D+d]-m1, gb = gp_b[d]-mb;
        float xk = g_K[(size_t)r*D + d];
        float xv = g_V[(size_t)r*D + d];
        aK+=xk; aK2=fmaf(xk,xk,aK2); a0=fmaf(xk,g0,a0); a1=fmaf(xk,g1,a1); ab=fmaf(xk,gb,ab);
        bK+=xv; bK2=fmaf(xv,xv,bK2); b0=fmaf(xv,g0,b0); b1=fmaf(xv,g1,b1); bb=fmaf(xv,gb,bb);
    }
    #pragma unroll
    for (int o=16;o;o>>=1){
        aK  += __shfl_xor_sync(0xffffffffu, aK,  o);
        aK2 += __shfl_xor_sync(0xffffffffu, aK2, o);
        a0  += __shfl_xor_sync(0xffffffffu, a0,  o);
        a1  += __shfl_xor_sync(0xffffffffu, a1,  o);
        ab  += __shfl_xor_sync(0xffffffffu, ab,  o);
        bK  += __shfl_xor_sync(0xffffffffu, bK,  o);
        bK2 += __shfl_xor_sync(0xffffffffu, bK2, o);
        b0  += __shfl_xor_sync(0xffffffffu, b0,  o);
        b1  += __shfl_xor_sync(0xffffffffu, b1,  o);
        bb  += __shfl_xor_sync(0xffffffffu, bb,  o);
    }
    if (lane == 0){
        float mk = aK*(1.f/D);
        float Vkk = aK2*(1.f/D) - mk*mk;
        float Ck0 = a0*(1.f/D), Ck1 = a1*(1.f/D), Ckb = ab*(1.f/D);
        g_statsK[r*4+0] = Vkk + Vbb + 2.f*Ckb;
        g_statsK[r*4+1] = 2.f*(Ck0 + C0b);
        g_statsK[r*4+2] = 2.f*(Ck1 + C1b);
        g_statsK[r*4+3] = 0.f;
        g_meanK[r] = mk;
        float mv = bK*(1.f/D);
        float Vvv = bK2*(1.f/D) - mv*mv;
        float Cv0 = b0*(1.f/D), Cv1 = b1*(1.f/D), Cvb = bb*(1.f/D);
        g_statsV[r*4+0] = Vvv + Vbb + 2.f*Cvb;
        g_statsV[r*4+1] = 2.f*(Cv0 + C0b);
        g_statsV[r*4+2] = 2.f*(Cv1 + C1b);
        g_statsV[r*4+3] = 0.f;
        g_meanV[r] = mv;
    }
}

// ---------------- per-slot q/wtil/scalars (1024 threads, single-pass LN) ----------------
__device__ __forceinline__ void slot_compute(
    int s, int t, const float* so,
    const float* __restrict__ ns_g, const float* __restrict__ ns_b,
    const float* __restrict__ wq,   const float* __restrict__ W2, const float* __restrict__ b2,
    float* sh, float* sq, float* qp, float* red)
{
    int w = t >> 5, lane = t & 31;
    float v = (t < 256) ? so[t] : 0.f;
    float s1 = v, s2 = v*v;
    #pragma unroll
    for (int o = 16; o; o >>= 1){
        s1 += __shfl_xor_sync(0xffffffffu, s1, o);
        s2 += __shfl_xor_sync(0xffffffffu, s2, o);
    }
    if (lane == 0 && t < 256){ red[w] = s1; red[w+8] = s2; }
    __syncthreads();
    float m = 0.f, e2 = 0.f;
    #pragma unroll
    for (int i=0;i<8;i++){ m += red[i]; e2 += red[i+8]; }
    m *= (1.f/D); e2 *= (1.f/D);
    float var = e2 - m*m;
    if (t < 256) sh[t] = (v - m) * rsqrtf(var + LNEPS) * ns_g[t] + ns_b[t];
    __syncthreads();

    {
        int cg = t & 63, ks = t >> 6;
        const float4* wq4 = (const float4*)wq;
        float4 a = make_float4(0.f,0.f,0.f,0.f);
        #pragma unroll 4
        for (int j = ks*16; j < ks*16 + 16; j++){
            float4 wv = __ldg(wq4 + j*64 + cg);
            float sv = sh[j];
            a.x = fmaf(sv, wv.x, a.x);
            a.y = fmaf(sv, wv.y, a.y);
            a.z = fmaf(sv, wv.z, a.z);
            a.w = fmaf(sv, wv.w, a.w);
        }
        *(float4*)(qp + ks*256 + cg*4) = a;
    }
    __syncthreads();
    if (t < 256){
        float vq = 0.f;
        #pragma unroll
        for (int ks=0; ks<16; ks++) vq += qp[ks*256 + t];
        sq[t] = vq;
    }
    __syncthreads();

    float p = (t < 256) ? sq[t]*b2[t] : 0.f;
    float ws = warpSum(p);
    __syncthreads();
    if (lane == 0 && t < 256) red[w] = ws;
    __syncthreads();

    float4 qa = *(const float4*)(sq + lane*8);
    float4 qb = *(const float4*)(sq + lane*8 + 4);
    #pragma unroll 2
    for (int k = 0; k < 16; k++){
        int j = (k << 5) + w;
        const float4* w2r = (const float4*)(W2 + j*D);
        float4 wa = __ldg(w2r + lane*2);
        float4 wb = __ldg(w2r + lane*2 + 1);
        float acc = wa.x*qa.x + wa.y*qa.y + wa.z*qa.z + wa.w*qa.w
                  + wb.x*qb.x + wb.y*qb.y + wb.z*qb.z + wb.w*qb.w;
        acc = warpSum(acc);
        if (lane == 0) g_slot[s*520 + j] = acc;
    }
    if (t == 0){
        float qb2 = 0.f;
        #pragma unroll
        for (int i=0;i<8;i++) qb2 += red[i];
        float px = fminf(fmaxf(g_Cond[s*260+256], -1.f), 1.f);
        float py = fminf(fmaxf(g_Cond[s*260+257], -1.f), 1.f);
        float sx = fminf(fmaxf(g_Cond[s*260+258], 1e-3f), 2.f);
        float sy = fminf(fmaxf(g_Cond[s*260+259], 1e-3f), 2.f);
        float* o = g_slot + s*520 + 512;
        o[0]=qb2; o[1]=px; o[2]=py; o[3]=1.f/(5.f*sx); o[4]=1.f/(5.f*sy);
    }
}

__global__ __launch_bounds__(1024) void slot0(const float* __restrict__ ns_g, const float* __restrict__ ns_b,
                                              const float* __restrict__ wq,   const float* __restrict__ W2,
                                              const float* __restrict__ b2)
{
    __shared__ float so[256], sh[256], sq[256], qp[4096], red[16];
    int s = blockIdx.x, t = threadIdx.x;
    if (t < 256) so[t] = g_Cond[s*260 + t];
    __syncthreads();
    slot_compute(s, t, so, ns_g, ns_b, wq, W2, b2, sh, sq, qp, red);
}

// ---------------- fused: dots + softmax + attn0 + partials (2-px ILP) ----------------
__global__ __launch_bounds__(256) void iter1_kernel(int last, float* __restrict__ out)
{
    int b = blockIdx.y, chunk = blockIdx.x;
    int t = threadIdx.x, w = t >> 5, lane = t & 31;
    __shared__ float sPk[16*512];
    __shared__ float sdots[NS][16];
    __shared__ float sscal[NS][5];

    float* attnDst = last ? (out + 16640) : g_attn0;
    float* relOut  = out + 16640 + 65536;
    int n0 = chunk*16;

    {
        const float4* src = (const float4*)(g_Pk + (((size_t)(b<<10) + n0)<<9));
        float4* dst = (float4*)sPk;
        #pragma unroll
        for (int i=0;i<8;i++) dst[t + i*256] = __ldg(src + t + i*256);
    }

    float4 u0v[4], u1v[4], wtv[4], cv[4];
    const float* wts = g_slot + (b*NS + w)*520;
    #pragma unroll
    for (int jj=0; jj<4; jj++){
        int j = jj*128 + lane*4;
        u0v[jj] = *(const float4*)(g_U0 + j);
        u1v[jj] = *(const float4*)(g_U1 + j);
        cv[jj]  = *(const float4*)(g_C  + j);
        wtv[jj] = *(const float4*)(wts  + j);
    }
    if (t < 40) sscal[t/5][t%5] = g_slot[(b*NS + t/5)*520 + 512 + (t%5)];
    __syncthreads();

    float qb2=sscal[w][0], px=sscal[w][1], py=sscal[w][2], i5x=sscal[w][3], i5y=sscal[w][4];
    float V00=g_cov[3], V11=g_cov[4], C01_2=2.f*g_cov[6];

    for (int pp=0; pp<16; pp+=2){
        int nA = n0 + pp, nB = nA + 1;
        float gxA = -1.f + (float)(nA>>5)*GSTEP, gyA = -1.f + (float)(nA&31)*GSTEP;
        float gxB = -1.f + (float)(nB>>5)*GSTEP, gyB = -1.f + (float)(nB&31)*GSTEP;
        float aA = (gxA-px)*i5x, cA = (gyA-py)*i5y;
        float aB = (gxB-px)*i5x, cB = (gyB-py)*i5y;
        const float4 stA = *(const float4*)(g_statsK + ((b<<10)+nA)*4);
        const float4 stB = *(const float4*)(g_statsK + ((b<<10)+nB)*4);
        float varA = stA.x + aA*stA.y + cA*stA.z + aA*aA*V00 + cA*cA*V11 + aA*cA*C01_2;
        float varB = stB.x + aB*stB.y + cB*stB.z + aB*aB*V00 + cB*cB*V11 + aB*cB*C01_2;
        float isA = rsqrtf(varA + LNEPS);
        float isB = rsqrtf(varB + LNEPS);
        const float* pkA = sPk + pp*512;
        const float* pkB = pkA + 512;
        float acA0=0.f, acA1=0.f, acB0=0.f, acB1=0.f;
        #pragma unroll
        for (int jj=0; jj<4; jj++){
            float4 p4A = *(const float4*)(pkA + jj*128 + lane*4);
            float4 p4B = *(const float4*)(pkB + jj*128 + lane*4);
            float eA0 = fmaf(isA, fmaf(cA,u1v[jj].x, fmaf(aA,u0v[jj].x, p4A.x)), cv[jj].x);
            float eB0 = fmaf(isB, fmaf(cB,u1v[jj].x, fmaf(aB,u0v[jj].x, p4B.x)), cv[jj].x);
            float eA1 = fmaf(isA, fmaf(cA,u1v[jj].y, fmaf(aA,u0v[jj].y, p4A.y)), cv[jj].y);
            float eB1 = fmaf(isB, fmaf(cB,u1v[jj].y, fmaf(aB,u0v[jj].y, p4B.y)), cv[jj].y);
            float eA2 = fmaf(isA, fmaf(cA,u1v[jj].z, fmaf(aA,u0v[jj].z, p4A.z)), cv[jj].z);
            float eB2 = fmaf(isB, fmaf(cB,u1v[jj].z, fmaf(aB,u0v[jj].z, p4B.z)), cv[jj].z);
            float eA3 = fmaf(isA, fmaf(cA,u1v[jj].w, fmaf(aA,u0v[jj].w, p4A.w)), cv[jj].w);
            float eB3 = fmaf(isB, fmaf(cB,u1v[jj].w, fmaf(aB,u0v[jj].w, p4B.w)), cv[jj].w);
            acA0 = fmaf(fmaxf(eA0,0.f), wtv[jj].x, acA0);
            acB0 = fmaf(fmaxf(eB0,0.f), wtv[jj].x, acB0);
            acA1 = fmaf(fmaxf(eA1,0.f), wtv[jj].y, acA1);
            acB1 = fmaf(fmaxf(eB1,0.f), wtv[jj].y, acB1);
            acA0 = fmaf(fmaxf(eA2,0.f), wtv[jj].z, acA0);
            acB0 = fmaf(fmaxf(eB2,0.f), wtv[jj].z, acB0);
            acA1 = fmaf(fmaxf(eA3,0.f), wtv[jj].w, acA1);
            acB1 = fmaf(fmaxf(eB3,0.f), wtv[jj].w, acB1);
        }
        float sA = acA0 + acA1, sB = acB0 + acB1;
        #pragma unroll
        for (int o=16;o;o>>=1){
            sA += __shfl_xor_sync(0xffffffffu, sA, o);
            sB += __shfl_xor_sync(0xffffffffu, sB, o);
        }
        if (lane == 0){
            sdots[w][pp]   = ATTN_SCALE * (sA + qb2);
            sdots[w][pp+1] = ATTN_SCALE * (sB + qb2);
            if (last){
                float2* rpA = (float2*)(relOut + ((((size_t)(b*NS+w)<<10)+nA)<<1));
                float2* rpB = (float2*)(relOut + ((((size_t)(b*NS+w)<<10)+nB)<<1));
                *rpA = make_float2(aA, cA);
                *rpB = make_float2(aB, cB);
            }
        }
    }
    __syncthreads();

    float a0 = 0.f, gx = 0.f, gy = 0.f;
    if (lane < 16){
        int n = n0 + lane;
        float dd[NS]; float mx = -1e30f;
        #pragma unroll
        for (int k=0;k<NS;k++){ dd[k] = sdots[k][lane]; mx = fmaxf(mx, dd[k]); }
        float sum = 0.f;
        #pragma unroll
        for (int k=0;k<NS;k++){ dd[k] = expf(dd[k]-mx); sum += dd[k]; }
        a0 = dd[w] / sum;
        attnDst[((b*NS+w)<<10) + n] = a0;
        gx = -1.f + (float)(n>>5)*GSTEP;
        gy = -1.f + (float)(n&31)*GSTEP;
    }
    float S0 = warpSum(a0);
    float Sx = warpSum(a0*gx);
    float Sy = warpSum(a0*gy);
    float Sxx = warpSum(a0*gx*gx);
    float Syy = warpSum(a0*gy*gy);
    if (lane == 0){
        float* pp = g_part + ((size_t)((b*NS+w)*64 + chunk))*8;
        pp[0]=S0; pp[1]=Sx; pp[2]=Sy; pp[3]=Sxx; pp[4]=Syy;
    }
}

// ---------------- slot-fused vacc + finalize ----------------
__global__ __launch_bounds__(512) void vaccF_kernel()
{
    int chunk = blockIdx.x;
    int b = blockIdx.y;
    int t = threadIdx.x;
    __shared__ float4 sC4[NS][64];
    __shared__ float sden[NS];

    int sl = t >> 6, p = t & 63;
    int n = chunk*64 + p;
    int gs = b*NS + sl;
    float rawA;
    {
        float px = g_slot[gs*520+513], py = g_slot[gs*520+514];
        float i5x= g_slot[gs*520+515], i5y= g_slot[gs*520+516];
        float gx = -1.f + (float)(n>>5)*GSTEP;
        float gy = -1.f + (float)(n&31)*GSTEP;
        float a = (gx-px)*i5x, c = (gy-py)*i5y;
        const float4 st = *(const float4*)(g_statsV + ((b<<10)+n)*4);
        float var = st.x + a*st.y + c*st.z + a*a*g_cov[3] + c*c*g_cov[4] + a*c*2.f*g_cov[6];
        float is = rsqrtf(var + LNEPS);
        rawA = g_attn0[(gs<<10)+n];
        sC4[sl][p] = make_float4(is, is*a, is*c, 0.f);
    }
    if (t < 256){
        int w = t >> 5, lane = t & 31;
        const float* pp0 = g_part + ((size_t)((b*NS+w)*64 + lane))*8;
        const float* pp1 = pp0 + 32*8;
        float S0 = warpSum(pp0[0] + pp1[0]);
        if (chunk == 0){
            float Sx = warpSum(pp0[1] + pp1[1]);
            float Sy = warpSum(pp0[2] + pp1[2]);
            float Sxx = warpSum(pp0[3] + pp1[3]);
            float Syy = warpSum(pp0[4] + pp1[4]);
            if (lane == 0){
                float px = Sx, py = Sy, G2 = g_cov[9];
                float vx = Sxx - 2.f*px*Sx + px*px*S0 + EPSA*(G2 + 1024.f*px*px);
                float vy = Syy - 2.f*py*Sy + py*py*S0 + EPSA*(G2 + 1024.f*py*py);
                float sx = fminf(fmaxf(sqrtf(fmaxf(vx,0.f)), 1e-3f), 2.f);
                float sy = fminf(fmaxf(sqrtf(fmaxf(vy,0.f)), 1e-3f), 2.f);
                int s2 = b*NS + w;
                g_Cond[s2*260+256]=px; g_Cond[s2*260+257]=py;
                g_Cond[s2*260+258]=sx; g_Cond[s2*260+259]=sy;
            }
        }
        if (lane == 0) sden[w] = 1.f/(S0 + 1024.f*EPSA);
    }
    __syncthreads();
    sC4[sl][p].w = (rawA + EPSA) * sden[sl];
    __syncthreads();

    float u0 = g_U0[t], u1 = g_U1[t], C = g_C[t];
    const float* pvb = g_Pv + ((((size_t)(b<<10)) + (size_t)chunk*64) << 9) + t;
    float acc[NS] = {};
    #pragma unroll 4
    for (int q=0; q<64; q++){
        float pv = __ldg(pvb + ((size_t)q << 9));
        #pragma unroll
        for (int s2=0; s2<NS; s2++){
            float4 cf = sC4[s2][q];
            float pre = fmaf(cf.y, u0, fmaf(cf.z, u1, fmaf(cf.x, pv, C)));
            acc[s2] = fmaf(fmaxf(pre, 0.f), cf.w, acc[s2]);
        }
    }
    #pragma unroll
    for (int s2=0; s2<NS; s2++)
        g_spart[((size_t)((b*NS+s2)*16 + chunk))*H + t] = acc[s2];
}

// ---------------- GRU update + slot prep for next iter ----------------
__global__ __launch_bounds__(1024) void updslot_kernel(
    const float* __restrict__ W2,  const float* __restrict__ b2,
    const float* __restrict__ Wih, const float* __restrict__ Whh,
    const float* __restrict__ bih, const float* __restrict__ bhh,
    const float* __restrict__ ns_g, const float* __restrict__ ns_b,
    const float* __restrict__ wq)
{
    __shared__ float ss[H], so[256], su[256], qp[4096], sgx[768], sgh[768], sh[256], sq[256], red[16];
    int s = blockIdx.x, t = threadIdx.x, w = t >> 5, lane = t & 31;

    if (t < 512){
        float r0 = 0.f;
        #pragma unroll
        for (int c=0; c<16; c++) r0 += g_spart[((size_t)(s*16 + c))*H + t];
        ss[t] = r0;
    }
    if (t < 256) so[t] = g_Cond[s*260 + t];
    __syncthreads();

    {
        int cg = t & 63, ks = t >> 6;
        const float4* W24 = (const float4*)W2;
        float4 a = make_float4(0.f,0.f,0.f,0.f);
        #pragma unroll 4
        for (int j = ks*32; j < ks*32 + 32; j++){
            float4 wv = __ldg(W24 + j*64 + cg);
            float sv = ss[j];
            a.x = fmaf(sv, wv.x, a.x);
            a.y = fmaf(sv, wv.y, a.y);
            a.z = fmaf(sv, wv.z, a.z);
            a.w = fmaf(sv, wv.w, a.w);
        }
        *(float4*)(qp + ks*256 + cg*4) = a;
    }
    __syncthreads();
    if (t < 256){
        float u = b2[t];
        #pragma unroll
        for (int ks=0; ks<16; ks++) u += qp[ks*256 + t];
        su[t] = u;
    }
    __syncthreads();

    {
        float4 sua = *(const float4*)(su + lane*8);
        float4 sub = *(const float4*)(su + lane*8 + 4);
        float4 soa = *(const float4*)(so + lane*8);
        float4 sob = *(const float4*)(so + lane*8 + 4);
        #pragma unroll 2
        for (int k = 0; k < 24; k++){
            int i = (k << 5) + w;
            const float4* wi4 = (const float4*)(Wih + i*D);
            const float4* wh4 = (const float4*)(Whh + i*D);
            float4 wa = __ldg(wi4 + lane*2);
            float4 wb = __ldg(wi4 + lane*2 + 1);
            float4 ha = __ldg(wh4 + lane*2);
            float4 hb = __ldg(wh4 + lane*2 + 1);
            float ax = wa.x*sua.x + wa.y*sua.y + wa.z*sua.z + wa.w*sua.w
                     + wb.x*sub.x + wb.y*sub.y + wb.z*sub.z + wb.w*sub.w;
            float ah = ha.x*soa.x + ha.y*soa.y + ha.z*soa.z + ha.w*soa.w
                     + hb.x*sob.x + hb.y*sob.y + hb.z*sob.z + hb.w*sob.w;
            #pragma unroll
            for (int o=16;o;o>>=1){
                ax += __shfl_xor_sync(0xffffffffu, ax, o);
                ah += __shfl_xor_sync(0xffffffffu, ah, o);
            }
            if (lane == 0){ sgx[i] = ax + bih[i]; sgh[i] = ah + bhh[i]; }
        }
    }
    __syncthreads();

    if (t < 256){
        float r = 1.f/(1.f + expf(-(sgx[t]     + sgh[t])));
        float z = 1.f/(1.f + expf(-(sgx[256+t] + sgh[256+t])));
        float nn = tanhf(sgx[512+t] + r*sgh[512+t]);
        float nv = (1.f - z)*nn + z*so[t];
        g_Cond[s*260 + t] = nv;
        so[t] = nv;
    }
    __syncthreads();

    slot_compute(s, t, so, ns_g, ns_b, wq, W2, b2, sh, sq, qp, red);
}

// ---------------- final: pos/scl + write conditioning to out ----------------
__global__ void finz3_kernel(float* __restrict__ out)
{
    __shared__ float sres[4];
    int s = blockIdx.x, t = threadIdx.x;
    if (t < 32){
        const float* pp0 = g_part + ((size_t)(s*64 + t))*8;
        const float* pp1 = pp0 + 32*8;
        float S0 = warpSum(pp0[0] + pp1[0]);
        float Sx = warpSum(pp0[1] + pp1[1]);
        float Sy = warpSum(pp0[2] + pp1[2]);
        float Sxx = warpSum(pp0[3] + pp1[3]);
        float Syy = warpSum(pp0[4] + pp1[4]);
        if (t == 0){
            float px = Sx, py = Sy, G2 = g_cov[9];
            float vx = Sxx - 2.f*px*Sx + px*px*S0 + EPSA*(G2 + 1024.f*px*px);
            float vy = Syy - 2.f*py*Sy + py*py*S0 + EPSA*(G2 + 1024.f*py*py);
            float sx = fminf(fmaxf(sqrtf(fmaxf(vx,0.f)), 1e-3f), 2.f);
            float sy = fminf(fmaxf(sqrtf(fmaxf(vy,0.f)), 1e-3f), 2.f);
            sres[0]=px; sres[1]=py; sres[2]=sx; sres[3]=sy;
        }
    }
    __syncthreads();
    for (int i = t; i < 260; i += 256)
        out[s*260 + i] = (i < 256) ? g_Cond[s*260 + i] : sres[i - 256];
}

// ---------------- launch ----------------
extern "C" void kernel_launch(void* const* d_in, const int* in_sizes, int n_in,
                              void* d_out, int out_size)
{
    const float* inputs = (const float*)d_in[0];
    const float* cond   = (const float*)d_in[1];
    const float* ni_g   = (const float*)d_in[2];
    const float* ni_b   = (const float*)d_in[3];
    const float* ns_g   = (const float*)d_in[4];
    const float* ns_b   = (const float*)d_in[5];
    const float* wq     = (const float*)d_in[6];
    const float* wk     = (const float*)d_in[7];
    const float* wv     = (const float*)d_in[8];
    const float* gp_w   = (const float*)d_in[9];
    const float* gp_b   = (const float*)d_in[10];
    const float* ge_ln_g= (const float*)d_in[11];
    const float* ge_ln_b= (const float*)d_in[12];
    const float* ge_w1  = (const float*)d_in[13];
    const float* ge_b1  = (const float*)d_in[14];
    const float* ge_w2  = (const float*)d_in[15];
    const float* ge_b2  = (const float*)d_in[16];
    const float* gru_wih= (const float*)d_in[17];
    const float* gru_whh= (const float*)d_in[18];
    const float* gru_bih= (const float*)d_in[19];
    const float* gru_bhh= (const float*)d_in[20];
    float* out = (float*)d_out;

    static int s_attr = 0;
    if (!s_attr){
        cudaFuncSetAttribute(gemmT0, cudaFuncAttributeMaxDynamicSharedMemorySize, 51200);
        cudaFuncSetAttribute(gemmT2, cudaFuncAttributeMaxDynamicSharedMemorySize, 30720);
        s_attr = 1;
    }

    pre_kernel<<<610, 512>>>(gp_w, gp_b, ge_ln_g, ge_ln_b, ge_w1, ge_b1, cond, inputs, wk, wv);
    gemmT0<<<dim3(4,64,2), 256, 51200>>>(inputs, ni_g, ni_b);
    stats2<<<512, 512>>>(gp_w, gp_b);
    gemmT2<<<dim3(8,64,2), 256, 30720>>>();
    slot0<<<64, 1024>>>(ns_g, ns_b, wq, ge_w2, ge_b2);

    for (int it = 0; it < 3; it++) {
        iter1_kernel<<<dim3(64,8), 256>>>(0, out);
        vaccF_kernel<<<dim3(16,8), 512>>>();
        updslot_kernel<<<64, 1024>>>(ge_w2, ge_b2, gru_wih, gru_whh, gru_bih, gru_bhh,
                                     ns_g, ns_b, wq);
    }
    iter1_kernel<<<dim3(64,8), 256>>>(1, out);
    finz3_kernel<<<64, 256>>>(out);
}